// round 9
// baseline (speedup 1.0000x reference)
#include <cuda_runtime.h>
#include <cuda_bf16.h>
#include <math.h>
#include <stdint.h>

#define BB   8
#define SS   256
#define HH   768
#define NLL  12
#define NHH  12
#define FFF  3072
#define CC   9
#define DHH  64
#define TOK  (BB*SS)   // 2048

// ================= scratch =================
__device__ float                         g_h   [TOK*HH];
__device__ __align__(256) __nv_bfloat16  g_h_hi[TOK*HH];
__device__ __align__(256) __nv_bfloat16  g_h_lo[TOK*HH];
__device__ __align__(256) float          g_qkv [3*TOK*HH];
__device__ __align__(256) __nv_bfloat16  g_cx_hi[TOK*HH];
__device__ __align__(256) __nv_bfloat16  g_cx_lo[TOK*HH];
__device__ __align__(256) float          g_t1  [TOK*HH];
__device__ __align__(256) __nv_bfloat16  g_f_hi[TOK*FFF];
__device__ __align__(256) __nv_bfloat16  g_f_lo[TOK*FFF];
__device__ float                         g_em  [TOK*CC];

__device__ __align__(256) __nv_bfloat16 w_qkv_hi[NLL*3*HH*HH];
__device__ __align__(256) __nv_bfloat16 w_qkv_lo[NLL*3*HH*HH];
__device__ __align__(256) __nv_bfloat16 w_ao_hi [NLL*HH*HH];
__device__ __align__(256) __nv_bfloat16 w_ao_lo [NLL*HH*HH];
__device__ __align__(256) __nv_bfloat16 w_f1_hi [NLL*HH*FFF];
__device__ __align__(256) __nv_bfloat16 w_f1_lo [NLL*HH*FFF];
__device__ __align__(256) __nv_bfloat16 w_f2_hi [NLL*FFF*HH];
__device__ __align__(256) __nv_bfloat16 w_f2_lo [NLL*FFF*HH];

// ================= low-level helpers =================
__device__ __forceinline__ void cpa16(uint32_t dst, const void* src) {
    asm volatile("cp.async.cg.shared.global [%0], [%1], 16;"
                 :: "r"(dst), "l"(src) : "memory");
}
#define CP_COMMIT() asm volatile("cp.async.commit_group;" ::: "memory")
#define CP_WAIT1()  asm volatile("cp.async.wait_group 1;" ::: "memory")
#define CP_WAIT0()  asm volatile("cp.async.wait_group 0;" ::: "memory")

__device__ __forceinline__ void ldm_x4(uint32_t* r, uint32_t a) {
    asm volatile("ldmatrix.sync.aligned.m8n8.x4.shared.b16 {%0,%1,%2,%3}, [%4];"
                 : "=r"(r[0]), "=r"(r[1]), "=r"(r[2]), "=r"(r[3]) : "r"(a));
}
__device__ __forceinline__ void mma16816(float* c, const uint32_t* a, const uint32_t* b) {
    asm volatile("mma.sync.aligned.m16n8k16.row.col.f32.bf16.bf16.f32 "
        "{%0,%1,%2,%3}, {%4,%5,%6,%7}, {%8,%9}, {%0,%1,%2,%3};"
        : "+f"(c[0]), "+f"(c[1]), "+f"(c[2]), "+f"(c[3])
        : "r"(a[0]), "r"(a[1]), "r"(a[2]), "r"(a[3]), "r"(b[0]), "r"(b[1]));
}

__device__ __forceinline__ float gelu_tanh(float v) {
    float c = 0.7978845608028654f * (v + 0.044715f * v * v * v);
    return 0.5f * v * (1.f + tanhf(c));
}
__device__ __forceinline__ void split_bf16(float v, __nv_bfloat16& h, __nv_bfloat16& l) {
    h = __float2bfloat16(v);
    l = __float2bfloat16(v - __bfloat162float(h));
}

// ================= weight transpose + split =================
__global__ void k_wsplit64(const float* __restrict__ W,
                           __nv_bfloat16* __restrict__ hi,
                           __nv_bfloat16* __restrict__ lo,
                           int K, int N) {
    __shared__ float t[64][68];
    size_t moff = (size_t)blockIdx.z * K * N;
    int n0 = blockIdx.x * 64, k0 = blockIdx.y * 64;
    int tid = threadIdx.x;
#pragma unroll
    for (int i = 0; i < 4; i++) {
        int l4 = tid + i * 256;
        int r = l4 >> 4, c4 = (l4 & 15) * 4;
        *(float4*)&t[r][c4] = *(const float4*)&W[moff + (size_t)(k0 + r) * N + n0 + c4];
    }
    __syncthreads();
#pragma unroll
    for (int i = 0; i < 4; i++) {
        int l4 = tid + i * 256;
        int r = l4 >> 4, c4 = (l4 & 15) * 4;
        float v0 = t[c4 + 0][r], v1 = t[c4 + 1][r], v2 = t[c4 + 2][r], v3 = t[c4 + 3][r];
        __nv_bfloat16 h0,l0,h1,l1,h2,l2,h3,l3;
        split_bf16(v0,h0,l0); split_bf16(v1,h1,l1);
        split_bf16(v2,h2,l2); split_bf16(v3,h3,l3);
        size_t o = moff + (size_t)(n0 + r) * K + k0 + c4;
        __nv_bfloat162 hh0 = __halves2bfloat162(h0,h1), hh1 = __halves2bfloat162(h2,h3);
        __nv_bfloat162 ll0 = __halves2bfloat162(l0,l1), ll1 = __halves2bfloat162(l2,l3);
        *(uint2*)(hi + o) = make_uint2(*(uint32_t*)&hh0, *(uint32_t*)&hh1);
        *(uint2*)(lo + o) = make_uint2(*(uint32_t*)&ll0, *(uint32_t*)&ll1);
    }
}

#define PADK 40

// ================= k_mma256: BM=128, BN=256, 64x64 warp tiles =================
// qkvstride>0 : demux output buffers every 768 columns (ldc=768, fp32+bias).
// mode==1    : gelu + split epilogue to Chi/Clo (ldc=N).
__global__ __launch_bounds__(256, 1)
void k_mma256(const __nv_bfloat16* __restrict__ A_hi,
              const __nv_bfloat16* __restrict__ A_lo,
              const __nv_bfloat16* __restrict__ B_hi,
              const __nv_bfloat16* __restrict__ B_lo,
              const float* __restrict__ bias,
              float* __restrict__ Cf,
              __nv_bfloat16* __restrict__ Chi,
              __nv_bfloat16* __restrict__ Clo,
              int N, int K, int mode, size_t qkvstride)
{
    constexpr int ASZ = 128 * PADK;     // halves
    constexpr int BSZ = 256 * PADK;
    constexpr int STG = 2 * ASZ + 2 * BSZ;

    extern __shared__ __nv_bfloat16 smem_dyn[];
    uint32_t smb = (uint32_t)__cvta_generic_to_shared(smem_dyn);

    int tid = threadIdx.x, wid = tid >> 5, lane = tid & 31;
    int n0 = blockIdx.x * 256, m0 = blockIdx.y * 128;

    int wm = (wid & 1) * 64;        // M offset of warp tile
    int wn = (wid >> 1) * 64;       // N offset of warp tile

    float acc[4][8][4];
#pragma unroll
    for (int mt = 0; mt < 4; mt++)
#pragma unroll
        for (int nt = 0; nt < 8; nt++)
#pragma unroll
            for (int f = 0; f < 4; f++) acc[mt][nt][f] = 0.f;

    auto load_stage = [&](int s, int k0) {
        uint32_t base = smb + (uint32_t)(s * STG) * 2;
#pragma unroll
        for (int i = 0; i < 2; i++) {
            int idx = tid + i * 256;
            int r = idx >> 2, ch = idx & 3;
            const char* g0 = (const char*)(A_hi + (size_t)(m0 + r) * K + k0) + ch * 16;
            const char* g1 = (const char*)(A_lo + (size_t)(m0 + r) * K + k0) + ch * 16;
            cpa16(base + (uint32_t)(r * PADK) * 2 + ch * 16, g0);
            cpa16(base + (uint32_t)(ASZ + r * PADK) * 2 + ch * 16, g1);
        }
#pragma unroll
        for (int i = 0; i < 4; i++) {
            int idx = tid + i * 256;
            int r = idx >> 2, ch = idx & 3;
            const char* g0 = (const char*)(B_hi + (size_t)(n0 + r) * K + k0) + ch * 16;
            const char* g1 = (const char*)(B_lo + (size_t)(n0 + r) * K + k0) + ch * 16;
            cpa16(base + (uint32_t)(2 * ASZ + r * PADK) * 2 + ch * 16, g0);
            cpa16(base + (uint32_t)(2 * ASZ + BSZ + r * PADK) * 2 + ch * 16, g1);
        }
    };

    int nc = K / 32;
    load_stage(0, 0);
    CP_COMMIT();
    load_stage(1, 32);
    CP_COMMIT();

    uint32_t aRow = (uint32_t)(wm + (lane & 15));
    uint32_t aK   = (uint32_t)((lane >> 4) * 8);
    uint32_t bRow = (uint32_t)(wn + ((lane >> 4) & 1) * 8 + (lane & 7));
    uint32_t bK   = (uint32_t)(((lane >> 3) & 1) * 8);

    for (int c = 0; c < nc; c++) {
        int b = c & 1;
        if (c == nc - 1) { CP_WAIT0(); } else { CP_WAIT1(); }
        __syncthreads();

        uint32_t sbase = smb + (uint32_t)(b * STG) * 2;
#pragma unroll
        for (int k16 = 0; k16 < 2; k16++) {
            uint32_t bh[4][4], bl[4][4];
#pragma unroll
            for (int np = 0; np < 4; np++) {
                uint32_t off = ((bRow + np * 16) * PADK + (uint32_t)(k16 * 16) + bK) * 2;
                ldm_x4(bh[np], sbase + (uint32_t)(2 * ASZ) * 2 + off);
                ldm_x4(bl[np], sbase + (uint32_t)(2 * ASZ + BSZ) * 2 + off);
            }
#pragma unroll
            for (int mt = 0; mt < 4; mt++) {
                uint32_t ah[4], al[4];
                uint32_t off = ((aRow + mt * 16) * PADK + (uint32_t)(k16 * 16) + aK) * 2;
                ldm_x4(ah, sbase + off);
                ldm_x4(al, sbase + (uint32_t)ASZ * 2 + off);
#pragma unroll
                for (int nt = 0; nt < 8; nt++) {
                    const uint32_t* Bh = &bh[nt >> 1][(nt & 1) * 2];
                    const uint32_t* Bl = &bl[nt >> 1][(nt & 1) * 2];
                    mma16816(acc[mt][nt], ah, Bh);
                    mma16816(acc[mt][nt], ah, Bl);
                    mma16816(acc[mt][nt], al, Bh);
                }
            }
        }

        if (c + 2 < nc) {
            __syncthreads();
            load_stage(b, (c + 2) * 32);
            CP_COMMIT();
        }
    }

    int rbase = m0 + wm + (lane >> 2);
    if (mode == 0) {
        // QKV demux: buffer = n0/768, local col base = n0%768, ldc = 768
        float* Cout = Cf + (size_t)(n0 / 768) * qkvstride;
        int cb = n0 % 768;
#pragma unroll
        for (int mt = 0; mt < 4; mt++) {
            int row = rbase + mt * 16;
#pragma unroll
            for (int nt = 0; nt < 8; nt++) {
                int coll = wn + nt * 8 + (lane & 3) * 2;
                float b0 = bias[n0 + coll], b1 = bias[n0 + coll + 1];
                int col = cb + coll;
                *(float2*)(Cout + (size_t)row * 768 + col) =
                    make_float2(acc[mt][nt][0] + b0, acc[mt][nt][1] + b1);
                *(float2*)(Cout + (size_t)(row + 8) * 768 + col) =
                    make_float2(acc[mt][nt][2] + b0, acc[mt][nt][3] + b1);
            }
        }
    } else {
#pragma unroll
        for (int mt = 0; mt < 4; mt++) {
            int row = rbase + mt * 16;
#pragma unroll
            for (int nt = 0; nt < 8; nt++) {
                int col = n0 + wn + nt * 8 + (lane & 3) * 2;
                float b0 = bias[col], b1 = bias[col + 1];
                float v0 = gelu_tanh(acc[mt][nt][0] + b0);
                float v1 = gelu_tanh(acc[mt][nt][1] + b1);
                float v2 = gelu_tanh(acc[mt][nt][2] + b0);
                float v3 = gelu_tanh(acc[mt][nt][3] + b1);
                __nv_bfloat16 h0, l0, h1, l1;
                split_bf16(v0, h0, l0); split_bf16(v1, h1, l1);
                *(__nv_bfloat162*)(Chi + (size_t)row * N + col) = __halves2bfloat162(h0, h1);
                *(__nv_bfloat162*)(Clo + (size_t)row * N + col) = __halves2bfloat162(l0, l1);
                split_bf16(v2, h0, l0); split_bf16(v3, h1, l1);
                *(__nv_bfloat162*)(Chi + (size_t)(row + 8) * N + col) = __halves2bfloat162(h0, h1);
                *(__nv_bfloat162*)(Clo + (size_t)(row + 8) * N + col) = __halves2bfloat162(l0, l1);
            }
        }
    }
}

// ================= k_mma BN=64 (AO / FFN2), unchanged =================
template<int BN>
__global__ __launch_bounds__(256, 2)
void k_mma(const __nv_bfloat16* __restrict__ A_hi,
           const __nv_bfloat16* __restrict__ A_lo,
           const __nv_bfloat16* __restrict__ B_hi,
           const __nv_bfloat16* __restrict__ B_lo,
           const float* __restrict__ bias,
           float* __restrict__ Cf,
           int N, int K)
{
    constexpr int WMW = 4;
    constexpr int WTM = 32;
    constexpr int MT  = 2;
    constexpr int ASZ = 128 * PADK;
    constexpr int BSZ = BN  * PADK;
    constexpr int STG = 2 * ASZ + 2 * BSZ;

    extern __shared__ __nv_bfloat16 smem_dyn[];
    uint32_t smb = (uint32_t)__cvta_generic_to_shared(smem_dyn);

    int tid = threadIdx.x, wid = tid >> 5, lane = tid & 31;
    int n0 = blockIdx.x * BN, m0 = blockIdx.y * 128;

    int wm = (wid % WMW) * WTM;
    int wn = (wid / WMW) * 32;

    float acc[MT][4][4];
#pragma unroll
    for (int mt = 0; mt < MT; mt++)
#pragma unroll
        for (int nt = 0; nt < 4; nt++)
#pragma unroll
            for (int f = 0; f < 4; f++) acc[mt][nt][f] = 0.f;

    auto load_stage = [&](int s, int k0) {
        uint32_t base = smb + (uint32_t)(s * STG) * 2;
#pragma unroll
        for (int i = 0; i < 2; i++) {
            int idx = tid + i * 256;
            int r = idx >> 2, ch = idx & 3;
            const char* g0 = (const char*)(A_hi + (size_t)(m0 + r) * K + k0) + ch * 16;
            const char* g1 = (const char*)(A_lo + (size_t)(m0 + r) * K + k0) + ch * 16;
            cpa16(base + (uint32_t)(r * PADK) * 2 + ch * 16, g0);
            cpa16(base + (uint32_t)(ASZ + r * PADK) * 2 + ch * 16, g1);
        }
#pragma unroll
        for (int i = 0; i < (BN * 4) / 256; i++) {
            int idx = tid + i * 256;
            int r = idx >> 2, ch = idx & 3;
            const char* g0 = (const char*)(B_hi + (size_t)(n0 + r) * K + k0) + ch * 16;
            const char* g1 = (const char*)(B_lo + (size_t)(n0 + r) * K + k0) + ch * 16;
            cpa16(base + (uint32_t)(2 * ASZ + r * PADK) * 2 + ch * 16, g0);
            cpa16(base + (uint32_t)(2 * ASZ + BSZ + r * PADK) * 2 + ch * 16, g1);
        }
    };

    int nc = K / 32;
    load_stage(0, 0);
    CP_COMMIT();
    load_stage(1, 32);
    CP_COMMIT();

    uint32_t aRow = (uint32_t)(wm + (lane & 15));
    uint32_t aK   = (uint32_t)((lane >> 4) * 8);
    uint32_t bRow = (uint32_t)(wn + ((lane >> 4) & 1) * 8 + (lane & 7));
    uint32_t bK   = (uint32_t)(((lane >> 3) & 1) * 8);

    for (int c = 0; c < nc; c++) {
        int b = c & 1;
        if (c == nc - 1) { CP_WAIT0(); } else { CP_WAIT1(); }
        __syncthreads();

        uint32_t sbase = smb + (uint32_t)(b * STG) * 2;
#pragma unroll
        for (int k16 = 0; k16 < 2; k16++) {
            uint32_t bh[2][4], bl[2][4];
#pragma unroll
            for (int np = 0; np < 2; np++) {
                uint32_t off = ((bRow + np * 16) * PADK + (uint32_t)(k16 * 16) + bK) * 2;
                ldm_x4(bh[np], sbase + (uint32_t)(2 * ASZ) * 2 + off);
                ldm_x4(bl[np], sbase + (uint32_t)(2 * ASZ + BSZ) * 2 + off);
            }
#pragma unroll
            for (int mt = 0; mt < MT; mt++) {
                uint32_t ah[4], al[4];
                uint32_t off = ((aRow + mt * 16) * PADK + (uint32_t)(k16 * 16) + aK) * 2;
                ldm_x4(ah, sbase + off);
                ldm_x4(al, sbase + (uint32_t)ASZ * 2 + off);
#pragma unroll
                for (int nt = 0; nt < 4; nt++) {
                    const uint32_t* Bh = &bh[nt >> 1][(nt & 1) * 2];
                    const uint32_t* Bl = &bl[nt >> 1][(nt & 1) * 2];
                    mma16816(acc[mt][nt], ah, Bh);
                    mma16816(acc[mt][nt], ah, Bl);
                    mma16816(acc[mt][nt], al, Bh);
                }
            }
        }

        if (c + 2 < nc) {
            __syncthreads();
            load_stage(b, (c + 2) * 32);
            CP_COMMIT();
        }
    }

    int rbase = m0 + wm + (lane >> 2);
#pragma unroll
    for (int mt = 0; mt < MT; mt++) {
        int row = rbase + mt * 16;
#pragma unroll
        for (int nt = 0; nt < 4; nt++) {
            int col = n0 + wn + nt * 8 + (lane & 3) * 2;
            float b0 = bias[col], b1 = bias[col + 1];
            *(float2*)(Cf + (size_t)row * N + col) =
                make_float2(acc[mt][nt][0] + b0, acc[mt][nt][1] + b1);
            *(float2*)(Cf + (size_t)(row + 8) * N + col) =
                make_float2(acc[mt][nt][2] + b0, acc[mt][nt][3] + b1);
        }
    }
}

// ================= embed + LN (float4) =================
__global__ void embed_ln_kernel(const int* __restrict__ x,
                                const float* __restrict__ we,
                                const float* __restrict__ pe,
                                const float* __restrict__ te,
                                const float* __restrict__ lw,
                                const float* __restrict__ lb) {
    int t = blockIdx.x, s = t % SS, tid = threadIdx.x;
    int wid = x[t];
    bool act = tid < 192;
    float4 v4 = make_float4(0.f, 0.f, 0.f, 0.f);
    if (act) {
        float4 a = *(const float4*)&we[(size_t)wid * HH + tid * 4];
        float4 b = *(const float4*)&pe[s * HH + tid * 4];
        float4 c = *(const float4*)&te[tid * 4];
        v4 = make_float4(a.x+b.x+c.x, a.y+b.y+c.y, a.z+b.z+c.z, a.w+b.w+c.w);
    }
    float sum = v4.x + v4.y + v4.z + v4.w;
    float sq  = v4.x*v4.x + v4.y*v4.y + v4.z*v4.z + v4.w*v4.w;
    __shared__ float red[256], red2[256];
    red[tid] = sum; red2[tid] = sq; __syncthreads();
    for (int off = 128; off > 0; off >>= 1) {
        if (tid < off) { red[tid] += red[tid+off]; red2[tid] += red2[tid+off]; }
        __syncthreads();
    }
    float m = red[0] * (1.f/HH), var = red2[0] * (1.f/HH) - m*m;
    float rstd = rsqrtf(var + 1e-12f);
    if (act) {
        float4 w4 = *(const float4*)&lw[tid*4];
        float4 b4 = *(const float4*)&lb[tid*4];
        float o0 = (v4.x-m)*rstd*w4.x + b4.x;
        float o1 = (v4.y-m)*rstd*w4.y + b4.y;
        float o2 = (v4.z-m)*rstd*w4.z + b4.z;
        float o3 = (v4.w-m)*rstd*w4.w + b4.w;
        size_t idx = (size_t)t * HH + tid * 4;
        *(float4*)&g_h[idx] = make_float4(o0,o1,o2,o3);
        __nv_bfloat16 h0,l0,h1,l1,h2,l2,h3,l3;
        split_bf16(o0,h0,l0); split_bf16(o1,h1,l1);
        split_bf16(o2,h2,l2); split_bf16(o3,h3,l3);
        __nv_bfloat162 hh0=__halves2bfloat162(h0,h1), hh1=__halves2bfloat162(h2,h3);
        __nv_bfloat162 ll0=__halves2bfloat162(l0,l1), ll1=__halves2bfloat162(l2,l3);
        *(uint2*)(g_h_hi + idx) = make_uint2(*(uint32_t*)&hh0, *(uint32_t*)&hh1);
        *(uint2*)(g_h_lo + idx) = make_uint2(*(uint32_t*)&ll0, *(uint32_t*)&ll1);
    }
}

// ================= residual + LN (float4) =================
__global__ void resid_ln_kernel(const float* __restrict__ add,
                                const float* __restrict__ lw,
                                const float* __restrict__ lb) {
    int t = blockIdx.x, tid = threadIdx.x;
    bool act = tid < 192;
    float4 v4 = make_float4(0.f, 0.f, 0.f, 0.f);
    size_t idx = (size_t)t * HH + tid * 4;
    if (act) {
        float4 a = *(const float4*)&g_h[idx];
        float4 b = *(const float4*)&add[idx];
        v4 = make_float4(a.x+b.x, a.y+b.y, a.z+b.z, a.w+b.w);
    }
    float sum = v4.x + v4.y + v4.z + v4.w;
    float sq  = v4.x*v4.x + v4.y*v4.y + v4.z*v4.z + v4.w*v4.w;
    __shared__ float red[256], red2[256];
    red[tid] = sum; red2[tid] = sq; __syncthreads();
    for (int off = 128; off > 0; off >>= 1) {
        if (tid < off) { red[tid] += red[tid+off]; red2[tid] += red2[tid+off]; }
        __syncthreads();
    }
    float m = red[0] * (1.f/HH), var = red2[0] * (1.f/HH) - m*m;
    float rstd = rsqrtf(var + 1e-12f);
    if (act) {
        float4 w4 = *(const float4*)&lw[tid*4];
        float4 b4 = *(const float4*)&lb[tid*4];
        float o0 = (v4.x-m)*rstd*w4.x + b4.x;
        float o1 = (v4.y-m)*rstd*w4.y + b4.y;
        float o2 = (v4.z-m)*rstd*w4.z + b4.z;
        float o3 = (v4.w-m)*rstd*w4.w + b4.w;
        *(float4*)&g_h[idx] = make_float4(o0,o1,o2,o3);
        __nv_bfloat16 h0,l0,h1,l1,h2,l2,h3,l3;
        split_bf16(o0,h0,l0); split_bf16(o1,h1,l1);
        split_bf16(o2,h2,l2); split_bf16(o3,h3,l3);
        __nv_bfloat162 hh0=__halves2bfloat162(h0,h1), hh1=__halves2bfloat162(h2,h3);
        __nv_bfloat162 ll0=__halves2bfloat162(l0,l1), ll1=__halves2bfloat162(l2,l3);
        *(uint2*)(g_h_hi + idx) = make_uint2(*(uint32_t*)&hh0, *(uint32_t*)&hh1);
        *(uint2*)(g_h_lo + idx) = make_uint2(*(uint32_t*)&ll0, *(uint32_t*)&ll1);
    }
}

// ================= attention v4 =================
__global__ void attn_kernel_v4() {
    extern __shared__ float sm[];
    float* Qs = sm;               // [128][64]
    float* KT = Qs + 128 * 64;    // [64][256]
    float* Vs = KT + 64 * 256;    // [256][64]
    float* Ps = Vs + 256 * 64;    // [32][256]

    const float* gq = g_qkv;
    const float* gk = g_qkv + (size_t)TOK * HH;
    const float* gv = g_qkv + 2 * (size_t)TOK * HH;

    int h = blockIdx.x, b = blockIdx.y, qh = blockIdx.z;
    int tid = threadIdx.x, lane = tid & 31, w = tid >> 5;
    size_t base = (size_t)(b * SS) * HH + h * DHH;
    int qoff = qh * 128;

    for (int i = tid; i < 128 * 16; i += 256) {
        int r = i >> 4, c4 = (i & 15) * 4;
        *(float4*)&Qs[r * 64 + c4] =
            *(const float4*)&gq[base + (size_t)(qoff + r) * HH + c4];
    }
    for (int i = tid; i < 256 * 16; i += 256) {
        int r = i >> 4, c4 = (i & 15) * 4;
        size_t g = base + (size_t)r * HH + c4;
        *(float4*)&Vs[r * 64 + c4] = *(const float4*)&gv[g];
        float4 k4 = *(const float4*)&gk[g];
        KT[(c4 + 0) * 256 + r] = k4.x;
        KT[(c4 + 1) * 256 + r] = k4.y;
        KT[(c4 + 2) * 256 + r] = k4.z;
        KT[(c4 + 3) * 256 + r] = k4.w;
    }
    __syncthreads();

    int lane8 = lane * 8;
    for (int pass = 0; pass < 2; pass++) {
        int qbase = pass * 64 + w * 8;
        float acc[8][8];
#pragma unroll
        for (int i = 0; i < 8; i++)
#pragma unroll
            for (int j = 0; j < 8; j++) acc[i][j] = 0.f;

        for (int d4 = 0; d4 < 64; d4 += 4) {
            float ka[4][8];
#pragma unroll
            for (int dd = 0; dd < 4; dd++) {
                float4 a = *(const float4*)&KT[(d4 + dd) * 256 + lane8];
                float4 bb = *(const float4*)&KT[(d4 + dd) * 256 + lane8 + 4];
                ka[dd][0]=a.x; ka[dd][1]=a.y; ka[dd][2]=a.z; ka[dd][3]=a.w;
                ka[dd][4]=bb.x; ka[dd][5]=bb.y; ka[dd][6]=bb.z; ka[dd][7]=bb.w;
            }
#pragma unroll
            for (int i = 0; i < 8; i++) {
                float4 q4 = *(const float4*)&Qs[(qbase + i) * 64 + d4];
                float qv[4] = {q4.x, q4.y, q4.z, q4.w};
#pragma unroll
                for (int dd = 0; dd < 4; dd++)
#pragma unroll
                    for (int j = 0; j < 8; j++)
                        acc[i][j] += qv[dd] * ka[dd][j];
            }
        }

        float inv_[8];
#pragma unroll
        for (int i = 0; i < 8; i++) {
            float m = -1e30f;
#pragma unroll
            for (int j = 0; j < 8; j++) m = fmaxf(m, acc[i][j]);
#pragma unroll
            for (int off = 16; off > 0; off >>= 1)
                m = fmaxf(m, __shfl_xor_sync(0xffffffffu, m, off));
            float s = 0.f;
#pragma unroll
            for (int j = 0; j < 8; j++) {
                acc[i][j] = __expf(0.125f * (acc[i][j] - m));
                s += acc[i][j];
            }
#pragma unroll
            for (int off = 16; off > 0; off >>= 1)
                s += __shfl_xor_sync(0xffffffffu, s, off);
            inv_[i] = 1.f / s;
        }

        int dql = (lane & 15) * 4, kh = lane >> 4;
#pragma unroll
        for (int chunk = 0; chunk < 2; chunk++) {
#pragma unroll
            for (int ii = 0; ii < 4; ii++) {
                int i = chunk * 4 + ii;
                float iv = inv_[i];
                *(float4*)&Ps[(w * 4 + ii) * 256 + lane8] =
                    make_float4(acc[i][0]*iv, acc[i][1]*iv, acc[i][2]*iv, acc[i][3]*iv);
                *(float4*)&Ps[(w * 4 + ii) * 256 + lane8 + 4] =
                    make_float4(acc[i][4]*iv, acc[i][5]*iv, acc[i][6]*iv, acc[i][7]*iv);
            }
            __syncwarp();

            float c[4][4];
#pragma unroll
            for (int ii = 0; ii < 4; ii++)
#pragma unroll
                for (int f = 0; f < 4; f++) c[ii][f] = 0.f;

            for (int kk = 0; kk < 128; kk++) {
                int k = kh * 128 + kk;
                float4 v4 = *(const float4*)&Vs[k * 64 + dql];
#pragma unroll
                for (int ii = 0; ii < 4; ii++) {
                    float p = Ps[(w * 4 + ii) * 256 + k];
                    c[ii][0] += p * v4.x;
                    c[ii][1] += p * v4.y;
                    c[ii][2] += p * v4.z;
                    c[ii][3] += p * v4.w;
                }
            }
#pragma unroll
            for (int ii = 0; ii < 4; ii++)
#pragma unroll
                for (int f = 0; f < 4; f++)
                    c[ii][f] += __shfl_xor_sync(0xffffffffu, c[ii][f], 16);

            if (lane < 16) {
#pragma unroll
                for (int ii = 0; ii < 4; ii++) {
                    int q = qoff + qbase + chunk * 4 + ii;
                    size_t idx = base + (size_t)q * HH + dql;
                    __nv_bfloat16 h0,l0,h1,l1,h2,l2,h3,l3;
                    split_bf16(c[ii][0],h0,l0); split_bf16(c[ii][1],h1,l1);
                    split_bf16(c[ii][2],h2,l2); split_bf16(c[ii][3],h3,l3);
                    __nv_bfloat162 hh0=__halves2bfloat162(h0,h1), hh1=__halves2bfloat162(h2,h3);
                    __nv_bfloat162 ll0=__halves2bfloat162(l0,l1), ll1=__halves2bfloat162(l2,l3);
                    *(uint2*)(g_cx_hi + idx) = make_uint2(*(uint32_t*)&hh0, *(uint32_t*)&hh1);
                    *(uint2*)(g_cx_lo + idx) = make_uint2(*(uint32_t*)&ll0, *(uint32_t*)&ll1);
                }
            }
            __syncwarp();
        }
    }
}

// ================= emissions =================
__global__ void emissions_kernel(const float* __restrict__ cw,
                                 const float* __restrict__ cb) {
    int t = blockIdx.x, tid = threadIdx.x;
    float part[CC];
#pragma unroll
    for (int c = 0; c < CC; c++) part[c] = 0.f;
    for (int k = tid; k < HH; k += 256) {
        float hv = g_h[(size_t)t * HH + k];
        const float* wr = cw + (size_t)k * CC;
#pragma unroll
        for (int c = 0; c < CC; c++) part[c] += hv * wr[c];
    }
#pragma unroll
    for (int c = 0; c < CC; c++)
        for (int off = 16; off > 0; off >>= 1)
            part[c] += __shfl_down_sync(0xffffffffu, part[c], off);

    __shared__ float wred[8][CC];
    int lane = tid & 31, w = tid >> 5;
    if (lane == 0)
#pragma unroll
        for (int c = 0; c < CC; c++) wred[w][c] = part[c];
    __syncthreads();
    if (tid < CC) {
        float s = cb[tid];
#pragma unroll
        for (int ww = 0; ww < 8; ww++) s += wred[ww][tid];
        g_em[(size_t)t * CC + tid] = s;
    }
}

// ================= CRF =================
__global__ void crf_kernel(const int* __restrict__ target,
                           const float* __restrict__ cstart,
                           const float* __restrict__ cend,
                           const float* __restrict__ ctrans,
                           float* __restrict__ out) {
    __shared__ float alpha[BB][CC];
    __shared__ float trans[CC][CC];
    __shared__ float den[BB], num[BB];
    int tid = threadIdx.x;

    if (tid < CC * CC) trans[tid / CC][tid % CC] = ctrans[tid];
    __syncthreads();

    int b = tid / CC, j = tid % CC;
    bool act = (tid < BB * CC);
    if (act) alpha[b][j] = cstart[j] + g_em[(size_t)(b * SS) * CC + j];
    __syncthreads();

    for (int s = 1; s < SS; s++) {
        float nv = 0.f;
        if (act) {
            float m = -1e30f;
#pragma unroll
            for (int i = 0; i < CC; i++) m = fmaxf(m, alpha[b][i] + trans[i][j]);
            float sum = 0.f;
#pragma unroll
            for (int i = 0; i < CC; i++) sum += __expf(alpha[b][i] + trans[i][j] - m);
            nv = m + __logf(sum) + g_em[(size_t)(b * SS + s) * CC + j];
            if (!(target[b * SS + s] > -1)) nv = alpha[b][j];
        }
        __syncthreads();
        if (act) alpha[b][j] = nv;
        __syncthreads();
    }

    if (act && j == 0) {
        float m = -1e30f;
#pragma unroll
        for (int jj = 0; jj < CC; jj++) m = fmaxf(m, alpha[b][jj] + cend[jj]);
        float sum = 0.f;
#pragma unroll
        for (int jj = 0; jj < CC; jj++) sum += __expf(alpha[b][jj] + cend[jj] - m);
        den[b] = m + __logf(sum);

        const int* tb = target + b * SS;
        int cnt = 0;
        for (int s = 0; s < SS; s++) cnt += (tb[s] > -1) ? 1 : 0;
        int send = cnt - 1;
        int t0 = tb[0] < 0 ? 0 : tb[0];
        float nu = cstart[t0] + g_em[(size_t)(b * SS) * CC + t0];
        for (int s = 1; s < SS; s++) {
            int ts = tb[s], tp = tb[s - 1];
            float mk = (ts > -1) ? 1.f : 0.f;
            int tsc = ts < 0 ? 0 : ts, tpc = tp < 0 ? 0 : tp;
            nu += mk * (trans[tpc][tsc] + g_em[(size_t)(b * SS + s) * CC + tsc]);
        }
        int last = tb[send < 0 ? 0 : send];
        nu += cend[last < 0 ? 0 : last];
        num[b] = nu;
    }
    __syncthreads();
    if (tid == 0) {
        float L = 0.f;
        for (int bb = 0; bb < BB; bb++) L += num[bb] - den[bb];
        out[0] = -L / BB;
    }
}

// ================= launch =================
extern "C" void kernel_launch(void* const* d_in, const int* in_sizes, int n_in,
                              void* d_out, int out_size) {
    const int*   x          = (const int*)  d_in[0];
    const int*   target     = (const int*)  d_in[1];
    const float* word_emb   = (const float*)d_in[2];
    const float* pos_emb    = (const float*)d_in[3];
    const float* type_emb   = (const float*)d_in[4];
    const float* emb_ln_w   = (const float*)d_in[5];
    const float* emb_ln_b   = (const float*)d_in[6];
    const float* qkv_w      = (const float*)d_in[7];
    const float* qkv_b      = (const float*)d_in[8];
    const float* attn_out_w = (const float*)d_in[9];
    const float* attn_out_b = (const float*)d_in[10];
    const float* attn_ln_w  = (const float*)d_in[11];
    const float* attn_ln_b  = (const float*)d_in[12];
    const float* ffn_w1     = (const float*)d_in[13];
    const float* ffn_b1     = (const float*)d_in[14];
    const float* ffn_w2     = (const float*)d_in[15];
    const float* ffn_b2     = (const float*)d_in[16];
    const float* ffn_ln_w   = (const float*)d_in[17];
    const float* ffn_ln_b   = (const float*)d_in[18];
    const float* cls_w      = (const float*)d_in[19];
    const float* cls_b      = (const float*)d_in[20];
    const float* crf_start  = (const float*)d_in[21];
    const float* crf_end    = (const float*)d_in[22];
    const float* crf_trans  = (const float*)d_in[23];
    float* out = (float*)d_out;

    float *pt1, *pqkv;
    __nv_bfloat16 *ph_hi, *ph_lo, *pcx_hi, *pcx_lo, *pf_hi, *pf_lo;
    __nv_bfloat16 *pwq_hi, *pwq_lo, *pwa_hi, *pwa_lo, *pw1_hi, *pw1_lo, *pw2_hi, *pw2_lo;
    cudaGetSymbolAddress((void**)&pt1,    g_t1);
    cudaGetSymbolAddress((void**)&pqkv,   g_qkv);
    cudaGetSymbolAddress((void**)&ph_hi,  g_h_hi);
    cudaGetSymbolAddress((void**)&ph_lo,  g_h_lo);
    cudaGetSymbolAddress((void**)&pcx_hi, g_cx_hi);
    cudaGetSymbolAddress((void**)&pcx_lo, g_cx_lo);
    cudaGetSymbolAddress((void**)&pf_hi,  g_f_hi);
    cudaGetSymbolAddress((void**)&pf_lo,  g_f_lo);
    cudaGetSymbolAddress((void**)&pwq_hi, w_qkv_hi);
    cudaGetSymbolAddress((void**)&pwq_lo, w_qkv_lo);
    cudaGetSymbolAddress((void**)&pwa_hi, w_ao_hi);
    cudaGetSymbolAddress((void**)&pwa_lo, w_ao_lo);
    cudaGetSymbolAddress((void**)&pw1_hi, w_f1_hi);
    cudaGetSymbolAddress((void**)&pw1_lo, w_f1_lo);
    cudaGetSymbolAddress((void**)&pw2_hi, w_f2_hi);
    cudaGetSymbolAddress((void**)&pw2_lo, w_f2_lo);

    const int SMEM_ATTN = (128*64 + 64*256 + 256*64 + 32*256) * 4;   // 196608
    const int SMEM_G256 = 2 * (2*128*PADK + 2*256*PADK) * 2;         // 122880
    const int SMEM_G64  = 2 * (2*128*PADK + 2*64*PADK) * 2;          // 61440
    cudaFuncSetAttribute(attn_kernel_v4,
                         cudaFuncAttributeMaxDynamicSharedMemorySize, SMEM_ATTN);
    cudaFuncSetAttribute(k_mma256,
                         cudaFuncAttributeMaxDynamicSharedMemorySize, SMEM_G256);
    cudaFuncSetAttribute(k_mma<64>,
                         cudaFuncAttributeMaxDynamicSharedMemorySize, SMEM_G64);

    k_wsplit64<<<dim3(12, 12, 36), 256>>>(qkv_w,      pwq_hi, pwq_lo, HH, HH);
    k_wsplit64<<<dim3(12, 12, 12), 256>>>(attn_out_w, pwa_hi, pwa_lo, HH, HH);
    k_wsplit64<<<dim3(48, 12, 12), 256>>>(ffn_w1,     pw1_hi, pw1_lo, HH, FFF);
    k_wsplit64<<<dim3(12, 48, 12), 256>>>(ffn_w2,     pw2_hi, pw2_lo, FFF, HH);

    embed_ln_kernel<<<TOK, 256>>>(x, word_emb, pos_emb, type_emb, emb_ln_w, emb_ln_b);

    dim3 gQKV(3*HH / 256, TOK / 128);    // (9,16)  = 144 CTAs
    dim3 gF1 (FFF / 256,  TOK / 128);    // (12,16) = 192 CTAs
    dim3 gH64(HH / 64,    TOK / 128);    // (12,16) = 192 CTAs
    dim3 gA  (NHH, BB, 2);

    for (int l = 0; l < NLL; l++) {
        k_mma256<<<gQKV, 256, SMEM_G256>>>(ph_hi, ph_lo,
            pwq_hi + (size_t)l*3*HH*HH, pwq_lo + (size_t)l*3*HH*HH,
            qkv_b + (size_t)l*3*HH,
            pqkv, nullptr, nullptr,
            3*HH, HH, 0, (size_t)TOK*HH);

        attn_kernel_v4<<<gA, 256, SMEM_ATTN>>>();

        k_mma<64><<<gH64, 256, SMEM_G64>>>(pcx_hi, pcx_lo,
            pwa_hi + (size_t)l*HH*HH, pwa_lo + (size_t)l*HH*HH,
            attn_out_b + (size_t)l*HH,
            pt1, HH, HH);
        resid_ln_kernel<<<TOK, 256>>>(pt1, attn_ln_w + (size_t)l*HH, attn_ln_b + (size_t)l*HH);

        k_mma256<<<gF1, 256, SMEM_G256>>>(ph_hi, ph_lo,
            pw1_hi + (size_t)l*HH*FFF, pw1_lo + (size_t)l*HH*FFF,
            ffn_b1 + (size_t)l*FFF,
            nullptr, pf_hi, pf_lo,
            FFF, HH, 1, 0);

        k_mma<64><<<gH64, 256, SMEM_G64>>>(pf_hi, pf_lo,
            pw2_hi + (size_t)l*FFF*HH, pw2_lo + (size_t)l*FFF*HH,
            ffn_b2 + (size_t)l*HH,
            pt1, HH, FFF);
        resid_ln_kernel<<<TOK, 256>>>(pt1, ffn_ln_w + (size_t)l*HH, ffn_ln_b + (size_t)l*HH);
    }

    emissions_kernel<<<TOK, 256>>>(cls_w, cls_b);
    crf_kernel<<<1, 128>>>(target, crf_start, crf_end, crf_trans, out);
}

// round 10
// speedup vs baseline: 1.0711x; 1.0711x over previous
#include <cuda_runtime.h>
#include <cuda_bf16.h>
#include <math.h>
#include <stdint.h>

#define BB   8
#define SS   256
#define HH   768
#define NLL  12
#define NHH  12
#define FFF  3072
#define CC   9
#define DHH  64
#define TOK  (BB*SS)   // 2048

// ================= scratch =================
__device__ float                         g_h   [TOK*HH];
__device__ __align__(256) __nv_bfloat16  g_h_hi[TOK*HH];
__device__ __align__(256) __nv_bfloat16  g_h_lo[TOK*HH];
__device__ __align__(256) float          g_qkv [3*TOK*HH];
__device__ __align__(256) __nv_bfloat16  g_cx_hi[TOK*HH];
__device__ __align__(256) __nv_bfloat16  g_cx_lo[TOK*HH];
__device__ __align__(256) float          g_t1  [TOK*HH];
__device__ __align__(256) __nv_bfloat16  g_f_hi[TOK*FFF];
__device__ __align__(256) __nv_bfloat16  g_f_lo[TOK*FFF];
__device__ float                         g_em  [TOK*CC];

__device__ __align__(256) __nv_bfloat16 w_qkv_hi[NLL*3*HH*HH];
__device__ __align__(256) __nv_bfloat16 w_qkv_lo[NLL*3*HH*HH];
__device__ __align__(256) __nv_bfloat16 w_ao_hi [NLL*HH*HH];
__device__ __align__(256) __nv_bfloat16 w_ao_lo [NLL*HH*HH];
__device__ __align__(256) __nv_bfloat16 w_f1_hi [NLL*HH*FFF];
__device__ __align__(256) __nv_bfloat16 w_f1_lo [NLL*HH*FFF];
__device__ __align__(256) __nv_bfloat16 w_f2_hi [NLL*FFF*HH];
__device__ __align__(256) __nv_bfloat16 w_f2_lo [NLL*FFF*HH];

// ================= low-level helpers =================
__device__ __forceinline__ void cpa16(uint32_t dst, const void* src) {
    asm volatile("cp.async.cg.shared.global [%0], [%1], 16;"
                 :: "r"(dst), "l"(src) : "memory");
}
#define CP_COMMIT() asm volatile("cp.async.commit_group;" ::: "memory")
#define CP_WAIT1()  asm volatile("cp.async.wait_group 1;" ::: "memory")
#define CP_WAIT0()  asm volatile("cp.async.wait_group 0;" ::: "memory")

__device__ __forceinline__ void ldm_x4(uint32_t* r, uint32_t a) {
    asm volatile("ldmatrix.sync.aligned.m8n8.x4.shared.b16 {%0,%1,%2,%3}, [%4];"
                 : "=r"(r[0]), "=r"(r[1]), "=r"(r[2]), "=r"(r[3]) : "r"(a));
}
__device__ __forceinline__ void mma16816(float* c, const uint32_t* a, const uint32_t* b) {
    asm volatile("mma.sync.aligned.m16n8k16.row.col.f32.bf16.bf16.f32 "
        "{%0,%1,%2,%3}, {%4,%5,%6,%7}, {%8,%9}, {%0,%1,%2,%3};"
        : "+f"(c[0]), "+f"(c[1]), "+f"(c[2]), "+f"(c[3])
        : "r"(a[0]), "r"(a[1]), "r"(a[2]), "r"(a[3]), "r"(b[0]), "r"(b[1]));
}

__device__ __forceinline__ float gelu_tanh(float v) {
    float c = 0.7978845608028654f * (v + 0.044715f * v * v * v);
    return 0.5f * v * (1.f + tanhf(c));
}
__device__ __forceinline__ void split_bf16(float v, __nv_bfloat16& h, __nv_bfloat16& l) {
    h = __float2bfloat16(v);
    l = __float2bfloat16(v - __bfloat162float(h));
}

// ================= weight transpose + split =================
__global__ void k_wsplit64(const float* __restrict__ W,
                           __nv_bfloat16* __restrict__ hi,
                           __nv_bfloat16* __restrict__ lo,
                           int K, int N) {
    __shared__ float t[64][68];
    size_t moff = (size_t)blockIdx.z * K * N;
    int n0 = blockIdx.x * 64, k0 = blockIdx.y * 64;
    int tid = threadIdx.x;
#pragma unroll
    for (int i = 0; i < 4; i++) {
        int l4 = tid + i * 256;
        int r = l4 >> 4, c4 = (l4 & 15) * 4;
        *(float4*)&t[r][c4] = *(const float4*)&W[moff + (size_t)(k0 + r) * N + n0 + c4];
    }
    __syncthreads();
#pragma unroll
    for (int i = 0; i < 4; i++) {
        int l4 = tid + i * 256;
        int r = l4 >> 4, c4 = (l4 & 15) * 4;
        float v0 = t[c4 + 0][r], v1 = t[c4 + 1][r], v2 = t[c4 + 2][r], v3 = t[c4 + 3][r];
        __nv_bfloat16 h0,l0,h1,l1,h2,l2,h3,l3;
        split_bf16(v0,h0,l0); split_bf16(v1,h1,l1);
        split_bf16(v2,h2,l2); split_bf16(v3,h3,l3);
        size_t o = moff + (size_t)(n0 + r) * K + k0 + c4;
        __nv_bfloat162 hh0 = __halves2bfloat162(h0,h1), hh1 = __halves2bfloat162(h2,h3);
        __nv_bfloat162 ll0 = __halves2bfloat162(l0,l1), ll1 = __halves2bfloat162(l2,l3);
        *(uint2*)(hi + o) = make_uint2(*(uint32_t*)&hh0, *(uint32_t*)&hh1);
        *(uint2*)(lo + o) = make_uint2(*(uint32_t*)&ll0, *(uint32_t*)&ll1);
    }
}

// ================= HMMA GEMM (R8 structure, STAGES templated) =================
#define PADK 40

template<int BN, int STAGES>
__global__ __launch_bounds__(256, 2)
void k_mma(const __nv_bfloat16* __restrict__ A_hi,
           const __nv_bfloat16* __restrict__ A_lo,
           const __nv_bfloat16* __restrict__ B_hi,
           const __nv_bfloat16* __restrict__ B_lo,
           const float* __restrict__ bias,
           float* __restrict__ Cf,
           __nv_bfloat16* __restrict__ Chi,
           __nv_bfloat16* __restrict__ Clo,
           int N, int K, int mode,
           int zW, int zC, int zB)
{
    constexpr int WMW = (BN == 128) ? 2 : 4;
    constexpr int WTM = 128 / WMW;
    constexpr int MT  = WTM / 16;
    constexpr int ASZ = 128 * PADK;
    constexpr int BSZ = BN  * PADK;
    constexpr int STG = 2 * ASZ + 2 * BSZ;

    extern __shared__ __nv_bfloat16 smem_dyn[];
    uint32_t smb = (uint32_t)__cvta_generic_to_shared(smem_dyn);

    int tid = threadIdx.x, wid = tid >> 5, lane = tid & 31;
    int n0 = blockIdx.x * BN, m0 = blockIdx.y * 128, z = blockIdx.z;
    B_hi += (size_t)z * zW;  B_lo += (size_t)z * zW;
    bias += (size_t)z * zB;
    if (Cf) Cf += (size_t)z * zC;

    int wm = (wid % WMW) * WTM;
    int wn = (wid / WMW) * 32;

    float acc[MT][4][4];
#pragma unroll
    for (int mt = 0; mt < MT; mt++)
#pragma unroll
        for (int nt = 0; nt < 4; nt++)
#pragma unroll
            for (int f = 0; f < 4; f++) acc[mt][nt][f] = 0.f;

    auto load_stage = [&](int s, int k0) {
        uint32_t base = smb + (uint32_t)(s * STG) * 2;
#pragma unroll
        for (int i = 0; i < 2; i++) {
            int idx = tid + i * 256;
            int r = idx >> 2, ch = idx & 3;
            const char* g0 = (const char*)(A_hi + (size_t)(m0 + r) * K + k0) + ch * 16;
            const char* g1 = (const char*)(A_lo + (size_t)(m0 + r) * K + k0) + ch * 16;
            cpa16(base + (uint32_t)(r * PADK) * 2 + ch * 16, g0);
            cpa16(base + (uint32_t)(ASZ + r * PADK) * 2 + ch * 16, g1);
        }
#pragma unroll
        for (int i = 0; i < (BN * 4) / 256; i++) {
            int idx = tid + i * 256;
            int r = idx >> 2, ch = idx & 3;
            const char* g0 = (const char*)(B_hi + (size_t)(n0 + r) * K + k0) + ch * 16;
            const char* g1 = (const char*)(B_lo + (size_t)(n0 + r) * K + k0) + ch * 16;
            cpa16(base + (uint32_t)(2 * ASZ + r * PADK) * 2 + ch * 16, g0);
            cpa16(base + (uint32_t)(2 * ASZ + BSZ + r * PADK) * 2 + ch * 16, g1);
        }
    };

    int nc = K / 32;
    load_stage(0, 0);
    CP_COMMIT();
    load_stage(1, 32);
    CP_COMMIT();

    uint32_t aRow = (uint32_t)(wm + (lane & 15));
    uint32_t aK   = (uint32_t)((lane >> 4) * 8);
    uint32_t bRow = (uint32_t)(wn + ((lane >> 4) & 1) * 8 + (lane & 7));
    uint32_t bK   = (uint32_t)(((lane >> 3) & 1) * 8);

    for (int c = 0; c < nc; c++) {
        int b = c % STAGES;
        if (c == nc - 1) { CP_WAIT0(); } else { CP_WAIT1(); }
        __syncthreads();

        if (STAGES == 3) {
            if (c + 2 < nc) {
                load_stage((c + 2) % 3, (c + 2) * 32);
                CP_COMMIT();
            }
        }

        uint32_t sbase = smb + (uint32_t)(b * STG) * 2;
#pragma unroll
        for (int k16 = 0; k16 < 2; k16++) {
            uint32_t bh[2][4], bl[2][4];
#pragma unroll
            for (int np = 0; np < 2; np++) {
                uint32_t off = ((bRow + np * 16) * PADK + (uint32_t)(k16 * 16) + bK) * 2;
                ldm_x4(bh[np], sbase + (uint32_t)(2 * ASZ) * 2 + off);
                ldm_x4(bl[np], sbase + (uint32_t)(2 * ASZ + BSZ) * 2 + off);
            }
#pragma unroll
            for (int mt = 0; mt < MT; mt++) {
                uint32_t ah[4], al[4];
                uint32_t off = ((aRow + mt * 16) * PADK + (uint32_t)(k16 * 16) + aK) * 2;
                ldm_x4(ah, sbase + off);
                ldm_x4(al, sbase + (uint32_t)ASZ * 2 + off);
#pragma unroll
                for (int nt = 0; nt < 4; nt++) {
                    const uint32_t* Bh = &bh[nt >> 1][(nt & 1) * 2];
                    const uint32_t* Bl = &bl[nt >> 1][(nt & 1) * 2];
                    mma16816(acc[mt][nt], ah, Bh);
                    mma16816(acc[mt][nt], ah, Bl);
                    mma16816(acc[mt][nt], al, Bh);
                }
            }
        }

        if (STAGES == 2) {
            if (c + 2 < nc) {
                __syncthreads();
                load_stage(b, (c + 2) * 32);
                CP_COMMIT();
            }
        }
    }

    int rbase = m0 + wm + (lane >> 2);
#pragma unroll
    for (int mt = 0; mt < MT; mt++) {
        int row = rbase + mt * 16;
#pragma unroll
        for (int nt = 0; nt < 4; nt++) {
            int col = n0 + wn + nt * 8 + (lane & 3) * 2;
            float b0 = bias[col], b1 = bias[col + 1];
            float v0 = acc[mt][nt][0] + b0;
            float v1 = acc[mt][nt][1] + b1;
            float v2 = acc[mt][nt][2] + b0;
            float v3 = acc[mt][nt][3] + b1;
            if (mode == 0) {
                *(float2*)(Cf + (size_t)row * N + col)       = make_float2(v0, v1);
                *(float2*)(Cf + (size_t)(row + 8) * N + col) = make_float2(v2, v3);
            } else {
                v0 = gelu_tanh(v0); v1 = gelu_tanh(v1);
                v2 = gelu_tanh(v2); v3 = gelu_tanh(v3);
                __nv_bfloat16 h0, l0, h1, l1;
                split_bf16(v0, h0, l0); split_bf16(v1, h1, l1);
                *(__nv_bfloat162*)(Chi + (size_t)row * N + col) = __halves2bfloat162(h0, h1);
                *(__nv_bfloat162*)(Clo + (size_t)row * N + col) = __halves2bfloat162(l0, l1);
                split_bf16(v2, h0, l0); split_bf16(v3, h1, l1);
                *(__nv_bfloat162*)(Chi + (size_t)(row + 8) * N + col) = __halves2bfloat162(h0, h1);
                *(__nv_bfloat162*)(Clo + (size_t)(row + 8) * N + col) = __halves2bfloat162(l0, l1);
            }
        }
    }
}

// ================= embed + LN (float4) =================
__global__ void embed_ln_kernel(const int* __restrict__ x,
                                const float* __restrict__ we,
                                const float* __restrict__ pe,
                                const float* __restrict__ te,
                                const float* __restrict__ lw,
                                const float* __restrict__ lb) {
    int t = blockIdx.x, s = t % SS, tid = threadIdx.x;
    int wid = x[t];
    bool act = tid < 192;
    float4 v4 = make_float4(0.f, 0.f, 0.f, 0.f);
    if (act) {
        float4 a = *(const float4*)&we[(size_t)wid * HH + tid * 4];
        float4 b = *(const float4*)&pe[s * HH + tid * 4];
        float4 c = *(const float4*)&te[tid * 4];
        v4 = make_float4(a.x+b.x+c.x, a.y+b.y+c.y, a.z+b.z+c.z, a.w+b.w+c.w);
    }
    float sum = v4.x + v4.y + v4.z + v4.w;
    float sq  = v4.x*v4.x + v4.y*v4.y + v4.z*v4.z + v4.w*v4.w;
    __shared__ float red[256], red2[256];
    red[tid] = sum; red2[tid] = sq; __syncthreads();
    for (int off = 128; off > 0; off >>= 1) {
        if (tid < off) { red[tid] += red[tid+off]; red2[tid] += red2[tid+off]; }
        __syncthreads();
    }
    float m = red[0] * (1.f/HH), var = red2[0] * (1.f/HH) - m*m;
    float rstd = rsqrtf(var + 1e-12f);
    if (act) {
        float4 w4 = *(const float4*)&lw[tid*4];
        float4 b4 = *(const float4*)&lb[tid*4];
        float o0 = (v4.x-m)*rstd*w4.x + b4.x;
        float o1 = (v4.y-m)*rstd*w4.y + b4.y;
        float o2 = (v4.z-m)*rstd*w4.z + b4.z;
        float o3 = (v4.w-m)*rstd*w4.w + b4.w;
        size_t idx = (size_t)t * HH + tid * 4;
        *(float4*)&g_h[idx] = make_float4(o0,o1,o2,o3);
        __nv_bfloat16 h0,l0,h1,l1,h2,l2,h3,l3;
        split_bf16(o0,h0,l0); split_bf16(o1,h1,l1);
        split_bf16(o2,h2,l2); split_bf16(o3,h3,l3);
        __nv_bfloat162 hh0=__halves2bfloat162(h0,h1), hh1=__halves2bfloat162(h2,h3);
        __nv_bfloat162 ll0=__halves2bfloat162(l0,l1), ll1=__halves2bfloat162(l2,l3);
        *(uint2*)(g_h_hi + idx) = make_uint2(*(uint32_t*)&hh0, *(uint32_t*)&hh1);
        *(uint2*)(g_h_lo + idx) = make_uint2(*(uint32_t*)&ll0, *(uint32_t*)&ll1);
    }
}

// ================= residual + LN (float4) =================
__global__ void resid_ln_kernel(const float* __restrict__ add,
                                const float* __restrict__ lw,
                                const float* __restrict__ lb) {
    int t = blockIdx.x, tid = threadIdx.x;
    bool act = tid < 192;
    float4 v4 = make_float4(0.f, 0.f, 0.f, 0.f);
    size_t idx = (size_t)t * HH + tid * 4;
    if (act) {
        float4 a = *(const float4*)&g_h[idx];
        float4 b = *(const float4*)&add[idx];
        v4 = make_float4(a.x+b.x, a.y+b.y, a.z+b.z, a.w+b.w);
    }
    float sum = v4.x + v4.y + v4.z + v4.w;
    float sq  = v4.x*v4.x + v4.y*v4.y + v4.z*v4.z + v4.w*v4.w;
    __shared__ float red[256], red2[256];
    red[tid] = sum; red2[tid] = sq; __syncthreads();
    for (int off = 128; off > 0; off >>= 1) {
        if (tid < off) { red[tid] += red[tid+off]; red2[tid] += red2[tid+off]; }
        __syncthreads();
    }
    float m = red[0] * (1.f/HH), var = red2[0] * (1.f/HH) - m*m;
    float rstd = rsqrtf(var + 1e-12f);
    if (act) {
        float4 w4 = *(const float4*)&lw[tid*4];
        float4 b4 = *(const float4*)&lb[tid*4];
        float o0 = (v4.x-m)*rstd*w4.x + b4.x;
        float o1 = (v4.y-m)*rstd*w4.y + b4.y;
        float o2 = (v4.z-m)*rstd*w4.z + b4.z;
        float o3 = (v4.w-m)*rstd*w4.w + b4.w;
        *(float4*)&g_h[idx] = make_float4(o0,o1,o2,o3);
        __nv_bfloat16 h0,l0,h1,l1,h2,l2,h3,l3;
        split_bf16(o0,h0,l0); split_bf16(o1,h1,l1);
        split_bf16(o2,h2,l2); split_bf16(o3,h3,l3);
        __nv_bfloat162 hh0=__halves2bfloat162(h0,h1), hh1=__halves2bfloat162(h2,h3);
        __nv_bfloat162 ll0=__halves2bfloat162(l0,l1), ll1=__halves2bfloat162(l2,l3);
        *(uint2*)(g_h_hi + idx) = make_uint2(*(uint32_t*)&hh0, *(uint32_t*)&hh1);
        *(uint2*)(g_h_lo + idx) = make_uint2(*(uint32_t*)&ll0, *(uint32_t*)&ll1);
    }
}

// ================= attention v5: conflict-free smem =================
#define QS_STR 68
#define KT_STR 257
#define VS_STR 68

__global__ void attn_kernel_v5() {
    extern __shared__ float sm[];
    float* Qs = sm;                       // [128][QS_STR]
    float* KT = Qs + 128 * QS_STR;        // [64][KT_STR]
    float* Vs = KT + 64 * KT_STR;         // [256][VS_STR]
    float* Ps = Vs + 256 * VS_STR;        // [32][256]

    const float* gq = g_qkv;
    const float* gk = g_qkv + (size_t)TOK * HH;
    const float* gv = g_qkv + 2 * (size_t)TOK * HH;

    int h = blockIdx.x, b = blockIdx.y, qh = blockIdx.z;
    int tid = threadIdx.x, lane = tid & 31, w = tid >> 5;
    size_t base = (size_t)(b * SS) * HH + h * DHH;
    int qoff = qh * 128;

    for (int i = tid; i < 128 * 16; i += 256) {
        int r = i >> 4, c4 = (i & 15) * 4;
        *(float4*)&Qs[r * QS_STR + c4] =
            *(const float4*)&gq[base + (size_t)(qoff + r) * HH + c4];
    }
    for (int i = tid; i < 256 * 16; i += 256) {
        int r = i >> 4, c4 = (i & 15) * 4;
        size_t g = base + (size_t)r * HH + c4;
        *(float4*)&Vs[r * VS_STR + c4] = *(const float4*)&gv[g];
        float4 k4 = *(const float4*)&gk[g];
        KT[(c4 + 0) * KT_STR + r] = k4.x;
        KT[(c4 + 1) * KT_STR + r] = k4.y;
        KT[(c4 + 2) * KT_STR + r] = k4.z;
        KT[(c4 + 3) * KT_STR + r] = k4.w;
    }
    __syncthreads();

    for (int pass = 0; pass < 2; pass++) {
        int qbase = pass * 64 + w * 8;
        float acc[8][8];   // acc[i][j]: query qbase+i, key j*32+lane
#pragma unroll
        for (int i = 0; i < 8; i++)
#pragma unroll
            for (int j = 0; j < 8; j++) acc[i][j] = 0.f;

        for (int d4 = 0; d4 < 64; d4 += 4) {
            float ka[4][8];
#pragma unroll
            for (int dd = 0; dd < 4; dd++)
#pragma unroll
                for (int j = 0; j < 8; j++)
                    ka[dd][j] = KT[(d4 + dd) * KT_STR + j * 32 + lane];
#pragma unroll
            for (int i = 0; i < 8; i++) {
                float4 q4 = *(const float4*)&Qs[(qbase + i) * QS_STR + d4];
                float qv[4] = {q4.x, q4.y, q4.z, q4.w};
#pragma unroll
                for (int dd = 0; dd < 4; dd++)
#pragma unroll
                    for (int j = 0; j < 8; j++)
                        acc[i][j] += qv[dd] * ka[dd][j];
            }
        }

        float inv_[8];
#pragma unroll
        for (int i = 0; i < 8; i++) {
            float m = -1e30f;
#pragma unroll
            for (int j = 0; j < 8; j++) m = fmaxf(m, acc[i][j]);
#pragma unroll
            for (int off = 16; off > 0; off >>= 1)
                m = fmaxf(m, __shfl_xor_sync(0xffffffffu, m, off));
            float s = 0.f;
#pragma unroll
            for (int j = 0; j < 8; j++) {
                acc[i][j] = __expf(0.125f * (acc[i][j] - m));
                s += acc[i][j];
            }
#pragma unroll
            for (int off = 16; off > 0; off >>= 1)
                s += __shfl_xor_sync(0xffffffffu, s, off);
            inv_[i] = 1.f / s;
        }

        int d0 = lane * 2;  // each lane owns d = {2*lane, 2*lane+1}
#pragma unroll
        for (int chunk = 0; chunk < 2; chunk++) {
            // write probs: scalar stores, bank = lane -> conflict-free
#pragma unroll
            for (int ii = 0; ii < 4; ii++) {
                int i = chunk * 4 + ii;
                float iv = inv_[i];
#pragma unroll
                for (int j = 0; j < 8; j++)
                    Ps[(w * 4 + ii) * 256 + j * 32 + lane] = acc[i][j] * iv;
            }
            __syncwarp();

            float c[4][2];
#pragma unroll
            for (int ii = 0; ii < 4; ii++) { c[ii][0] = 0.f; c[ii][1] = 0.f; }

            for (int k4 = 0; k4 < 256; k4 += 4) {
                float2 v0 = *(const float2*)&Vs[(k4 + 0) * VS_STR + d0];
                float2 v1 = *(const float2*)&Vs[(k4 + 1) * VS_STR + d0];
                float2 v2 = *(const float2*)&Vs[(k4 + 2) * VS_STR + d0];
                float2 v3 = *(const float2*)&Vs[(k4 + 3) * VS_STR + d0];
#pragma unroll
                for (int ii = 0; ii < 4; ii++) {
                    float4 p4 = *(const float4*)&Ps[(w * 4 + ii) * 256 + k4];
                    c[ii][0] += p4.x * v0.x + p4.y * v1.x + p4.z * v2.x + p4.w * v3.x;
                    c[ii][1] += p4.x * v0.y + p4.y * v1.y + p4.z * v2.y + p4.w * v3.y;
                }
            }
#pragma unroll
            for (int ii = 0; ii < 4; ii++) {
                int q = qoff + qbase + chunk * 4 + ii;
                size_t idx = base + (size_t)q * HH + d0;
                __nv_bfloat16 h0, l0, h1, l1;
                split_bf16(c[ii][0], h0, l0);
                split_bf16(c[ii][1], h1, l1);
                __nv_bfloat162 hh = __halves2bfloat162(h0, h1);
                __nv_bfloat162 ll = __halves2bfloat162(l0, l1);
                *(uint32_t*)(g_cx_hi + idx) = *(uint32_t*)&hh;
                *(uint32_t*)(g_cx_lo + idx) = *(uint32_t*)&ll;
            }
            __syncwarp();
        }
    }
}

// ================= emissions =================
__global__ void emissions_kernel(const float* __restrict__ cw,
                                 const float* __restrict__ cb) {
    int t = blockIdx.x, tid = threadIdx.x;
    float part[CC];
#pragma unroll
    for (int c = 0; c < CC; c++) part[c] = 0.f;
    for (int k = tid; k < HH; k += 256) {
        float hv = g_h[(size_t)t * HH + k];
        const float* wr = cw + (size_t)k * CC;
#pragma unroll
        for (int c = 0; c < CC; c++) part[c] += hv * wr[c];
    }
#pragma unroll
    for (int c = 0; c < CC; c++)
        for (int off = 16; off > 0; off >>= 1)
            part[c] += __shfl_down_sync(0xffffffffu, part[c], off);

    __shared__ float wred[8][CC];
    int lane = tid & 31, w = tid >> 5;
    if (lane == 0)
#pragma unroll
        for (int c = 0; c < CC; c++) wred[w][c] = part[c];
    __syncthreads();
    if (tid < CC) {
        float s = cb[tid];
#pragma unroll
        for (int ww = 0; ww < 8; ww++) s += wred[ww][tid];
        g_em[(size_t)t * CC + tid] = s;
    }
}

// ================= CRF =================
__global__ void crf_kernel(const int* __restrict__ target,
                           const float* __restrict__ cstart,
                           const float* __restrict__ cend,
                           const float* __restrict__ ctrans,
                           float* __restrict__ out) {
    __shared__ float alpha[BB][CC];
    __shared__ float trans[CC][CC];
    __shared__ float den[BB], num[BB];
    int tid = threadIdx.x;

    if (tid < CC * CC) trans[tid / CC][tid % CC] = ctrans[tid];
    __syncthreads();

    int b = tid / CC, j = tid % CC;
    bool act = (tid < BB * CC);
    if (act) alpha[b][j] = cstart[j] + g_em[(size_t)(b * SS) * CC + j];
    __syncthreads();

    for (int s = 1; s < SS; s++) {
        float nv = 0.f;
        if (act) {
            float m = -1e30f;
#pragma unroll
            for (int i = 0; i < CC; i++) m = fmaxf(m, alpha[b][i] + trans[i][j]);
            float sum = 0.f;
#pragma unroll
            for (int i = 0; i < CC; i++) sum += __expf(alpha[b][i] + trans[i][j] - m);
            nv = m + __logf(sum) + g_em[(size_t)(b * SS + s) * CC + j];
            if (!(target[b * SS + s] > -1)) nv = alpha[b][j];
        }
        __syncthreads();
        if (act) alpha[b][j] = nv;
        __syncthreads();
    }

    if (act && j == 0) {
        float m = -1e30f;
#pragma unroll
        for (int jj = 0; jj < CC; jj++) m = fmaxf(m, alpha[b][jj] + cend[jj]);
        float sum = 0.f;
#pragma unroll
        for (int jj = 0; jj < CC; jj++) sum += __expf(alpha[b][jj] + cend[jj] - m);
        den[b] = m + __logf(sum);

        const int* tb = target + b * SS;
        int cnt = 0;
        for (int s = 0; s < SS; s++) cnt += (tb[s] > -1) ? 1 : 0;
        int send = cnt - 1;
        int t0 = tb[0] < 0 ? 0 : tb[0];
        float nu = cstart[t0] + g_em[(size_t)(b * SS) * CC + t0];
        for (int s = 1; s < SS; s++) {
            int ts = tb[s], tp = tb[s - 1];
            float mk = (ts > -1) ? 1.f : 0.f;
            int tsc = ts < 0 ? 0 : ts, tpc = tp < 0 ? 0 : tp;
            nu += mk * (trans[tpc][tsc] + g_em[(size_t)(b * SS + s) * CC + tsc]);
        }
        int last = tb[send < 0 ? 0 : send];
        nu += cend[last < 0 ? 0 : last];
        num[b] = nu;
    }
    __syncthreads();
    if (tid == 0) {
        float L = 0.f;
        for (int bb = 0; bb < BB; bb++) L += num[bb] - den[bb];
        out[0] = -L / BB;
    }
}

// ================= launch =================
extern "C" void kernel_launch(void* const* d_in, const int* in_sizes, int n_in,
                              void* d_out, int out_size) {
    const int*   x          = (const int*)  d_in[0];
    const int*   target     = (const int*)  d_in[1];
    const float* word_emb   = (const float*)d_in[2];
    const float* pos_emb    = (const float*)d_in[3];
    const float* type_emb   = (const float*)d_in[4];
    const float* emb_ln_w   = (const float*)d_in[5];
    const float* emb_ln_b   = (const float*)d_in[6];
    const float* qkv_w      = (const float*)d_in[7];
    const float* qkv_b      = (const float*)d_in[8];
    const float* attn_out_w = (const float*)d_in[9];
    const float* attn_out_b = (const float*)d_in[10];
    const float* attn_ln_w  = (const float*)d_in[11];
    const float* attn_ln_b  = (const float*)d_in[12];
    const float* ffn_w1     = (const float*)d_in[13];
    const float* ffn_b1     = (const float*)d_in[14];
    const float* ffn_w2     = (const float*)d_in[15];
    const float* ffn_b2     = (const float*)d_in[16];
    const float* ffn_ln_w   = (const float*)d_in[17];
    const float* ffn_ln_b   = (const float*)d_in[18];
    const float* cls_w      = (const float*)d_in[19];
    const float* cls_b      = (const float*)d_in[20];
    const float* crf_start  = (const float*)d_in[21];
    const float* crf_end    = (const float*)d_in[22];
    const float* crf_trans  = (const float*)d_in[23];
    float* out = (float*)d_out;

    float *pt1, *pqkv;
    __nv_bfloat16 *ph_hi, *ph_lo, *pcx_hi, *pcx_lo, *pf_hi, *pf_lo;
    __nv_bfloat16 *pwq_hi, *pwq_lo, *pwa_hi, *pwa_lo, *pw1_hi, *pw1_lo, *pw2_hi, *pw2_lo;
    cudaGetSymbolAddress((void**)&pt1,    g_t1);
    cudaGetSymbolAddress((void**)&pqkv,   g_qkv);
    cudaGetSymbolAddress((void**)&ph_hi,  g_h_hi);
    cudaGetSymbolAddress((void**)&ph_lo,  g_h_lo);
    cudaGetSymbolAddress((void**)&pcx_hi, g_cx_hi);
    cudaGetSymbolAddress((void**)&pcx_lo, g_cx_lo);
    cudaGetSymbolAddress((void**)&pf_hi,  g_f_hi);
    cudaGetSymbolAddress((void**)&pf_lo,  g_f_lo);
    cudaGetSymbolAddress((void**)&pwq_hi, w_qkv_hi);
    cudaGetSymbolAddress((void**)&pwq_lo, w_qkv_lo);
    cudaGetSymbolAddress((void**)&pwa_hi, w_ao_hi);
    cudaGetSymbolAddress((void**)&pwa_lo, w_ao_lo);
    cudaGetSymbolAddress((void**)&pw1_hi, w_f1_hi);
    cudaGetSymbolAddress((void**)&pw1_lo, w_f1_lo);
    cudaGetSymbolAddress((void**)&pw2_hi, w_f2_hi);
    cudaGetSymbolAddress((void**)&pw2_lo, w_f2_lo);

    const int SMEM_ATTN = (128*QS_STR + 64*KT_STR + 256*VS_STR + 32*256) * 4; // 203008
    const int SMEM_G128 = 2 * (2*128*PADK + 2*128*PADK) * 2;   // 81920
    const int SMEM_G64  = 3 * (2*128*PADK + 2*64*PADK) * 2;    // 92160
    cudaFuncSetAttribute(attn_kernel_v5,
                         cudaFuncAttributeMaxDynamicSharedMemorySize, SMEM_ATTN);
    cudaFuncSetAttribute(k_mma<128,2>,
                         cudaFuncAttributeMaxDynamicSharedMemorySize, SMEM_G128);
    cudaFuncSetAttribute(k_mma<64,3>,
                         cudaFuncAttributeMaxDynamicSharedMemorySize, SMEM_G64);

    k_wsplit64<<<dim3(12, 12, 36), 256>>>(qkv_w,      pwq_hi, pwq_lo, HH, HH);
    k_wsplit64<<<dim3(12, 12, 12), 256>>>(attn_out_w, pwa_hi, pwa_lo, HH, HH);
    k_wsplit64<<<dim3(48, 12, 12), 256>>>(ffn_w1,     pw1_hi, pw1_lo, HH, FFF);
    k_wsplit64<<<dim3(12, 48, 12), 256>>>(ffn_w2,     pw2_hi, pw2_lo, FFF, HH);

    embed_ln_kernel<<<TOK, 256>>>(x, word_emb, pos_emb, type_emb, emb_ln_w, emb_ln_b);

    dim3 gQKV(HH / 128, TOK / 128, 3);
    dim3 gH64(HH / 64,  TOK / 128, 1);
    dim3 gF  (FFF / 128, TOK / 128, 1);
    dim3 gA  (NHH, BB, 2);

    for (int l = 0; l < NLL; l++) {
        k_mma<128,2><<<gQKV, 256, SMEM_G128>>>(ph_hi, ph_lo,
            pwq_hi + (size_t)l*3*HH*HH, pwq_lo + (size_t)l*3*HH*HH,
            qkv_b + (size_t)l*3*HH,
            pqkv, nullptr, nullptr,
            HH, HH, 0, HH*HH, TOK*HH, HH);

        attn_kernel_v5<<<gA, 256, SMEM_ATTN>>>();

        k_mma<64,3><<<gH64, 256, SMEM_G64>>>(pcx_hi, pcx_lo,
            pwa_hi + (size_t)l*HH*HH, pwa_lo + (size_t)l*HH*HH,
            attn_out_b + (size_t)l*HH,
            pt1, nullptr, nullptr,
            HH, HH, 0, 0, 0, 0);
        resid_ln_kernel<<<TOK, 256>>>(pt1, attn_ln_w + (size_t)l*HH, attn_ln_b + (size_t)l*HH);

        k_mma<128,2><<<gF, 256, SMEM_G128>>>(ph_hi, ph_lo,
            pw1_hi + (size_t)l*HH*FFF, pw1_lo + (size_t)l*HH*FFF,
            ffn_b1 + (size_t)l*FFF,
            nullptr, pf_hi, pf_lo,
            FFF, HH, 1, 0, 0, 0);

        k_mma<64,3><<<gH64, 256, SMEM_G64>>>(pf_hi, pf_lo,
            pw2_hi + (size_t)l*FFF*HH, pw2_lo + (size_t)l*FFF*HH,
            ffn_b2 + (size_t)l*HH,
            pt1, nullptr, nullptr,
            HH, FFF, 0, 0, 0, 0);
        resid_ln_kernel<<<TOK, 256>>>(pt1, ffn_ln_w + (size_t)l*HH, ffn_ln_b + (size_t)l*HH);
    }

    emissions_kernel<<<TOK, 256>>>(cls_w, cls_b);
    crf_kernel<<<1, 128>>>(target, crf_start, crf_end, crf_trans, out);
}

// round 11
// speedup vs baseline: 1.4225x; 1.3281x over previous
#include <cuda_runtime.h>
#include <cuda_fp16.h>
#include <math.h>
#include <stdint.h>

#define BB   8
#define SS   256
#define HH   768
#define NLL  12
#define NHH  12
#define FFF  3072
#define CC   9
#define DHH  64
#define TOK  (BB*SS)   // 2048

// ================= scratch =================
__device__ float                  g_h   [TOK*HH];
__device__ __align__(256) __half  g_h16 [TOK*HH];
__device__ __align__(256) float   g_qkv [3*TOK*HH];
__device__ __align__(256) __half  g_cx16[TOK*HH];
__device__ __align__(256) float   g_t1  [TOK*HH];
__device__ __align__(256) __half  g_f16 [TOK*FFF];
__device__ float                  g_em  [TOK*CC];

__device__ __align__(256) __half w_qkv_hi[NLL*3*HH*HH];
__device__ __align__(256) __half w_qkv_lo[NLL*3*HH*HH];
__device__ __align__(256) __half w_ao_hi [NLL*HH*HH];
__device__ __align__(256) __half w_ao_lo [NLL*HH*HH];
__device__ __align__(256) __half w_f1_hi [NLL*HH*FFF];
__device__ __align__(256) __half w_f1_lo [NLL*HH*FFF];
__device__ __align__(256) __half w_f2_hi [NLL*FFF*HH];
__device__ __align__(256) __half w_f2_lo [NLL*FFF*HH];

// ================= low-level helpers =================
__device__ __forceinline__ void cpa16(uint32_t dst, const void* src) {
    asm volatile("cp.async.cg.shared.global [%0], [%1], 16;"
                 :: "r"(dst), "l"(src) : "memory");
}
#define CP_COMMIT() asm volatile("cp.async.commit_group;" ::: "memory")
#define CP_WAIT1()  asm volatile("cp.async.wait_group 1;" ::: "memory")
#define CP_WAIT0()  asm volatile("cp.async.wait_group 0;" ::: "memory")

__device__ __forceinline__ void ldm_x4(uint32_t* r, uint32_t a) {
    asm volatile("ldmatrix.sync.aligned.m8n8.x4.shared.b16 {%0,%1,%2,%3}, [%4];"
                 : "=r"(r[0]), "=r"(r[1]), "=r"(r[2]), "=r"(r[3]) : "r"(a));
}
__device__ __forceinline__ void mma16816(float* c, const uint32_t* a, const uint32_t* b) {
    asm volatile("mma.sync.aligned.m16n8k16.row.col.f32.f16.f16.f32 "
        "{%0,%1,%2,%3}, {%4,%5,%6,%7}, {%8,%9}, {%0,%1,%2,%3};"
        : "+f"(c[0]), "+f"(c[1]), "+f"(c[2]), "+f"(c[3])
        : "r"(a[0]), "r"(a[1]), "r"(a[2]), "r"(a[3]), "r"(b[0]), "r"(b[1]));
}

__device__ __forceinline__ float gelu_tanh(float v) {
    float c = 0.7978845608028654f * (v + 0.044715f * v * v * v);
    return 0.5f * v * (1.f + tanhf(c));
}
__device__ __forceinline__ void split_f16(float v, __half& h, __half& l) {
    h = __float2half(v);
    l = __float2half(v - __half2float(h));
}

// ================= weight transpose + split (fp16 hi/lo) =================
__global__ void k_wsplit64(const float* __restrict__ W,
                           __half* __restrict__ hi,
                           __half* __restrict__ lo,
                           int K, int N) {
    __shared__ float t[64][68];
    size_t moff = (size_t)blockIdx.z * K * N;
    int n0 = blockIdx.x * 64, k0 = blockIdx.y * 64;
    int tid = threadIdx.x;
#pragma unroll
    for (int i = 0; i < 4; i++) {
        int l4 = tid + i * 256;
        int r = l4 >> 4, c4 = (l4 & 15) * 4;
        *(float4*)&t[r][c4] = *(const float4*)&W[moff + (size_t)(k0 + r) * N + n0 + c4];
    }
    __syncthreads();
#pragma unroll
    for (int i = 0; i < 4; i++) {
        int l4 = tid + i * 256;
        int r = l4 >> 4, c4 = (l4 & 15) * 4;
        float v0 = t[c4 + 0][r], v1 = t[c4 + 1][r], v2 = t[c4 + 2][r], v3 = t[c4 + 3][r];
        __half h0,l0,h1,l1,h2,l2,h3,l3;
        split_f16(v0,h0,l0); split_f16(v1,h1,l1);
        split_f16(v2,h2,l2); split_f16(v3,h3,l3);
        size_t o = moff + (size_t)(n0 + r) * K + k0 + c4;
        __half2 hh0 = __halves2half2(h0,h1), hh1 = __halves2half2(h2,h3);
        __half2 ll0 = __halves2half2(l0,l1), ll1 = __halves2half2(l2,l3);
        *(uint2*)(hi + o) = make_uint2(*(uint32_t*)&hh0, *(uint32_t*)&hh1);
        *(uint2*)(lo + o) = make_uint2(*(uint32_t*)&ll0, *(uint32_t*)&ll1);
    }
}

// ================= HMMA GEMM: C = A(fp16) @ [Whi+Wlo]^T, 3-stage, 2 CTAs/SM =================
#define PADK 40

template<int BN>
__global__ __launch_bounds__(256, 2)
void k_mma(const __half* __restrict__ A,
           const __half* __restrict__ B_hi,
           const __half* __restrict__ B_lo,
           const float* __restrict__ bias,
           float* __restrict__ Cf,
           __half* __restrict__ Ch,
           int N, int K, int mode,
           int zW, int zC, int zB)
{
    constexpr int WMW = (BN == 128) ? 2 : 4;
    constexpr int WTM = 128 / WMW;
    constexpr int MT  = WTM / 16;
    constexpr int ASZ = 128 * PADK;        // halves
    constexpr int BSZ = BN  * PADK;
    constexpr int STG = ASZ + 2 * BSZ;

    extern __shared__ __half smem_dyn[];
    uint32_t smb = (uint32_t)__cvta_generic_to_shared(smem_dyn);

    int tid = threadIdx.x, wid = tid >> 5, lane = tid & 31;
    int n0 = blockIdx.x * BN, m0 = blockIdx.y * 128, z = blockIdx.z;
    B_hi += (size_t)z * zW;  B_lo += (size_t)z * zW;
    bias += (size_t)z * zB;
    if (Cf) Cf += (size_t)z * zC;

    int wm = (wid % WMW) * WTM;
    int wn = (wid / WMW) * 32;

    float acc[MT][4][4];
#pragma unroll
    for (int mt = 0; mt < MT; mt++)
#pragma unroll
        for (int nt = 0; nt < 4; nt++)
#pragma unroll
            for (int f = 0; f < 4; f++) acc[mt][nt][f] = 0.f;

    auto load_stage = [&](int s, int k0) {
        uint32_t base = smb + (uint32_t)(s * STG) * 2;
        // A: 128 rows x 4 chunks of 16B, single buffer
#pragma unroll
        for (int i = 0; i < 2; i++) {
            int idx = tid + i * 256;
            int r = idx >> 2, ch = idx & 3;
            const char* g0 = (const char*)(A + (size_t)(m0 + r) * K + k0) + ch * 16;
            cpa16(base + (uint32_t)(r * PADK) * 2 + ch * 16, g0);
        }
        // B hi/lo
#pragma unroll
        for (int i = 0; i < (BN * 4) / 256; i++) {
            int idx = tid + i * 256;
            int r = idx >> 2, ch = idx & 3;
            const char* g0 = (const char*)(B_hi + (size_t)(n0 + r) * K + k0) + ch * 16;
            const char* g1 = (const char*)(B_lo + (size_t)(n0 + r) * K + k0) + ch * 16;
            cpa16(base + (uint32_t)(ASZ + r * PADK) * 2 + ch * 16, g0);
            cpa16(base + (uint32_t)(ASZ + BSZ + r * PADK) * 2 + ch * 16, g1);
        }
    };

    int nc = K / 32;
    load_stage(0, 0);
    CP_COMMIT();
    load_stage(1, 32);
    CP_COMMIT();

    uint32_t aRow = (uint32_t)(wm + (lane & 15));
    uint32_t aK   = (uint32_t)((lane >> 4) * 8);
    uint32_t bRow = (uint32_t)(wn + ((lane >> 4) & 1) * 8 + (lane & 7));
    uint32_t bK   = (uint32_t)(((lane >> 3) & 1) * 8);

    for (int c = 0; c < nc; c++) {
        int b = c % 3;
        if (c == nc - 1) { CP_WAIT0(); } else { CP_WAIT1(); }
        __syncthreads();
        if (c + 2 < nc) {
            load_stage((c + 2) % 3, (c + 2) * 32);
            CP_COMMIT();
        }

        uint32_t sbase = smb + (uint32_t)(b * STG) * 2;
#pragma unroll
        for (int k16 = 0; k16 < 2; k16++) {
            uint32_t bh[2][4], bl[2][4];
#pragma unroll
            for (int np = 0; np < 2; np++) {
                uint32_t off = ((bRow + np * 16) * PADK + (uint32_t)(k16 * 16) + bK) * 2;
                ldm_x4(bh[np], sbase + (uint32_t)ASZ * 2 + off);
                ldm_x4(bl[np], sbase + (uint32_t)(ASZ + BSZ) * 2 + off);
            }
#pragma unroll
            for (int mt = 0; mt < MT; mt++) {
                uint32_t ah[4];
                uint32_t off = ((aRow + mt * 16) * PADK + (uint32_t)(k16 * 16) + aK) * 2;
                ldm_x4(ah, sbase + off);
#pragma unroll
                for (int nt = 0; nt < 4; nt++) {
                    const uint32_t* Bh = &bh[nt >> 1][(nt & 1) * 2];
                    const uint32_t* Bl = &bl[nt >> 1][(nt & 1) * 2];
                    mma16816(acc[mt][nt], ah, Bh);
                    mma16816(acc[mt][nt], ah, Bl);
                }
            }
        }
    }

    int rbase = m0 + wm + (lane >> 2);
#pragma unroll
    for (int mt = 0; mt < MT; mt++) {
        int row = rbase + mt * 16;
#pragma unroll
        for (int nt = 0; nt < 4; nt++) {
            int col = n0 + wn + nt * 8 + (lane & 3) * 2;
            float b0 = bias[col], b1 = bias[col + 1];
            float v0 = acc[mt][nt][0] + b0;
            float v1 = acc[mt][nt][1] + b1;
            float v2 = acc[mt][nt][2] + b0;
            float v3 = acc[mt][nt][3] + b1;
            if (mode == 0) {
                *(float2*)(Cf + (size_t)row * N + col)       = make_float2(v0, v1);
                *(float2*)(Cf + (size_t)(row + 8) * N + col) = make_float2(v2, v3);
            } else {
                v0 = gelu_tanh(v0); v1 = gelu_tanh(v1);
                v2 = gelu_tanh(v2); v3 = gelu_tanh(v3);
                __half2 p0 = __halves2half2(__float2half(v0), __float2half(v1));
                __half2 p1 = __halves2half2(__float2half(v2), __float2half(v3));
                *(__half2*)(Ch + (size_t)row * N + col)       = p0;
                *(__half2*)(Ch + (size_t)(row + 8) * N + col) = p1;
            }
        }
    }
}

// ================= embed + LN =================
__global__ void embed_ln_kernel(const int* __restrict__ x,
                                const float* __restrict__ we,
                                const float* __restrict__ pe,
                                const float* __restrict__ te,
                                const float* __restrict__ lw,
                                const float* __restrict__ lb) {
    int t = blockIdx.x, s = t % SS, tid = threadIdx.x;
    int wid = x[t];
    bool act = tid < 192;
    float4 v4 = make_float4(0.f, 0.f, 0.f, 0.f);
    if (act) {
        float4 a = *(const float4*)&we[(size_t)wid * HH + tid * 4];
        float4 b = *(const float4*)&pe[s * HH + tid * 4];
        float4 c = *(const float4*)&te[tid * 4];
        v4 = make_float4(a.x+b.x+c.x, a.y+b.y+c.y, a.z+b.z+c.z, a.w+b.w+c.w);
    }
    float sum = v4.x + v4.y + v4.z + v4.w;
    float sq  = v4.x*v4.x + v4.y*v4.y + v4.z*v4.z + v4.w*v4.w;
    __shared__ float red[256], red2[256];
    red[tid] = sum; red2[tid] = sq; __syncthreads();
    for (int off = 128; off > 0; off >>= 1) {
        if (tid < off) { red[tid] += red[tid+off]; red2[tid] += red2[tid+off]; }
        __syncthreads();
    }
    float m = red[0] * (1.f/HH), var = red2[0] * (1.f/HH) - m*m;
    float rstd = rsqrtf(var + 1e-12f);
    if (act) {
        float4 w4 = *(const float4*)&lw[tid*4];
        float4 b4 = *(const float4*)&lb[tid*4];
        float o0 = (v4.x-m)*rstd*w4.x + b4.x;
        float o1 = (v4.y-m)*rstd*w4.y + b4.y;
        float o2 = (v4.z-m)*rstd*w4.z + b4.z;
        float o3 = (v4.w-m)*rstd*w4.w + b4.w;
        size_t idx = (size_t)t * HH + tid * 4;
        *(float4*)&g_h[idx] = make_float4(o0,o1,o2,o3);
        __half2 p0 = __halves2half2(__float2half(o0), __float2half(o1));
        __half2 p1 = __halves2half2(__float2half(o2), __float2half(o3));
        *(uint2*)(g_h16 + idx) = make_uint2(*(uint32_t*)&p0, *(uint32_t*)&p1);
    }
}

// ================= residual + LN =================
__global__ void resid_ln_kernel(const float* __restrict__ add,
                                const float* __restrict__ lw,
                                const float* __restrict__ lb) {
    int t = blockIdx.x, tid = threadIdx.x;
    bool act = tid < 192;
    float4 v4 = make_float4(0.f, 0.f, 0.f, 0.f);
    size_t idx = (size_t)t * HH + tid * 4;
    if (act) {
        float4 a = *(const float4*)&g_h[idx];
        float4 b = *(const float4*)&add[idx];
        v4 = make_float4(a.x+b.x, a.y+b.y, a.z+b.z, a.w+b.w);
    }
    float sum = v4.x + v4.y + v4.z + v4.w;
    float sq  = v4.x*v4.x + v4.y*v4.y + v4.z*v4.z + v4.w*v4.w;
    __shared__ float red[256], red2[256];
    red[tid] = sum; red2[tid] = sq; __syncthreads();
    for (int off = 128; off > 0; off >>= 1) {
        if (tid < off) { red[tid] += red[tid+off]; red2[tid] += red2[tid+off]; }
        __syncthreads();
    }
    float m = red[0] * (1.f/HH), var = red2[0] * (1.f/HH) - m*m;
    float rstd = rsqrtf(var + 1e-12f);
    if (act) {
        float4 w4 = *(const float4*)&lw[tid*4];
        float4 b4 = *(const float4*)&lb[tid*4];
        float o0 = (v4.x-m)*rstd*w4.x + b4.x;
        float o1 = (v4.y-m)*rstd*w4.y + b4.y;
        float o2 = (v4.z-m)*rstd*w4.z + b4.z;
        float o3 = (v4.w-m)*rstd*w4.w + b4.w;
        *(float4*)&g_h[idx] = make_float4(o0,o1,o2,o3);
        __half2 p0 = __halves2half2(__float2half(o0), __float2half(o1));
        __half2 p1 = __halves2half2(__float2half(o2), __float2half(o3));
        *(uint2*)(g_h16 + idx) = make_uint2(*(uint32_t*)&p0, *(uint32_t*)&p1);
    }
}

// ================= attention v5 (conflict-free), ctx -> fp16 =================
#define QS_STR 68
#define KT_STR 257
#define VS_STR 68

__global__ void attn_kernel_v5() {
    extern __shared__ float sm[];
    float* Qs = sm;                       // [128][QS_STR]
    float* KT = Qs + 128 * QS_STR;        // [64][KT_STR]
    float* Vs = KT + 64 * KT_STR;         // [256][VS_STR]
    float* Ps = Vs + 256 * VS_STR;        // [32][256]

    const float* gq = g_qkv;
    const float* gk = g_qkv + (size_t)TOK * HH;
    const float* gv = g_qkv + 2 * (size_t)TOK * HH;

    int h = blockIdx.x, b = blockIdx.y, qh = blockIdx.z;
    int tid = threadIdx.x, lane = tid & 31, w = tid >> 5;
    size_t base = (size_t)(b * SS) * HH + h * DHH;
    int qoff = qh * 128;

    for (int i = tid; i < 128 * 16; i += 256) {
        int r = i >> 4, c4 = (i & 15) * 4;
        *(float4*)&Qs[r * QS_STR + c4] =
            *(const float4*)&gq[base + (size_t)(qoff + r) * HH + c4];
    }
    for (int i = tid; i < 256 * 16; i += 256) {
        int r = i >> 4, c4 = (i & 15) * 4;
        size_t g = base + (size_t)r * HH + c4;
        *(float4*)&Vs[r * VS_STR + c4] = *(const float4*)&gv[g];
        float4 k4 = *(const float4*)&gk[g];
        KT[(c4 + 0) * KT_STR + r] = k4.x;
        KT[(c4 + 1) * KT_STR + r] = k4.y;
        KT[(c4 + 2) * KT_STR + r] = k4.z;
        KT[(c4 + 3) * KT_STR + r] = k4.w;
    }
    __syncthreads();

    for (int pass = 0; pass < 2; pass++) {
        int qbase = pass * 64 + w * 8;
        float acc[8][8];
#pragma unroll
        for (int i = 0; i < 8; i++)
#pragma unroll
            for (int j = 0; j < 8; j++) acc[i][j] = 0.f;

        for (int d4 = 0; d4 < 64; d4 += 4) {
            float ka[4][8];
#pragma unroll
            for (int dd = 0; dd < 4; dd++)
#pragma unroll
                for (int j = 0; j < 8; j++)
                    ka[dd][j] = KT[(d4 + dd) * KT_STR + j * 32 + lane];
#pragma unroll
            for (int i = 0; i < 8; i++) {
                float4 q4 = *(const float4*)&Qs[(qbase + i) * QS_STR + d4];
                float qv[4] = {q4.x, q4.y, q4.z, q4.w};
#pragma unroll
                for (int dd = 0; dd < 4; dd++)
#pragma unroll
                    for (int j = 0; j < 8; j++)
                        acc[i][j] += qv[dd] * ka[dd][j];
            }
        }

        float inv_[8];
#pragma unroll
        for (int i = 0; i < 8; i++) {
            float m = -1e30f;
#pragma unroll
            for (int j = 0; j < 8; j++) m = fmaxf(m, acc[i][j]);
#pragma unroll
            for (int off = 16; off > 0; off >>= 1)
                m = fmaxf(m, __shfl_xor_sync(0xffffffffu, m, off));
            float s = 0.f;
#pragma unroll
            for (int j = 0; j < 8; j++) {
                acc[i][j] = __expf(0.125f * (acc[i][j] - m));
                s += acc[i][j];
            }
#pragma unroll
            for (int off = 16; off > 0; off >>= 1)
                s += __shfl_xor_sync(0xffffffffu, s, off);
            inv_[i] = 1.f / s;
        }

        int d0 = lane * 2;
#pragma unroll
        for (int chunk = 0; chunk < 2; chunk++) {
#pragma unroll
            for (int ii = 0; ii < 4; ii++) {
                int i = chunk * 4 + ii;
                float iv = inv_[i];
#pragma unroll
                for (int j = 0; j < 8; j++)
                    Ps[(w * 4 + ii) * 256 + j * 32 + lane] = acc[i][j] * iv;
            }
            __syncwarp();

            float c[4][2];
#pragma unroll
            for (int ii = 0; ii < 4; ii++) { c[ii][0] = 0.f; c[ii][1] = 0.f; }

            for (int k4 = 0; k4 < 256; k4 += 4) {
                float2 v0 = *(const float2*)&Vs[(k4 + 0) * VS_STR + d0];
                float2 v1 = *(const float2*)&Vs[(k4 + 1) * VS_STR + d0];
                float2 v2 = *(const float2*)&Vs[(k4 + 2) * VS_STR + d0];
                float2 v3 = *(const float2*)&Vs[(k4 + 3) * VS_STR + d0];
#pragma unroll
                for (int ii = 0; ii < 4; ii++) {
                    float4 p4 = *(const float4*)&Ps[(w * 4 + ii) * 256 + k4];
                    c[ii][0] += p4.x * v0.x + p4.y * v1.x + p4.z * v2.x + p4.w * v3.x;
                    c[ii][1] += p4.x * v0.y + p4.y * v1.y + p4.z * v2.y + p4.w * v3.y;
                }
            }
#pragma unroll
            for (int ii = 0; ii < 4; ii++) {
                int q = qoff + qbase + chunk * 4 + ii;
                size_t idx = base + (size_t)q * HH + d0;
                __half2 p = __halves2half2(__float2half(c[ii][0]), __float2half(c[ii][1]));
                *(uint32_t*)(g_cx16 + idx) = *(uint32_t*)&p;
            }
            __syncwarp();
        }
    }
}

// ================= emissions =================
__global__ void emissions_kernel(const float* __restrict__ cw,
                                 const float* __restrict__ cb) {
    int t = blockIdx.x, tid = threadIdx.x;
    float part[CC];
#pragma unroll
    for (int c = 0; c < CC; c++) part[c] = 0.f;
    for (int k = tid; k < HH; k += 256) {
        float hv = g_h[(size_t)t * HH + k];
        const float* wr = cw + (size_t)k * CC;
#pragma unroll
        for (int c = 0; c < CC; c++) part[c] += hv * wr[c];
    }
#pragma unroll
    for (int c = 0; c < CC; c++)
        for (int off = 16; off > 0; off >>= 1)
            part[c] += __shfl_down_sync(0xffffffffu, part[c], off);

    __shared__ float wred[8][CC];
    int lane = tid & 31, w = tid >> 5;
    if (lane == 0)
#pragma unroll
        for (int c = 0; c < CC; c++) wred[w][c] = part[c];
    __syncthreads();
    if (tid < CC) {
        float s = cb[tid];
#pragma unroll
        for (int ww = 0; ww < 8; ww++) s += wred[ww][tid];
        g_em[(size_t)t * CC + tid] = s;
    }
}

// ================= CRF =================
__global__ void crf_kernel(const int* __restrict__ target,
                           const float* __restrict__ cstart,
                           const float* __restrict__ cend,
                           const float* __restrict__ ctrans,
                           float* __restrict__ out) {
    __shared__ float alpha[BB][CC];
    __shared__ float trans[CC][CC];
    __shared__ float den[BB], num[BB];
    int tid = threadIdx.x;

    if (tid < CC * CC) trans[tid / CC][tid % CC] = ctrans[tid];
    __syncthreads();

    int b = tid / CC, j = tid % CC;
    bool act = (tid < BB * CC);
    if (act) alpha[b][j] = cstart[j] + g_em[(size_t)(b * SS) * CC + j];
    __syncthreads();

    for (int s = 1; s < SS; s++) {
        float nv = 0.f;
        if (act) {
            float m = -1e30f;
#pragma unroll
            for (int i = 0; i < CC; i++) m = fmaxf(m, alpha[b][i] + trans[i][j]);
            float sum = 0.f;
#pragma unroll
            for (int i = 0; i < CC; i++) sum += __expf(alpha[b][i] + trans[i][j] - m);
            nv = m + __logf(sum) + g_em[(size_t)(b * SS + s) * CC + j];
            if (!(target[b * SS + s] > -1)) nv = alpha[b][j];
        }
        __syncthreads();
        if (act) alpha[b][j] = nv;
        __syncthreads();
    }

    if (act && j == 0) {
        float m = -1e30f;
#pragma unroll
        for (int jj = 0; jj < CC; jj++) m = fmaxf(m, alpha[b][jj] + cend[jj]);
        float sum = 0.f;
#pragma unroll
        for (int jj = 0; jj < CC; jj++) sum += __expf(alpha[b][jj] + cend[jj] - m);
        den[b] = m + __logf(sum);

        const int* tb = target + b * SS;
        int cnt = 0;
        for (int s = 0; s < SS; s++) cnt += (tb[s] > -1) ? 1 : 0;
        int send = cnt - 1;
        int t0 = tb[0] < 0 ? 0 : tb[0];
        float nu = cstart[t0] + g_em[(size_t)(b * SS) * CC + t0];
        for (int s = 1; s < SS; s++) {
            int ts = tb[s], tp = tb[s - 1];
            float mk = (ts > -1) ? 1.f : 0.f;
            int tsc = ts < 0 ? 0 : ts, tpc = tp < 0 ? 0 : tp;
            nu += mk * (trans[tpc][tsc] + g_em[(size_t)(b * SS + s) * CC + tsc]);
        }
        int last = tb[send < 0 ? 0 : send];
        nu += cend[last < 0 ? 0 : last];
        num[b] = nu;
    }
    __syncthreads();
    if (tid == 0) {
        float L = 0.f;
        for (int bb = 0; bb < BB; bb++) L += num[bb] - den[bb];
        out[0] = -L / BB;
    }
}

// ================= launch =================
extern "C" void kernel_launch(void* const* d_in, const int* in_sizes, int n_in,
                              void* d_out, int out_size) {
    const int*   x          = (const int*)  d_in[0];
    const int*   target     = (const int*)  d_in[1];
    const float* word_emb   = (const float*)d_in[2];
    const float* pos_emb    = (const float*)d_in[3];
    const float* type_emb   = (const float*)d_in[4];
    const float* emb_ln_w   = (const float*)d_in[5];
    const float* emb_ln_b   = (const float*)d_in[6];
    const float* qkv_w      = (const float*)d_in[7];
    const float* qkv_b      = (const float*)d_in[8];
    const float* attn_out_w = (const float*)d_in[9];
    const float* attn_out_b = (const float*)d_in[10];
    const float* attn_ln_w  = (const float*)d_in[11];
    const float* attn_ln_b  = (const float*)d_in[12];
    const float* ffn_w1     = (const float*)d_in[13];
    const float* ffn_b1     = (const float*)d_in[14];
    const float* ffn_w2     = (const float*)d_in[15];
    const float* ffn_b2     = (const float*)d_in[16];
    const float* ffn_ln_w   = (const float*)d_in[17];
    const float* ffn_ln_b   = (const float*)d_in[18];
    const float* cls_w      = (const float*)d_in[19];
    const float* cls_b      = (const float*)d_in[20];
    const float* crf_start  = (const float*)d_in[21];
    const float* crf_end    = (const float*)d_in[22];
    const float* crf_trans  = (const float*)d_in[23];
    float* out = (float*)d_out;

    float *pt1, *pqkv;
    __half *ph16, *pcx16, *pf16;
    __half *pwq_hi, *pwq_lo, *pwa_hi, *pwa_lo, *pw1_hi, *pw1_lo, *pw2_hi, *pw2_lo;
    cudaGetSymbolAddress((void**)&pt1,   g_t1);
    cudaGetSymbolAddress((void**)&pqkv,  g_qkv);
    cudaGetSymbolAddress((void**)&ph16,  g_h16);
    cudaGetSymbolAddress((void**)&pcx16, g_cx16);
    cudaGetSymbolAddress((void**)&pf16,  g_f16);
    cudaGetSymbolAddress((void**)&pwq_hi, w_qkv_hi);
    cudaGetSymbolAddress((void**)&pwq_lo, w_qkv_lo);
    cudaGetSymbolAddress((void**)&pwa_hi, w_ao_hi);
    cudaGetSymbolAddress((void**)&pwa_lo, w_ao_lo);
    cudaGetSymbolAddress((void**)&pw1_hi, w_f1_hi);
    cudaGetSymbolAddress((void**)&pw1_lo, w_f1_lo);
    cudaGetSymbolAddress((void**)&pw2_hi, w_f2_hi);
    cudaGetSymbolAddress((void**)&pw2_lo, w_f2_lo);

    const int SMEM_ATTN = (128*QS_STR + 64*KT_STR + 256*VS_STR + 32*256) * 4; // 203008
    const int SMEM_G128 = 3 * (128*PADK + 2*128*PADK) * 2;   // 92160
    const int SMEM_G64  = 3 * (128*PADK + 2*64*PADK) * 2;    // 61440
    cudaFuncSetAttribute(attn_kernel_v5,
                         cudaFuncAttributeMaxDynamicSharedMemorySize, SMEM_ATTN);
    cudaFuncSetAttribute(k_mma<128>,
                         cudaFuncAttributeMaxDynamicSharedMemorySize, SMEM_G128);
    cudaFuncSetAttribute(k_mma<64>,
                         cudaFuncAttributeMaxDynamicSharedMemorySize, SMEM_G64);

    k_wsplit64<<<dim3(12, 12, 36), 256>>>(qkv_w,      pwq_hi, pwq_lo, HH, HH);
    k_wsplit64<<<dim3(12, 12, 12), 256>>>(attn_out_w, pwa_hi, pwa_lo, HH, HH);
    k_wsplit64<<<dim3(48, 12, 12), 256>>>(ffn_w1,     pw1_hi, pw1_lo, HH, FFF);
    k_wsplit64<<<dim3(12, 48, 12), 256>>>(ffn_w2,     pw2_hi, pw2_lo, FFF, HH);

    embed_ln_kernel<<<TOK, 256>>>(x, word_emb, pos_emb, type_emb, emb_ln_w, emb_ln_b);

    dim3 gQKV(HH / 128, TOK / 128, 3);
    dim3 gH64(HH / 64,  TOK / 128, 1);
    dim3 gF  (FFF / 128, TOK / 128, 1);
    dim3 gA  (NHH, BB, 2);

    for (int l = 0; l < NLL; l++) {
        k_mma<128><<<gQKV, 256, SMEM_G128>>>(ph16,
            pwq_hi + (size_t)l*3*HH*HH, pwq_lo + (size_t)l*3*HH*HH,
            qkv_b + (size_t)l*3*HH,
            pqkv, nullptr,
            HH, HH, 0, HH*HH, TOK*HH, HH);

        attn_kernel_v5<<<gA, 256, SMEM_ATTN>>>();

        k_mma<64><<<gH64, 256, SMEM_G64>>>(pcx16,
            pwa_hi + (size_t)l*HH*HH, pwa_lo + (size_t)l*HH*HH,
            attn_out_b + (size_t)l*HH,
            pt1, nullptr,
            HH, HH, 0, 0, 0, 0);
        resid_ln_kernel<<<TOK, 256>>>(pt1, attn_ln_w + (size_t)l*HH, attn_ln_b + (size_t)l*HH);

        k_mma<128><<<gF, 256, SMEM_G128>>>(ph16,
            pw1_hi + (size_t)l*HH*FFF, pw1_lo + (size_t)l*HH*FFF,
            ffn_b1 + (size_t)l*FFF,
            nullptr, pf16,
            FFF, HH, 1, 0, 0, 0);

        k_mma<64><<<gH64, 256, SMEM_G64>>>(pf16,
            pw2_hi + (size_t)l*FFF*HH, pw2_lo + (size_t)l*FFF*HH,
            ffn_b2 + (size_t)l*HH,
            pt1, nullptr,
            HH, FFF, 0, 0, 0, 0);
        resid_ln_kernel<<<TOK, 256>>>(pt1, ffn_ln_w + (size_t)l*HH, ffn_ln_b + (size_t)l*HH);
    }

    emissions_kernel<<<TOK, 256>>>(cls_w, cls_b);
    crf_kernel<<<1, 128>>>(target, crf_start, crf_end, crf_trans, out);
}

// round 12
// speedup vs baseline: 1.7604x; 1.2375x over previous
#include <cuda_runtime.h>
#include <cuda_fp16.h>
#include <math.h>
#include <stdint.h>

#define BB   8
#define SS   256
#define HH   768
#define NLL  12
#define NHH  12
#define FFF  3072
#define CC   9
#define DHH  64
#define TOK  (BB*SS)   // 2048

// ================= scratch =================
__device__ float                  g_h    [TOK*HH];
__device__ __align__(256) __half  g_h16  [TOK*HH];
__device__ __align__(256) __half  g_qkv16[3*TOK*HH];
__device__ __align__(256) __half  g_cx16 [TOK*HH];
__device__ __align__(256) float   g_t1   [TOK*HH];
__device__ __align__(256) __half  g_f16  [TOK*FFF];
__device__ float                  g_em   [TOK*CC];

__device__ __align__(256) __half w_qkv_hi[NLL*3*HH*HH];
__device__ __align__(256) __half w_qkv_lo[NLL*3*HH*HH];
__device__ __align__(256) __half w_ao_hi [NLL*HH*HH];
__device__ __align__(256) __half w_ao_lo [NLL*HH*HH];
__device__ __align__(256) __half w_f1_hi [NLL*HH*FFF];
__device__ __align__(256) __half w_f1_lo [NLL*HH*FFF];
__device__ __align__(256) __half w_f2_hi [NLL*FFF*HH];
__device__ __align__(256) __half w_f2_lo [NLL*FFF*HH];

// ================= low-level helpers =================
__device__ __forceinline__ void cpa16(uint32_t dst, const void* src) {
    asm volatile("cp.async.cg.shared.global [%0], [%1], 16;"
                 :: "r"(dst), "l"(src) : "memory");
}
#define CP_COMMIT() asm volatile("cp.async.commit_group;" ::: "memory")
#define CP_WAIT1()  asm volatile("cp.async.wait_group 1;" ::: "memory")
#define CP_WAIT0()  asm volatile("cp.async.wait_group 0;" ::: "memory")

__device__ __forceinline__ void ldm_x4(uint32_t* r, uint32_t a) {
    asm volatile("ldmatrix.sync.aligned.m8n8.x4.shared.b16 {%0,%1,%2,%3}, [%4];"
                 : "=r"(r[0]), "=r"(r[1]), "=r"(r[2]), "=r"(r[3]) : "r"(a));
}
__device__ __forceinline__ void ldm_x4_t(uint32_t* r, uint32_t a) {
    asm volatile("ldmatrix.sync.aligned.m8n8.x4.trans.shared.b16 {%0,%1,%2,%3}, [%4];"
                 : "=r"(r[0]), "=r"(r[1]), "=r"(r[2]), "=r"(r[3]) : "r"(a));
}
__device__ __forceinline__ void mma16816(float* c, const uint32_t* a, const uint32_t* b) {
    asm volatile("mma.sync.aligned.m16n8k16.row.col.f32.f16.f16.f32 "
        "{%0,%1,%2,%3}, {%4,%5,%6,%7}, {%8,%9}, {%0,%1,%2,%3};"
        : "+f"(c[0]), "+f"(c[1]), "+f"(c[2]), "+f"(c[3])
        : "r"(a[0]), "r"(a[1]), "r"(a[2]), "r"(a[3]), "r"(b[0]), "r"(b[1]));
}

__device__ __forceinline__ float gelu_tanh(float v) {
    float c = 0.7978845608028654f * (v + 0.044715f * v * v * v);
    return 0.5f * v * (1.f + tanhf(c));
}
__device__ __forceinline__ void split_f16(float v, __half& h, __half& l) {
    h = __float2half(v);
    l = __float2half(v - __half2float(h));
}

// ================= weight transpose + split (fp16 hi/lo) =================
__global__ void k_wsplit64(const float* __restrict__ W,
                           __half* __restrict__ hi,
                           __half* __restrict__ lo,
                           int K, int N) {
    __shared__ float t[64][68];
    size_t moff = (size_t)blockIdx.z * K * N;
    int n0 = blockIdx.x * 64, k0 = blockIdx.y * 64;
    int tid = threadIdx.x;
#pragma unroll
    for (int i = 0; i < 4; i++) {
        int l4 = tid + i * 256;
        int r = l4 >> 4, c4 = (l4 & 15) * 4;
        *(float4*)&t[r][c4] = *(const float4*)&W[moff + (size_t)(k0 + r) * N + n0 + c4];
    }
    __syncthreads();
#pragma unroll
    for (int i = 0; i < 4; i++) {
        int l4 = tid + i * 256;
        int r = l4 >> 4, c4 = (l4 & 15) * 4;
        float v0 = t[c4 + 0][r], v1 = t[c4 + 1][r], v2 = t[c4 + 2][r], v3 = t[c4 + 3][r];
        __half h0,l0,h1,l1,h2,l2,h3,l3;
        split_f16(v0,h0,l0); split_f16(v1,h1,l1);
        split_f16(v2,h2,l2); split_f16(v3,h3,l3);
        size_t o = moff + (size_t)(n0 + r) * K + k0 + c4;
        __half2 hh0 = __halves2half2(h0,h1), hh1 = __halves2half2(h2,h3);
        __half2 ll0 = __halves2half2(l0,l1), ll1 = __halves2half2(l2,l3);
        *(uint2*)(hi + o) = make_uint2(*(uint32_t*)&hh0, *(uint32_t*)&hh1);
        *(uint2*)(lo + o) = make_uint2(*(uint32_t*)&ll0, *(uint32_t*)&ll1);
    }
}

// ================= HMMA GEMM: C = A(fp16) @ [Whi+Wlo]^T, 3-stage =================
// mode 0: fp32 out (Cf, + z*zC). mode 1: gelu->fp16 (Ch). mode 2: fp16 out (Ch + z*zC).
#define PADK 40

template<int BN>
__global__ __launch_bounds__(256, 2)
void k_mma(const __half* __restrict__ A,
           const __half* __restrict__ B_hi,
           const __half* __restrict__ B_lo,
           const float* __restrict__ bias,
           float* __restrict__ Cf,
           __half* __restrict__ Ch,
           int N, int K, int mode,
           int zW, int zC, int zB)
{
    constexpr int WMW = (BN == 128) ? 2 : 4;
    constexpr int WTM = 128 / WMW;
    constexpr int MT  = WTM / 16;
    constexpr int ASZ = 128 * PADK;
    constexpr int BSZ = BN  * PADK;
    constexpr int STG = ASZ + 2 * BSZ;

    extern __shared__ __half smem_dyn[];
    uint32_t smb = (uint32_t)__cvta_generic_to_shared(smem_dyn);

    int tid = threadIdx.x, wid = tid >> 5, lane = tid & 31;
    int n0 = blockIdx.x * BN, m0 = blockIdx.y * 128, z = blockIdx.z;
    B_hi += (size_t)z * zW;  B_lo += (size_t)z * zW;
    bias += (size_t)z * zB;
    if (mode == 0 && Cf) Cf += (size_t)z * zC;
    if (mode == 2 && Ch) Ch += (size_t)z * zC;

    int wm = (wid % WMW) * WTM;
    int wn = (wid / WMW) * 32;

    float acc[MT][4][4];
#pragma unroll
    for (int mt = 0; mt < MT; mt++)
#pragma unroll
        for (int nt = 0; nt < 4; nt++)
#pragma unroll
            for (int f = 0; f < 4; f++) acc[mt][nt][f] = 0.f;

    auto load_stage = [&](int s, int k0) {
        uint32_t base = smb + (uint32_t)(s * STG) * 2;
#pragma unroll
        for (int i = 0; i < 2; i++) {
            int idx = tid + i * 256;
            int r = idx >> 2, ch = idx & 3;
            const char* g0 = (const char*)(A + (size_t)(m0 + r) * K + k0) + ch * 16;
            cpa16(base + (uint32_t)(r * PADK) * 2 + ch * 16, g0);
        }
#pragma unroll
        for (int i = 0; i < (BN * 4) / 256; i++) {
            int idx = tid + i * 256;
            int r = idx >> 2, ch = idx & 3;
            const char* g0 = (const char*)(B_hi + (size_t)(n0 + r) * K + k0) + ch * 16;
            const char* g1 = (const char*)(B_lo + (size_t)(n0 + r) * K + k0) + ch * 16;
            cpa16(base + (uint32_t)(ASZ + r * PADK) * 2 + ch * 16, g0);
            cpa16(base + (uint32_t)(ASZ + BSZ + r * PADK) * 2 + ch * 16, g1);
        }
    };

    int nc = K / 32;
    load_stage(0, 0);
    CP_COMMIT();
    load_stage(1, 32);
    CP_COMMIT();

    uint32_t aRow = (uint32_t)(wm + (lane & 15));
    uint32_t aK   = (uint32_t)((lane >> 4) * 8);
    uint32_t bRow = (uint32_t)(wn + ((lane >> 4) & 1) * 8 + (lane & 7));
    uint32_t bK   = (uint32_t)(((lane >> 3) & 1) * 8);

    for (int c = 0; c < nc; c++) {
        int b = c % 3;
        if (c == nc - 1) { CP_WAIT0(); } else { CP_WAIT1(); }
        __syncthreads();
        if (c + 2 < nc) {
            load_stage((c + 2) % 3, (c + 2) * 32);
            CP_COMMIT();
        }

        uint32_t sbase = smb + (uint32_t)(b * STG) * 2;
#pragma unroll
        for (int k16 = 0; k16 < 2; k16++) {
            uint32_t bh[2][4], bl[2][4];
#pragma unroll
            for (int np = 0; np < 2; np++) {
                uint32_t off = ((bRow + np * 16) * PADK + (uint32_t)(k16 * 16) + bK) * 2;
                ldm_x4(bh[np], sbase + (uint32_t)ASZ * 2 + off);
                ldm_x4(bl[np], sbase + (uint32_t)(ASZ + BSZ) * 2 + off);
            }
#pragma unroll
            for (int mt = 0; mt < MT; mt++) {
                uint32_t ah[4];
                uint32_t off = ((aRow + mt * 16) * PADK + (uint32_t)(k16 * 16) + aK) * 2;
                ldm_x4(ah, sbase + off);
#pragma unroll
                for (int nt = 0; nt < 4; nt++) {
                    const uint32_t* Bh = &bh[nt >> 1][(nt & 1) * 2];
                    const uint32_t* Bl = &bl[nt >> 1][(nt & 1) * 2];
                    mma16816(acc[mt][nt], ah, Bh);
                    mma16816(acc[mt][nt], ah, Bl);
                }
            }
        }
    }

    int rbase = m0 + wm + (lane >> 2);
#pragma unroll
    for (int mt = 0; mt < MT; mt++) {
        int row = rbase + mt * 16;
#pragma unroll
        for (int nt = 0; nt < 4; nt++) {
            int col = n0 + wn + nt * 8 + (lane & 3) * 2;
            float b0 = bias[col], b1 = bias[col + 1];
            float v0 = acc[mt][nt][0] + b0;
            float v1 = acc[mt][nt][1] + b1;
            float v2 = acc[mt][nt][2] + b0;
            float v3 = acc[mt][nt][3] + b1;
            if (mode == 0) {
                *(float2*)(Cf + (size_t)row * N + col)       = make_float2(v0, v1);
                *(float2*)(Cf + (size_t)(row + 8) * N + col) = make_float2(v2, v3);
            } else {
                if (mode == 1) {
                    v0 = gelu_tanh(v0); v1 = gelu_tanh(v1);
                    v2 = gelu_tanh(v2); v3 = gelu_tanh(v3);
                }
                __half2 p0 = __halves2half2(__float2half(v0), __float2half(v1));
                __half2 p1 = __halves2half2(__float2half(v2), __float2half(v3));
                *(__half2*)(Ch + (size_t)row * N + col)       = p0;
                *(__half2*)(Ch + (size_t)(row + 8) * N + col) = p1;
            }
        }
    }
}

// ================= embed + LN =================
__global__ void embed_ln_kernel(const int* __restrict__ x,
                                const float* __restrict__ we,
                                const float* __restrict__ pe,
                                const float* __restrict__ te,
                                const float* __restrict__ lw,
                                const float* __restrict__ lb) {
    int t = blockIdx.x, s = t % SS, tid = threadIdx.x;
    int wid = x[t];
    bool act = tid < 192;
    float4 v4 = make_float4(0.f, 0.f, 0.f, 0.f);
    if (act) {
        float4 a = *(const float4*)&we[(size_t)wid * HH + tid * 4];
        float4 b = *(const float4*)&pe[s * HH + tid * 4];
        float4 c = *(const float4*)&te[tid * 4];
        v4 = make_float4(a.x+b.x+c.x, a.y+b.y+c.y, a.z+b.z+c.z, a.w+b.w+c.w);
    }
    float sum = v4.x + v4.y + v4.z + v4.w;
    float sq  = v4.x*v4.x + v4.y*v4.y + v4.z*v4.z + v4.w*v4.w;
    __shared__ float red[256], red2[256];
    red[tid] = sum; red2[tid] = sq; __syncthreads();
    for (int off = 128; off > 0; off >>= 1) {
        if (tid < off) { red[tid] += red[tid+off]; red2[tid] += red2[tid+off]; }
        __syncthreads();
    }
    float m = red[0] * (1.f/HH), var = red2[0] * (1.f/HH) - m*m;
    float rstd = rsqrtf(var + 1e-12f);
    if (act) {
        float4 w4 = *(const float4*)&lw[tid*4];
        float4 b4 = *(const float4*)&lb[tid*4];
        float o0 = (v4.x-m)*rstd*w4.x + b4.x;
        float o1 = (v4.y-m)*rstd*w4.y + b4.y;
        float o2 = (v4.z-m)*rstd*w4.z + b4.z;
        float o3 = (v4.w-m)*rstd*w4.w + b4.w;
        size_t idx = (size_t)t * HH + tid * 4;
        *(float4*)&g_h[idx] = make_float4(o0,o1,o2,o3);
        __half2 p0 = __halves2half2(__float2half(o0), __float2half(o1));
        __half2 p1 = __halves2half2(__float2half(o2), __float2half(o3));
        *(uint2*)(g_h16 + idx) = make_uint2(*(uint32_t*)&p0, *(uint32_t*)&p1);
    }
}

// ================= residual + LN =================
__global__ void resid_ln_kernel(const float* __restrict__ add,
                                const float* __restrict__ lw,
                                const float* __restrict__ lb) {
    int t = blockIdx.x, tid = threadIdx.x;
    bool act = tid < 192;
    float4 v4 = make_float4(0.f, 0.f, 0.f, 0.f);
    size_t idx = (size_t)t * HH + tid * 4;
    if (act) {
        float4 a = *(const float4*)&g_h[idx];
        float4 b = *(const float4*)&add[idx];
        v4 = make_float4(a.x+b.x, a.y+b.y, a.z+b.z, a.w+b.w);
    }
    float sum = v4.x + v4.y + v4.z + v4.w;
    float sq  = v4.x*v4.x + v4.y*v4.y + v4.z*v4.z + v4.w*v4.w;
    __shared__ float red[256], red2[256];
    red[tid] = sum; red2[tid] = sq; __syncthreads();
    for (int off = 128; off > 0; off >>= 1) {
        if (tid < off) { red[tid] += red[tid+off]; red2[tid] += red2[tid+off]; }
        __syncthreads();
    }
    float m = red[0] * (1.f/HH), var = red2[0] * (1.f/HH) - m*m;
    float rstd = rsqrtf(var + 1e-12f);
    if (act) {
        float4 w4 = *(const float4*)&lw[tid*4];
        float4 b4 = *(const float4*)&lb[tid*4];
        float o0 = (v4.x-m)*rstd*w4.x + b4.x;
        float o1 = (v4.y-m)*rstd*w4.y + b4.y;
        float o2 = (v4.z-m)*rstd*w4.z + b4.z;
        float o3 = (v4.w-m)*rstd*w4.w + b4.w;
        *(float4*)&g_h[idx] = make_float4(o0,o1,o2,o3);
        __half2 p0 = __halves2half2(__float2half(o0), __float2half(o1));
        __half2 p1 = __halves2half2(__float2half(o2), __float2half(o3));
        *(uint2*)(g_h16 + idx) = make_uint2(*(uint32_t*)&p0, *(uint32_t*)&p1);
    }
}

// ================= attention v6: HMMA flash-style =================
// smem: Qs[128][72] | Ks[256][72] | Vs[256][72] (fp16)
#define AQ_STR 72
#define AK_STR 72
#define AV_STR 72

__global__ __launch_bounds__(256, 1)
void attn_kernel_v6() {
    extern __shared__ __half smh[];
    __half* Qs = smh;
    __half* Ks = Qs + 128 * AQ_STR;
    __half* Vs = Ks + 256 * AK_STR;
    uint32_t sQ = (uint32_t)__cvta_generic_to_shared(Qs);
    uint32_t sK = (uint32_t)__cvta_generic_to_shared(Ks);
    uint32_t sV = (uint32_t)__cvta_generic_to_shared(Vs);

    const __half* gq = g_qkv16;
    const __half* gk = g_qkv16 + (size_t)TOK * HH;
    const __half* gv = g_qkv16 + 2 * (size_t)TOK * HH;

    int h = blockIdx.x, b = blockIdx.y, qh = blockIdx.z;
    int tid = threadIdx.x, lane = tid & 31, w = tid >> 5;
    size_t base = (size_t)(b * SS) * HH + h * DHH;
    int qoff = qh * 128;

    // loads: rows of 64 halves = 8 x 16B chunks
    for (int i = tid; i < 128 * 8; i += 256) {
        int r = i >> 3, ch = i & 7;
        *(uint4*)&Qs[r * AQ_STR + ch * 8] =
            *(const uint4*)&gq[base + (size_t)(qoff + r) * HH + ch * 8];
    }
    for (int i = tid; i < 256 * 8; i += 256) {
        int r = i >> 3, ch = i & 7;
        size_t g = base + (size_t)r * HH + ch * 8;
        *(uint4*)&Ks[r * AK_STR + ch * 8] = *(const uint4*)&gk[g];
        *(uint4*)&Vs[r * AV_STR + ch * 8] = *(const uint4*)&gv[g];
    }
    __syncthreads();

    int wq = w * 16;   // warp's 16 query rows
    // ---- scores: S[16][256] as 16 n16-tiles of C frags ----
    float c[16][2][4];
#pragma unroll
    for (int t = 0; t < 16; t++)
#pragma unroll
        for (int f = 0; f < 2; f++)
#pragma unroll
            for (int k = 0; k < 4; k++) c[t][f][k] = 0.f;

    uint32_t aRow = (uint32_t)(wq + (lane & 15));
    uint32_t aCol = (uint32_t)((lane >> 4) * 8);
    uint32_t bRow = (uint32_t)(((lane >> 4) & 1) * 8 + (lane & 7));
    uint32_t bCol = (uint32_t)(((lane >> 3) & 1) * 8);

#pragma unroll
    for (int k16 = 0; k16 < 4; k16++) {
        uint32_t aq[4];
        ldm_x4(aq, sQ + (aRow * AQ_STR + (uint32_t)(k16 * 16) + aCol) * 2);
#pragma unroll
        for (int t = 0; t < 16; t++) {
            uint32_t bk[4];
            ldm_x4(bk, sK + ((bRow + (uint32_t)(t * 16)) * AK_STR +
                             (uint32_t)(k16 * 16) + bCol) * 2);
            mma16816(c[t][0], aq, &bk[0]);
            mma16816(c[t][1], aq, &bk[2]);
        }
    }

    // ---- softmax over rows r0 = lane>>2, r1 = r0+8 (quad shfl reduce) ----
    float m0 = -1e30f, m1 = -1e30f;
#pragma unroll
    for (int t = 0; t < 16; t++)
#pragma unroll
        for (int f = 0; f < 2; f++) {
            m0 = fmaxf(m0, fmaxf(c[t][f][0], c[t][f][1]));
            m1 = fmaxf(m1, fmaxf(c[t][f][2], c[t][f][3]));
        }
    m0 = fmaxf(m0, __shfl_xor_sync(0xffffffffu, m0, 1));
    m0 = fmaxf(m0, __shfl_xor_sync(0xffffffffu, m0, 2));
    m1 = fmaxf(m1, __shfl_xor_sync(0xffffffffu, m1, 1));
    m1 = fmaxf(m1, __shfl_xor_sync(0xffffffffu, m1, 2));

    float s0 = 0.f, s1 = 0.f;
#pragma unroll
    for (int t = 0; t < 16; t++)
#pragma unroll
        for (int f = 0; f < 2; f++) {
            c[t][f][0] = __expf(0.125f * (c[t][f][0] - m0));
            c[t][f][1] = __expf(0.125f * (c[t][f][1] - m0));
            c[t][f][2] = __expf(0.125f * (c[t][f][2] - m1));
            c[t][f][3] = __expf(0.125f * (c[t][f][3] - m1));
            s0 += c[t][f][0] + c[t][f][1];
            s1 += c[t][f][2] + c[t][f][3];
        }
    s0 += __shfl_xor_sync(0xffffffffu, s0, 1);
    s0 += __shfl_xor_sync(0xffffffffu, s0, 2);
    s1 += __shfl_xor_sync(0xffffffffu, s1, 1);
    s1 += __shfl_xor_sync(0xffffffffu, s1, 2);
    float iv0 = 1.f / s0, iv1 = 1.f / s1;

    // ---- ctx = P @ V via ldmatrix.trans on Vs[s][d] ----
    float ctx[8][4];
#pragma unroll
    for (int nf = 0; nf < 8; nf++)
#pragma unroll
        for (int k = 0; k < 4; k++) ctx[nf][k] = 0.f;

    uint32_t vRow = (uint32_t)((lane & 7) + ((lane >> 3) & 1) * 8);
    uint32_t vCol = (uint32_t)((lane >> 4) * 8);

#pragma unroll
    for (int t = 0; t < 16; t++) {
        uint32_t pa[4];
        __half2 h0 = __halves2half2(__float2half(c[t][0][0] * iv0),
                                    __float2half(c[t][0][1] * iv0));
        __half2 h1 = __halves2half2(__float2half(c[t][0][2] * iv1),
                                    __float2half(c[t][0][3] * iv1));
        __half2 h2 = __halves2half2(__float2half(c[t][1][0] * iv0),
                                    __float2half(c[t][1][1] * iv0));
        __half2 h3 = __halves2half2(__float2half(c[t][1][2] * iv1),
                                    __float2half(c[t][1][3] * iv1));
        pa[0] = *(uint32_t*)&h0;
        pa[1] = *(uint32_t*)&h1;
        pa[2] = *(uint32_t*)&h2;
        pa[3] = *(uint32_t*)&h3;
#pragma unroll
        for (int dn = 0; dn < 4; dn++) {
            uint32_t bv[4];
            ldm_x4_t(bv, sV + ((vRow + (uint32_t)(t * 16)) * AV_STR +
                               (uint32_t)(dn * 16) + vCol) * 2);
            mma16816(ctx[dn * 2 + 0], pa, &bv[0]);
            mma16816(ctx[dn * 2 + 1], pa, &bv[2]);
        }
    }

    // ---- epilogue ----
    int q0 = qoff + wq + (lane >> 2);
#pragma unroll
    for (int nf = 0; nf < 8; nf++) {
        int d = nf * 8 + (lane & 3) * 2;
        size_t i0 = base + (size_t)q0 * HH + d;
        size_t i1 = base + (size_t)(q0 + 8) * HH + d;
        __half2 p0 = __halves2half2(__float2half(ctx[nf][0]), __float2half(ctx[nf][1]));
        __half2 p1 = __halves2half2(__float2half(ctx[nf][2]), __float2half(ctx[nf][3]));
        *(uint32_t*)(g_cx16 + i0) = *(uint32_t*)&p0;
        *(uint32_t*)(g_cx16 + i1) = *(uint32_t*)&p1;
    }
}

// ================= emissions =================
__global__ void emissions_kernel(const float* __restrict__ cw,
                                 const float* __restrict__ cb) {
    int t = blockIdx.x, tid = threadIdx.x;
    float part[CC];
#pragma unroll
    for (int c = 0; c < CC; c++) part[c] = 0.f;
    for (int k = tid; k < HH; k += 256) {
        float hv = g_h[(size_t)t * HH + k];
        const float* wr = cw + (size_t)k * CC;
#pragma unroll
        for (int c = 0; c < CC; c++) part[c] += hv * wr[c];
    }
#pragma unroll
    for (int c = 0; c < CC; c++)
        for (int off = 16; off > 0; off >>= 1)
            part[c] += __shfl_down_sync(0xffffffffu, part[c], off);

    __shared__ float wred[8][CC];
    int lane = tid & 31, w = tid >> 5;
    if (lane == 0)
#pragma unroll
        for (int c = 0; c < CC; c++) wred[w][c] = part[c];
    __syncthreads();
    if (tid < CC) {
        float s = cb[tid];
#pragma unroll
        for (int ww = 0; ww < 8; ww++) s += wred[ww][tid];
        g_em[(size_t)t * CC + tid] = s;
    }
}

// ================= CRF =================
__global__ void crf_kernel(const int* __restrict__ target,
                           const float* __restrict__ cstart,
                           const float* __restrict__ cend,
                           const float* __restrict__ ctrans,
                           float* __restrict__ out) {
    __shared__ float alpha[BB][CC];
    __shared__ float trans[CC][CC];
    __shared__ float den[BB], num[BB];
    int tid = threadIdx.x;

    if (tid < CC * CC) trans[tid / CC][tid % CC] = ctrans[tid];
    __syncthreads();

    int b = tid / CC, j = tid % CC;
    bool act = (tid < BB * CC);
    if (act) alpha[b][j] = cstart[j] + g_em[(size_t)(b * SS) * CC + j];
    __syncthreads();

    for (int s = 1; s < SS; s++) {
        float nv = 0.f;
        if (act) {
            float m = -1e30f;
#pragma unroll
            for (int i = 0; i < CC; i++) m = fmaxf(m, alpha[b][i] + trans[i][j]);
            float sum = 0.f;
#pragma unroll
            for (int i = 0; i < CC; i++) sum += __expf(alpha[b][i] + trans[i][j] - m);
            nv = m + __logf(sum) + g_em[(size_t)(b * SS + s) * CC + j];
            if (!(target[b * SS + s] > -1)) nv = alpha[b][j];
        }
        __syncthreads();
        if (act) alpha[b][j] = nv;
        __syncthreads();
    }

    if (act && j == 0) {
        float m = -1e30f;
#pragma unroll
        for (int jj = 0; jj < CC; jj++) m = fmaxf(m, alpha[b][jj] + cend[jj]);
        float sum = 0.f;
#pragma unroll
        for (int jj = 0; jj < CC; jj++) sum += __expf(alpha[b][jj] + cend[jj] - m);
        den[b] = m + __logf(sum);

        const int* tb = target + b * SS;
        int cnt = 0;
        for (int s = 0; s < SS; s++) cnt += (tb[s] > -1) ? 1 : 0;
        int send = cnt - 1;
        int t0 = tb[0] < 0 ? 0 : tb[0];
        float nu = cstart[t0] + g_em[(size_t)(b * SS) * CC + t0];
        for (int s = 1; s < SS; s++) {
            int ts = tb[s], tp = tb[s - 1];
            float mk = (ts > -1) ? 1.f : 0.f;
            int tsc = ts < 0 ? 0 : ts, tpc = tp < 0 ? 0 : tp;
            nu += mk * (trans[tpc][tsc] + g_em[(size_t)(b * SS + s) * CC + tsc]);
        }
        int last = tb[send < 0 ? 0 : send];
        nu += cend[last < 0 ? 0 : last];
        num[b] = nu;
    }
    __syncthreads();
    if (tid == 0) {
        float L = 0.f;
        for (int bb = 0; bb < BB; bb++) L += num[bb] - den[bb];
        out[0] = -L / BB;
    }
}

// ================= launch =================
extern "C" void kernel_launch(void* const* d_in, const int* in_sizes, int n_in,
                              void* d_out, int out_size) {
    const int*   x          = (const int*)  d_in[0];
    const int*   target     = (const int*)  d_in[1];
    const float* word_emb   = (const float*)d_in[2];
    const float* pos_emb    = (const float*)d_in[3];
    const float* type_emb   = (const float*)d_in[4];
    const float* emb_ln_w   = (const float*)d_in[5];
    const float* emb_ln_b   = (const float*)d_in[6];
    const float* qkv_w      = (const float*)d_in[7];
    const float* qkv_b      = (const float*)d_in[8];
    const float* attn_out_w = (const float*)d_in[9];
    const float* attn_out_b = (const float*)d_in[10];
    const float* attn_ln_w  = (const float*)d_in[11];
    const float* attn_ln_b  = (const float*)d_in[12];
    const float* ffn_w1     = (const float*)d_in[13];
    const float* ffn_b1     = (const float*)d_in[14];
    const float* ffn_w2     = (const float*)d_in[15];
    const float* ffn_b2     = (const float*)d_in[16];
    const float* ffn_ln_w   = (const float*)d_in[17];
    const float* ffn_ln_b   = (const float*)d_in[18];
    const float* cls_w      = (const float*)d_in[19];
    const float* cls_b      = (const float*)d_in[20];
    const float* crf_start  = (const float*)d_in[21];
    const float* crf_end    = (const float*)d_in[22];
    const float* crf_trans  = (const float*)d_in[23];
    float* out = (float*)d_out;

    float *pt1;
    __half *ph16, *pqkv16, *pcx16, *pf16;
    __half *pwq_hi, *pwq_lo, *pwa_hi, *pwa_lo, *pw1_hi, *pw1_lo, *pw2_hi, *pw2_lo;
    cudaGetSymbolAddress((void**)&pt1,    g_t1);
    cudaGetSymbolAddress((void**)&ph16,   g_h16);
    cudaGetSymbolAddress((void**)&pqkv16, g_qkv16);
    cudaGetSymbolAddress((void**)&pcx16,  g_cx16);
    cudaGetSymbolAddress((void**)&pf16,   g_f16);
    cudaGetSymbolAddress((void**)&pwq_hi, w_qkv_hi);
    cudaGetSymbolAddress((void**)&pwq_lo, w_qkv_lo);
    cudaGetSymbolAddress((void**)&pwa_hi, w_ao_hi);
    cudaGetSymbolAddress((void**)&pwa_lo, w_ao_lo);
    cudaGetSymbolAddress((void**)&pw1_hi, w_f1_hi);
    cudaGetSymbolAddress((void**)&pw1_lo, w_f1_lo);
    cudaGetSymbolAddress((void**)&pw2_hi, w_f2_hi);
    cudaGetSymbolAddress((void**)&pw2_lo, w_f2_lo);

    const int SMEM_ATTN = (128*AQ_STR + 256*AK_STR + 256*AV_STR) * 2; // 92160
    const int SMEM_G128 = 3 * (128*PADK + 2*128*PADK) * 2;            // 92160
    const int SMEM_G64  = 3 * (128*PADK + 2*64*PADK) * 2;             // 61440
    cudaFuncSetAttribute(attn_kernel_v6,
                         cudaFuncAttributeMaxDynamicSharedMemorySize, SMEM_ATTN);
    cudaFuncSetAttribute(k_mma<128>,
                         cudaFuncAttributeMaxDynamicSharedMemorySize, SMEM_G128);
    cudaFuncSetAttribute(k_mma<64>,
                         cudaFuncAttributeMaxDynamicSharedMemorySize, SMEM_G64);

    k_wsplit64<<<dim3(12, 12, 36), 256>>>(qkv_w,      pwq_hi, pwq_lo, HH, HH);
    k_wsplit64<<<dim3(12, 12, 12), 256>>>(attn_out_w, pwa_hi, pwa_lo, HH, HH);
    k_wsplit64<<<dim3(48, 12, 12), 256>>>(ffn_w1,     pw1_hi, pw1_lo, HH, FFF);
    k_wsplit64<<<dim3(12, 48, 12), 256>>>(ffn_w2,     pw2_hi, pw2_lo, FFF, HH);

    embed_ln_kernel<<<TOK, 256>>>(x, word_emb, pos_emb, type_emb, emb_ln_w, emb_ln_b);

    dim3 gQKV(HH / 128, TOK / 128, 3);
    dim3 gH64(HH / 64,  TOK / 128, 1);
    dim3 gF  (FFF / 128, TOK / 128, 1);
    dim3 gA  (NHH, BB, 2);

    for (int l = 0; l < NLL; l++) {
        k_mma<128><<<gQKV, 256, SMEM_G128>>>(ph16,
            pwq_hi + (size_t)l*3*HH*HH, pwq_lo + (size_t)l*3*HH*HH,
            qkv_b + (size_t)l*3*HH,
            nullptr, pqkv16,
            HH, HH, 2, HH*HH, TOK*HH, HH);

        attn_kernel_v6<<<gA, 256, SMEM_ATTN>>>();

        k_mma<64><<<gH64, 256, SMEM_G64>>>(pcx16,
            pwa_hi + (size_t)l*HH*HH, pwa_lo + (size_t)l*HH*HH,
            attn_out_b + (size_t)l*HH,
            pt1, nullptr,
            HH, HH, 0, 0, 0, 0);
        resid_ln_kernel<<<TOK, 256>>>(pt1, attn_ln_w + (size_t)l*HH, attn_ln_b + (size_t)l*HH);

        k_mma<128><<<gF, 256, SMEM_G128>>>(ph16,
            pw1_hi + (size_t)l*HH*FFF, pw1_lo + (size_t)l*HH*FFF,
            ffn_b1 + (size_t)l*FFF,
            nullptr, pf16,
            FFF, HH, 1, 0, 0, 0);

        k_mma<64><<<gH64, 256, SMEM_G64>>>(pf16,
            pw2_hi + (size_t)l*FFF*HH, pw2_lo + (size_t)l*FFF*HH,
            ffn_b2 + (size_t)l*HH,
            pt1, nullptr,
            HH, FFF, 0, 0, 0, 0);
        resid_ln_kernel<<<TOK, 256>>>(pt1, ffn_ln_w + (size_t)l*HH, ffn_ln_b + (size_t)l*HH);
    }

    emissions_kernel<<<TOK, 256>>>(cls_w, cls_b);
    crf_kernel<<<1, 128>>>(target, crf_start, crf_end, crf_trans, out);
}

// round 13
// speedup vs baseline: 2.4387x; 1.3853x over previous
#include <cuda_runtime.h>
#include <cuda_fp16.h>
#include <math.h>
#include <stdint.h>

#define BB   8
#define SS   256
#define HH   768
#define NLL  12
#define NHH  12
#define FFF  3072
#define CC   9
#define DHH  64
#define TOK  (BB*SS)   // 2048

// ================= scratch =================
__device__ float                  g_h    [TOK*HH];
__device__ __align__(256) __half  g_h16  [TOK*HH];
__device__ __align__(256) __half  g_qkv16[3*TOK*HH];
__device__ __align__(256) __half  g_cx16 [TOK*HH];
__device__ __align__(256) float   g_t1   [TOK*HH];
__device__ __align__(256) __half  g_f16  [TOK*FFF];
__device__ float                  g_em   [TOK*CC];

__device__ __align__(256) __half w_qkv16[NLL*3*HH*HH];
__device__ __align__(256) __half w_ao16 [NLL*HH*HH];
__device__ __align__(256) __half w_f116 [NLL*HH*FFF];
__device__ __align__(256) __half w_f216 [NLL*FFF*HH];

// ================= low-level helpers =================
__device__ __forceinline__ void cpa16(uint32_t dst, const void* src) {
    asm volatile("cp.async.cg.shared.global [%0], [%1], 16;"
                 :: "r"(dst), "l"(src) : "memory");
}
#define CP_COMMIT() asm volatile("cp.async.commit_group;" ::: "memory")
#define CP_WAIT1()  asm volatile("cp.async.wait_group 1;" ::: "memory")
#define CP_WAIT0()  asm volatile("cp.async.wait_group 0;" ::: "memory")

__device__ __forceinline__ void ldm_x4(uint32_t* r, uint32_t a) {
    asm volatile("ldmatrix.sync.aligned.m8n8.x4.shared.b16 {%0,%1,%2,%3}, [%4];"
                 : "=r"(r[0]), "=r"(r[1]), "=r"(r[2]), "=r"(r[3]) : "r"(a));
}
__device__ __forceinline__ void ldm_x4_t(uint32_t* r, uint32_t a) {
    asm volatile("ldmatrix.sync.aligned.m8n8.x4.trans.shared.b16 {%0,%1,%2,%3}, [%4];"
                 : "=r"(r[0]), "=r"(r[1]), "=r"(r[2]), "=r"(r[3]) : "r"(a));
}
__device__ __forceinline__ void mma16816(float* c, const uint32_t* a, const uint32_t* b) {
    asm volatile("mma.sync.aligned.m16n8k16.row.col.f32.f16.f16.f32 "
        "{%0,%1,%2,%3}, {%4,%5,%6,%7}, {%8,%9}, {%0,%1,%2,%3};"
        : "+f"(c[0]), "+f"(c[1]), "+f"(c[2]), "+f"(c[3])
        : "r"(a[0]), "r"(a[1]), "r"(a[2]), "r"(a[3]), "r"(b[0]), "r"(b[1]));
}

__device__ __forceinline__ float gelu_tanh(float v) {
    float c = 0.7978845608028654f * (v + 0.044715f * v * v * v);
    return 0.5f * v * (1.f + tanhf(c));
}

// ================= weight transpose + fp16 convert =================
__global__ void k_wconv64(const float* __restrict__ W,
                          __half* __restrict__ out,
                          int K, int N) {
    __shared__ float t[64][68];
    size_t moff = (size_t)blockIdx.z * K * N;
    int n0 = blockIdx.x * 64, k0 = blockIdx.y * 64;
    int tid = threadIdx.x;
#pragma unroll
    for (int i = 0; i < 4; i++) {
        int l4 = tid + i * 256;
        int r = l4 >> 4, c4 = (l4 & 15) * 4;
        *(float4*)&t[r][c4] = *(const float4*)&W[moff + (size_t)(k0 + r) * N + n0 + c4];
    }
    __syncthreads();
#pragma unroll
    for (int i = 0; i < 4; i++) {
        int l4 = tid + i * 256;
        int r = l4 >> 4, c4 = (l4 & 15) * 4;
        __half2 p0 = __halves2half2(__float2half(t[c4 + 0][r]), __float2half(t[c4 + 1][r]));
        __half2 p1 = __halves2half2(__float2half(t[c4 + 2][r]), __float2half(t[c4 + 3][r]));
        size_t o = moff + (size_t)(n0 + r) * K + k0 + c4;
        *(uint2*)(out + o) = make_uint2(*(uint32_t*)&p0, *(uint32_t*)&p1);
    }
}

// ================= HMMA GEMM: C = A(fp16) @ W16^T, 3-stage, 2 CTAs/SM =================
// mode 0: fp32 out (Cf + z*zC). mode 1: gelu->fp16 (Ch). mode 2: fp16 out (Ch + z*zC).
#define PADK 40

template<int BN>
__global__ __launch_bounds__(256, 2)
void k_mma(const __half* __restrict__ A,
           const __half* __restrict__ B16,
           const float* __restrict__ bias,
           float* __restrict__ Cf,
           __half* __restrict__ Ch,
           int N, int K, int mode,
           int zW, int zC, int zB)
{
    constexpr int WMW = (BN == 128) ? 2 : 4;
    constexpr int WTM = 128 / WMW;
    constexpr int MT  = WTM / 16;
    constexpr int ASZ = 128 * PADK;
    constexpr int BSZ = BN  * PADK;
    constexpr int STG = ASZ + BSZ;

    extern __shared__ __half smem_dyn[];
    uint32_t smb = (uint32_t)__cvta_generic_to_shared(smem_dyn);

    int tid = threadIdx.x, wid = tid >> 5, lane = tid & 31;
    int n0 = blockIdx.x * BN, m0 = blockIdx.y * 128, z = blockIdx.z;
    B16  += (size_t)z * zW;
    bias += (size_t)z * zB;
    if (mode == 0 && Cf) Cf += (size_t)z * zC;
    if (mode == 2 && Ch) Ch += (size_t)z * zC;

    int wm = (wid % WMW) * WTM;
    int wn = (wid / WMW) * 32;

    float acc[MT][4][4];
#pragma unroll
    for (int mt = 0; mt < MT; mt++)
#pragma unroll
        for (int nt = 0; nt < 4; nt++)
#pragma unroll
            for (int f = 0; f < 4; f++) acc[mt][nt][f] = 0.f;

    auto load_stage = [&](int s, int k0) {
        uint32_t base = smb + (uint32_t)(s * STG) * 2;
#pragma unroll
        for (int i = 0; i < 2; i++) {
            int idx = tid + i * 256;
            int r = idx >> 2, ch = idx & 3;
            const char* g0 = (const char*)(A + (size_t)(m0 + r) * K + k0) + ch * 16;
            cpa16(base + (uint32_t)(r * PADK) * 2 + ch * 16, g0);
        }
#pragma unroll
        for (int i = 0; i < (BN * 4) / 256; i++) {
            int idx = tid + i * 256;
            int r = idx >> 2, ch = idx & 3;
            const char* g0 = (const char*)(B16 + (size_t)(n0 + r) * K + k0) + ch * 16;
            cpa16(base + (uint32_t)(ASZ + r * PADK) * 2 + ch * 16, g0);
        }
    };

    int nc = K / 32;
    load_stage(0, 0);
    CP_COMMIT();
    load_stage(1, 32);
    CP_COMMIT();

    uint32_t aRow = (uint32_t)(wm + (lane & 15));
    uint32_t aK   = (uint32_t)((lane >> 4) * 8);
    uint32_t bRow = (uint32_t)(wn + ((lane >> 4) & 1) * 8 + (lane & 7));
    uint32_t bK   = (uint32_t)(((lane >> 3) & 1) * 8);

    for (int c = 0; c < nc; c++) {
        int b = c % 3;
        if (c == nc - 1) { CP_WAIT0(); } else { CP_WAIT1(); }
        __syncthreads();
        if (c + 2 < nc) {
            load_stage((c + 2) % 3, (c + 2) * 32);
            CP_COMMIT();
        }

        uint32_t sbase = smb + (uint32_t)(b * STG) * 2;
#pragma unroll
        for (int k16 = 0; k16 < 2; k16++) {
            uint32_t bh[2][4];
#pragma unroll
            for (int np = 0; np < 2; np++) {
                uint32_t off = ((bRow + np * 16) * PADK + (uint32_t)(k16 * 16) + bK) * 2;
                ldm_x4(bh[np], sbase + (uint32_t)ASZ * 2 + off);
            }
#pragma unroll
            for (int mt = 0; mt < MT; mt++) {
                uint32_t ah[4];
                uint32_t off = ((aRow + mt * 16) * PADK + (uint32_t)(k16 * 16) + aK) * 2;
                ldm_x4(ah, sbase + off);
#pragma unroll
                for (int nt = 0; nt < 4; nt++)
                    mma16816(acc[mt][nt], ah, &bh[nt >> 1][(nt & 1) * 2]);
            }
        }
    }

    int rbase = m0 + wm + (lane >> 2);
#pragma unroll
    for (int mt = 0; mt < MT; mt++) {
        int row = rbase + mt * 16;
#pragma unroll
        for (int nt = 0; nt < 4; nt++) {
            int col = n0 + wn + nt * 8 + (lane & 3) * 2;
            float b0 = bias[col], b1 = bias[col + 1];
            float v0 = acc[mt][nt][0] + b0;
            float v1 = acc[mt][nt][1] + b1;
            float v2 = acc[mt][nt][2] + b0;
            float v3 = acc[mt][nt][3] + b1;
            if (mode == 0) {
                *(float2*)(Cf + (size_t)row * N + col)       = make_float2(v0, v1);
                *(float2*)(Cf + (size_t)(row + 8) * N + col) = make_float2(v2, v3);
            } else {
                if (mode == 1) {
                    v0 = gelu_tanh(v0); v1 = gelu_tanh(v1);
                    v2 = gelu_tanh(v2); v3 = gelu_tanh(v3);
                }
                __half2 p0 = __halves2half2(__float2half(v0), __float2half(v1));
                __half2 p1 = __halves2half2(__float2half(v2), __float2half(v3));
                *(__half2*)(Ch + (size_t)row * N + col)       = p0;
                *(__half2*)(Ch + (size_t)(row + 8) * N + col) = p1;
            }
        }
    }
}

// ================= embed + LN =================
__global__ void embed_ln_kernel(const int* __restrict__ x,
                                const float* __restrict__ we,
                                const float* __restrict__ pe,
                                const float* __restrict__ te,
                                const float* __restrict__ lw,
                                const float* __restrict__ lb) {
    int t = blockIdx.x, s = t % SS, tid = threadIdx.x;
    int wid = x[t];
    bool act = tid < 192;
    float4 v4 = make_float4(0.f, 0.f, 0.f, 0.f);
    if (act) {
        float4 a = *(const float4*)&we[(size_t)wid * HH + tid * 4];
        float4 b = *(const float4*)&pe[s * HH + tid * 4];
        float4 c = *(const float4*)&te[tid * 4];
        v4 = make_float4(a.x+b.x+c.x, a.y+b.y+c.y, a.z+b.z+c.z, a.w+b.w+c.w);
    }
    float sum = v4.x + v4.y + v4.z + v4.w;
    float sq  = v4.x*v4.x + v4.y*v4.y + v4.z*v4.z + v4.w*v4.w;
    __shared__ float red[256], red2[256];
    red[tid] = sum; red2[tid] = sq; __syncthreads();
    for (int off = 128; off > 0; off >>= 1) {
        if (tid < off) { red[tid] += red[tid+off]; red2[tid] += red2[tid+off]; }
        __syncthreads();
    }
    float m = red[0] * (1.f/HH), var = red2[0] * (1.f/HH) - m*m;
    float rstd = rsqrtf(var + 1e-12f);
    if (act) {
        float4 w4 = *(const float4*)&lw[tid*4];
        float4 b4 = *(const float4*)&lb[tid*4];
        float o0 = (v4.x-m)*rstd*w4.x + b4.x;
        float o1 = (v4.y-m)*rstd*w4.y + b4.y;
        float o2 = (v4.z-m)*rstd*w4.z + b4.z;
        float o3 = (v4.w-m)*rstd*w4.w + b4.w;
        size_t idx = (size_t)t * HH + tid * 4;
        *(float4*)&g_h[idx] = make_float4(o0,o1,o2,o3);
        __half2 p0 = __halves2half2(__float2half(o0), __float2half(o1));
        __half2 p1 = __halves2half2(__float2half(o2), __float2half(o3));
        *(uint2*)(g_h16 + idx) = make_uint2(*(uint32_t*)&p0, *(uint32_t*)&p1);
    }
}

// ================= residual + LN =================
__global__ void resid_ln_kernel(const float* __restrict__ add,
                                const float* __restrict__ lw,
                                const float* __restrict__ lb) {
    int t = blockIdx.x, tid = threadIdx.x;
    bool act = tid < 192;
    float4 v4 = make_float4(0.f, 0.f, 0.f, 0.f);
    size_t idx = (size_t)t * HH + tid * 4;
    if (act) {
        float4 a = *(const float4*)&g_h[idx];
        float4 b = *(const float4*)&add[idx];
        v4 = make_float4(a.x+b.x, a.y+b.y, a.z+b.z, a.w+b.w);
    }
    float sum = v4.x + v4.y + v4.z + v4.w;
    float sq  = v4.x*v4.x + v4.y*v4.y + v4.z*v4.z + v4.w*v4.w;
    __shared__ float red[256], red2[256];
    red[tid] = sum; red2[tid] = sq; __syncthreads();
    for (int off = 128; off > 0; off >>= 1) {
        if (tid < off) { red[tid] += red[tid+off]; red2[tid] += red2[tid+off]; }
        __syncthreads();
    }
    float m = red[0] * (1.f/HH), var = red2[0] * (1.f/HH) - m*m;
    float rstd = rsqrtf(var + 1e-12f);
    if (act) {
        float4 w4 = *(const float4*)&lw[tid*4];
        float4 b4 = *(const float4*)&lb[tid*4];
        float o0 = (v4.x-m)*rstd*w4.x + b4.x;
        float o1 = (v4.y-m)*rstd*w4.y + b4.y;
        float o2 = (v4.z-m)*rstd*w4.z + b4.z;
        float o3 = (v4.w-m)*rstd*w4.w + b4.w;
        *(float4*)&g_h[idx] = make_float4(o0,o1,o2,o3);
        __half2 p0 = __halves2half2(__float2half(o0), __float2half(o1));
        __half2 p1 = __halves2half2(__float2half(o2), __float2half(o3));
        *(uint2*)(g_h16 + idx) = make_uint2(*(uint32_t*)&p0, *(uint32_t*)&p1);
    }
}

// ================= attention v6: HMMA flash-style =================
#define AQ_STR 72
#define AK_STR 72
#define AV_STR 72

__global__ __launch_bounds__(256, 1)
void attn_kernel_v6() {
    extern __shared__ __half smh[];
    __half* Qs = smh;
    __half* Ks = Qs + 128 * AQ_STR;
    __half* Vs = Ks + 256 * AK_STR;
    uint32_t sQ = (uint32_t)__cvta_generic_to_shared(Qs);
    uint32_t sK = (uint32_t)__cvta_generic_to_shared(Ks);
    uint32_t sV = (uint32_t)__cvta_generic_to_shared(Vs);

    const __half* gq = g_qkv16;
    const __half* gk = g_qkv16 + (size_t)TOK * HH;
    const __half* gv = g_qkv16 + 2 * (size_t)TOK * HH;

    int h = blockIdx.x, b = blockIdx.y, qh = blockIdx.z;
    int tid = threadIdx.x, lane = tid & 31, w = tid >> 5;
    size_t base = (size_t)(b * SS) * HH + h * DHH;
    int qoff = qh * 128;

    for (int i = tid; i < 128 * 8; i += 256) {
        int r = i >> 3, ch = i & 7;
        *(uint4*)&Qs[r * AQ_STR + ch * 8] =
            *(const uint4*)&gq[base + (size_t)(qoff + r) * HH + ch * 8];
    }
    for (int i = tid; i < 256 * 8; i += 256) {
        int r = i >> 3, ch = i & 7;
        size_t g = base + (size_t)r * HH + ch * 8;
        *(uint4*)&Ks[r * AK_STR + ch * 8] = *(const uint4*)&gk[g];
        *(uint4*)&Vs[r * AV_STR + ch * 8] = *(const uint4*)&gv[g];
    }
    __syncthreads();

    int wq = w * 16;
    float c[16][2][4];
#pragma unroll
    for (int t = 0; t < 16; t++)
#pragma unroll
        for (int f = 0; f < 2; f++)
#pragma unroll
            for (int k = 0; k < 4; k++) c[t][f][k] = 0.f;

    uint32_t aRow = (uint32_t)(wq + (lane & 15));
    uint32_t aCol = (uint32_t)((lane >> 4) * 8);
    uint32_t bRow = (uint32_t)(((lane >> 4) & 1) * 8 + (lane & 7));
    uint32_t bCol = (uint32_t)(((lane >> 3) & 1) * 8);

#pragma unroll
    for (int k16 = 0; k16 < 4; k16++) {
        uint32_t aq[4];
        ldm_x4(aq, sQ + (aRow * AQ_STR + (uint32_t)(k16 * 16) + aCol) * 2);
#pragma unroll
        for (int t = 0; t < 16; t++) {
            uint32_t bk[4];
            ldm_x4(bk, sK + ((bRow + (uint32_t)(t * 16)) * AK_STR +
                             (uint32_t)(k16 * 16) + bCol) * 2);
            mma16816(c[t][0], aq, &bk[0]);
            mma16816(c[t][1], aq, &bk[2]);
        }
    }

    float m0 = -1e30f, m1 = -1e30f;
#pragma unroll
    for (int t = 0; t < 16; t++)
#pragma unroll
        for (int f = 0; f < 2; f++) {
            m0 = fmaxf(m0, fmaxf(c[t][f][0], c[t][f][1]));
            m1 = fmaxf(m1, fmaxf(c[t][f][2], c[t][f][3]));
        }
    m0 = fmaxf(m0, __shfl_xor_sync(0xffffffffu, m0, 1));
    m0 = fmaxf(m0, __shfl_xor_sync(0xffffffffu, m0, 2));
    m1 = fmaxf(m1, __shfl_xor_sync(0xffffffffu, m1, 1));
    m1 = fmaxf(m1, __shfl_xor_sync(0xffffffffu, m1, 2));

    float s0 = 0.f, s1 = 0.f;
#pragma unroll
    for (int t = 0; t < 16; t++)
#pragma unroll
        for (int f = 0; f < 2; f++) {
            c[t][f][0] = __expf(0.125f * (c[t][f][0] - m0));
            c[t][f][1] = __expf(0.125f * (c[t][f][1] - m0));
            c[t][f][2] = __expf(0.125f * (c[t][f][2] - m1));
            c[t][f][3] = __expf(0.125f * (c[t][f][3] - m1));
            s0 += c[t][f][0] + c[t][f][1];
            s1 += c[t][f][2] + c[t][f][3];
        }
    s0 += __shfl_xor_sync(0xffffffffu, s0, 1);
    s0 += __shfl_xor_sync(0xffffffffu, s0, 2);
    s1 += __shfl_xor_sync(0xffffffffu, s1, 1);
    s1 += __shfl_xor_sync(0xffffffffu, s1, 2);
    float iv0 = 1.f / s0, iv1 = 1.f / s1;

    float ctx[8][4];
#pragma unroll
    for (int nf = 0; nf < 8; nf++)
#pragma unroll
        for (int k = 0; k < 4; k++) ctx[nf][k] = 0.f;

    uint32_t vRow = (uint32_t)((lane & 7) + ((lane >> 3) & 1) * 8);
    uint32_t vCol = (uint32_t)((lane >> 4) * 8);

#pragma unroll
    for (int t = 0; t < 16; t++) {
        uint32_t pa[4];
        __half2 h0 = __halves2half2(__float2half(c[t][0][0] * iv0),
                                    __float2half(c[t][0][1] * iv0));
        __half2 h1 = __halves2half2(__float2half(c[t][0][2] * iv1),
                                    __float2half(c[t][0][3] * iv1));
        __half2 h2 = __halves2half2(__float2half(c[t][1][0] * iv0),
                                    __float2half(c[t][1][1] * iv0));
        __half2 h3 = __halves2half2(__float2half(c[t][1][2] * iv1),
                                    __float2half(c[t][1][3] * iv1));
        pa[0] = *(uint32_t*)&h0;
        pa[1] = *(uint32_t*)&h1;
        pa[2] = *(uint32_t*)&h2;
        pa[3] = *(uint32_t*)&h3;
#pragma unroll
        for (int dn = 0; dn < 4; dn++) {
            uint32_t bv[4];
            ldm_x4_t(bv, sV + ((vRow + (uint32_t)(t * 16)) * AV_STR +
                               (uint32_t)(dn * 16) + vCol) * 2);
            mma16816(ctx[dn * 2 + 0], pa, &bv[0]);
            mma16816(ctx[dn * 2 + 1], pa, &bv[2]);
        }
    }

    int q0 = qoff + wq + (lane >> 2);
#pragma unroll
    for (int nf = 0; nf < 8; nf++) {
        int d = nf * 8 + (lane & 3) * 2;
        size_t i0 = base + (size_t)q0 * HH + d;
        size_t i1 = base + (size_t)(q0 + 8) * HH + d;
        __half2 p0 = __halves2half2(__float2half(ctx[nf][0]), __float2half(ctx[nf][1]));
        __half2 p1 = __halves2half2(__float2half(ctx[nf][2]), __float2half(ctx[nf][3]));
        *(uint32_t*)(g_cx16 + i0) = *(uint32_t*)&p0;
        *(uint32_t*)(g_cx16 + i1) = *(uint32_t*)&p1;
    }
}

// ================= emissions =================
__global__ void emissions_kernel(const float* __restrict__ cw,
                                 const float* __restrict__ cb) {
    int t = blockIdx.x, tid = threadIdx.x;
    float part[CC];
#pragma unroll
    for (int c = 0; c < CC; c++) part[c] = 0.f;
    for (int k = tid; k < HH; k += 256) {
        float hv = g_h[(size_t)t * HH + k];
        const float* wr = cw + (size_t)k * CC;
#pragma unroll
        for (int c = 0; c < CC; c++) part[c] += hv * wr[c];
    }
#pragma unroll
    for (int c = 0; c < CC; c++)
        for (int off = 16; off > 0; off >>= 1)
            part[c] += __shfl_down_sync(0xffffffffu, part[c], off);

    __shared__ float wred[8][CC];
    int lane = tid & 31, w = tid >> 5;
    if (lane == 0)
#pragma unroll
        for (int c = 0; c < CC; c++) wred[w][c] = part[c];
    __syncthreads();
    if (tid < CC) {
        float s = cb[tid];
#pragma unroll
        for (int ww = 0; ww < 8; ww++) s += wred[ww][tid];
        g_em[(size_t)t * CC + tid] = s;
    }
}

// ================= CRF =================
__global__ void crf_kernel(const int* __restrict__ target,
                           const float* __restrict__ cstart,
                           const float* __restrict__ cend,
                           const float* __restrict__ ctrans,
                           float* __restrict__ out) {
    __shared__ float alpha[BB][CC];
    __shared__ float trans[CC][CC];
    __shared__ float den[BB], num[BB];
    int tid = threadIdx.x;

    if (tid < CC * CC) trans[tid / CC][tid % CC] = ctrans[tid];
    __syncthreads();

    int b = tid / CC, j = tid % CC;
    bool act = (tid < BB * CC);
    if (act) alpha[b][j] = cstart[j] + g_em[(size_t)(b * SS) * CC + j];
    __syncthreads();

    for (int s = 1; s < SS; s++) {
        float nv = 0.f;
        if (act) {
            float m = -1e30f;
#pragma unroll
            for (int i = 0; i < CC; i++) m = fmaxf(m, alpha[b][i] + trans[i][j]);
            float sum = 0.f;
#pragma unroll
            for (int i = 0; i < CC; i++) sum += __expf(alpha[b][i] + trans[i][j] - m);
            nv = m + __logf(sum) + g_em[(size_t)(b * SS + s) * CC + j];
            if (!(target[b * SS + s] > -1)) nv = alpha[b][j];
        }
        __syncthreads();
        if (act) alpha[b][j] = nv;
        __syncthreads();
    }

    if (act && j == 0) {
        float m = -1e30f;
#pragma unroll
        for (int jj = 0; jj < CC; jj++) m = fmaxf(m, alpha[b][jj] + cend[jj]);
        float sum = 0.f;
#pragma unroll
        for (int jj = 0; jj < CC; jj++) sum += __expf(alpha[b][jj] + cend[jj] - m);
        den[b] = m + __logf(sum);

        const int* tb = target + b * SS;
        int cnt = 0;
        for (int s = 0; s < SS; s++) cnt += (tb[s] > -1) ? 1 : 0;
        int send = cnt - 1;
        int t0 = tb[0] < 0 ? 0 : tb[0];
        float nu = cstart[t0] + g_em[(size_t)(b * SS) * CC + t0];
        for (int s = 1; s < SS; s++) {
            int ts = tb[s], tp = tb[s - 1];
            float mk = (ts > -1) ? 1.f : 0.f;
            int tsc = ts < 0 ? 0 : ts, tpc = tp < 0 ? 0 : tp;
            nu += mk * (trans[tpc][tsc] + g_em[(size_t)(b * SS + s) * CC + tsc]);
        }
        int last = tb[send < 0 ? 0 : send];
        nu += cend[last < 0 ? 0 : last];
        num[b] = nu;
    }
    __syncthreads();
    if (tid == 0) {
        float L = 0.f;
        for (int bb = 0; bb < BB; bb++) L += num[bb] - den[bb];
        out[0] = -L / BB;
    }
}

// ================= launch =================
extern "C" void kernel_launch(void* const* d_in, const int* in_sizes, int n_in,
                              void* d_out, int out_size) {
    const int*   x          = (const int*)  d_in[0];
    const int*   target     = (const int*)  d_in[1];
    const float* word_emb   = (const float*)d_in[2];
    const float* pos_emb    = (const float*)d_in[3];
    const float* type_emb   = (const float*)d_in[4];
    const float* emb_ln_w   = (const float*)d_in[5];
    const float* emb_ln_b   = (const float*)d_in[6];
    const float* qkv_w      = (const float*)d_in[7];
    const float* qkv_b      = (const float*)d_in[8];
    const float* attn_out_w = (const float*)d_in[9];
    const float* attn_out_b = (const float*)d_in[10];
    const float* attn_ln_w  = (const float*)d_in[11];
    const float* attn_ln_b  = (const float*)d_in[12];
    const float* ffn_w1     = (const float*)d_in[13];
    const float* ffn_b1     = (const float*)d_in[14];
    const float* ffn_w2     = (const float*)d_in[15];
    const float* ffn_b2     = (const float*)d_in[16];
    const float* ffn_ln_w   = (const float*)d_in[17];
    const float* ffn_ln_b   = (const float*)d_in[18];
    const float* cls_w      = (const float*)d_in[19];
    const float* cls_b      = (const float*)d_in[20];
    const float* crf_start  = (const float*)d_in[21];
    const float* crf_end    = (const float*)d_in[22];
    const float* crf_trans  = (const float*)d_in[23];
    float* out = (float*)d_out;

    float *pt1;
    __half *ph16, *pqkv16, *pcx16, *pf16;
    __half *pwq, *pwa, *pw1, *pw2;
    cudaGetSymbolAddress((void**)&pt1,    g_t1);
    cudaGetSymbolAddress((void**)&ph16,   g_h16);
    cudaGetSymbolAddress((void**)&pqkv16, g_qkv16);
    cudaGetSymbolAddress((void**)&pcx16,  g_cx16);
    cudaGetSymbolAddress((void**)&pf16,   g_f16);
    cudaGetSymbolAddress((void**)&pwq, w_qkv16);
    cudaGetSymbolAddress((void**)&pwa, w_ao16);
    cudaGetSymbolAddress((void**)&pw1, w_f116);
    cudaGetSymbolAddress((void**)&pw2, w_f216);

    const int SMEM_ATTN = (128*AQ_STR + 256*AK_STR + 256*AV_STR) * 2; // 92160
    const int SMEM_G128 = 3 * (128*PADK + 128*PADK) * 2;              // 61440
    const int SMEM_G64  = 3 * (128*PADK + 64*PADK) * 2;               // 46080
    cudaFuncSetAttribute(attn_kernel_v6,
                         cudaFuncAttributeMaxDynamicSharedMemorySize, SMEM_ATTN);
    cudaFuncSetAttribute(k_mma<128>,
                         cudaFuncAttributeMaxDynamicSharedMemorySize, SMEM_G128);
    cudaFuncSetAttribute(k_mma<64>,
                         cudaFuncAttributeMaxDynamicSharedMemorySize, SMEM_G64);

    k_wconv64<<<dim3(12, 12, 36), 256>>>(qkv_w,      pwq, HH, HH);
    k_wconv64<<<dim3(12, 12, 12), 256>>>(attn_out_w, pwa, HH, HH);
    k_wconv64<<<dim3(48, 12, 12), 256>>>(ffn_w1,     pw1, HH, FFF);
    k_wconv64<<<dim3(12, 48, 12), 256>>>(ffn_w2,     pw2, FFF, HH);

    embed_ln_kernel<<<TOK, 256>>>(x, word_emb, pos_emb, type_emb, emb_ln_w, emb_ln_b);

    dim3 gQKV(HH / 128, TOK / 128, 3);
    dim3 gH64(HH / 64,  TOK / 128, 1);
    dim3 gF  (FFF / 128, TOK / 128, 1);
    dim3 gA  (NHH, BB, 2);

    for (int l = 0; l < NLL; l++) {
        k_mma<128><<<gQKV, 256, SMEM_G128>>>(ph16,
            pwq + (size_t)l*3*HH*HH,
            qkv_b + (size_t)l*3*HH,
            nullptr, pqkv16,
            HH, HH, 2, HH*HH, TOK*HH, HH);

        attn_kernel_v6<<<gA, 256, SMEM_ATTN>>>();

        k_mma<64><<<gH64, 256, SMEM_G64>>>(pcx16,
            pwa + (size_t)l*HH*HH,
            attn_out_b + (size_t)l*HH,
            pt1, nullptr,
            HH, HH, 0, 0, 0, 0);
        resid_ln_kernel<<<TOK, 256>>>(pt1, attn_ln_w + (size_t)l*HH, attn_ln_b + (size_t)l*HH);

        k_mma<128><<<gF, 256, SMEM_G128>>>(ph16,
            pw1 + (size_t)l*HH*FFF,
            ffn_b1 + (size_t)l*FFF,
            nullptr, pf16,
            FFF, HH, 1, 0, 0, 0);

        k_mma<64><<<gH64, 256, SMEM_G64>>>(pf16,
            pw2 + (size_t)l*FFF*HH,
            ffn_b2 + (size_t)l*HH,
            pt1, nullptr,
            HH, FFF, 0, 0, 0, 0);
        resid_ln_kernel<<<TOK, 256>>>(pt1, ffn_ln_w + (size_t)l*HH, ffn_ln_b + (size_t)l*HH);
    }

    emissions_kernel<<<TOK, 256>>>(cls_w, cls_b);
    crf_kernel<<<1, 128>>>(target, crf_start, crf_end, crf_trans, out);
}

// round 14
// speedup vs baseline: 2.6418x; 1.0833x over previous
#include <cuda_runtime.h>
#include <cuda_fp16.h>
#include <math.h>
#include <stdint.h>

#define BB   8
#define SS   256
#define HH   768
#define NLL  12
#define NHH  12
#define FFF  3072
#define CC   9
#define DHH  64
#define TOK  (BB*SS)   // 2048

// ================= scratch =================
__device__ float                  g_h    [TOK*HH];
__device__ __align__(256) __half  g_h16  [TOK*HH];
__device__ __align__(256) __half  g_qkv16[3*TOK*HH];
__device__ __align__(256) __half  g_cx16 [TOK*HH];
__device__ __align__(256) float   g_t1   [TOK*HH];
__device__ __align__(256) __half  g_f16  [TOK*FFF];
__device__ float                  g_em   [TOK*CC];

// fp16 weights in NATIVE [K][N] layout (no transpose)
__device__ __align__(256) __half w_qkv16[NLL*3*HH*HH];
__device__ __align__(256) __half w_ao16 [NLL*HH*HH];
__device__ __align__(256) __half w_f116 [NLL*HH*FFF];
__device__ __align__(256) __half w_f216 [NLL*FFF*HH];

// ================= low-level helpers =================
__device__ __forceinline__ void cpa16(uint32_t dst, const void* src) {
    asm volatile("cp.async.cg.shared.global [%0], [%1], 16;"
                 :: "r"(dst), "l"(src) : "memory");
}
#define CP_COMMIT() asm volatile("cp.async.commit_group;" ::: "memory")
#define CP_WAIT1()  asm volatile("cp.async.wait_group 1;" ::: "memory")
#define CP_WAIT0()  asm volatile("cp.async.wait_group 0;" ::: "memory")

__device__ __forceinline__ void ldm_x4(uint32_t* r, uint32_t a) {
    asm volatile("ldmatrix.sync.aligned.m8n8.x4.shared.b16 {%0,%1,%2,%3}, [%4];"
                 : "=r"(r[0]), "=r"(r[1]), "=r"(r[2]), "=r"(r[3]) : "r"(a));
}
__device__ __forceinline__ void ldm_x4_t(uint32_t* r, uint32_t a) {
    asm volatile("ldmatrix.sync.aligned.m8n8.x4.trans.shared.b16 {%0,%1,%2,%3}, [%4];"
                 : "=r"(r[0]), "=r"(r[1]), "=r"(r[2]), "=r"(r[3]) : "r"(a));
}
__device__ __forceinline__ void mma16816(float* c, const uint32_t* a, const uint32_t* b) {
    asm volatile("mma.sync.aligned.m16n8k16.row.col.f32.f16.f16.f32 "
        "{%0,%1,%2,%3}, {%4,%5,%6,%7}, {%8,%9}, {%0,%1,%2,%3};"
        : "+f"(c[0]), "+f"(c[1]), "+f"(c[2]), "+f"(c[3])
        : "r"(a[0]), "r"(a[1]), "r"(a[2]), "r"(a[3]), "r"(b[0]), "r"(b[1]));
}

__device__ __forceinline__ float gelu_tanh(float v) {
    float c = 0.7978845608028654f * (v + 0.044715f * v * v * v);
    return 0.5f * v * (1.f + tanhf(c));
}

// ================= streaming fp32 -> fp16 weight convert (no transpose) =================
__global__ void k_wconv(const float* __restrict__ W,
                        __half* __restrict__ out, size_t n) {
    size_t i = ((size_t)blockIdx.x * 256 + threadIdx.x) * 8;
    if (i < n) {
        float4 a = *(const float4*)(W + i);
        float4 b = *(const float4*)(W + i + 4);
        __half2 p0 = __halves2half2(__float2half(a.x), __float2half(a.y));
        __half2 p1 = __halves2half2(__float2half(a.z), __float2half(a.w));
        __half2 p2 = __halves2half2(__float2half(b.x), __float2half(b.y));
        __half2 p3 = __halves2half2(__float2half(b.z), __float2half(b.w));
        uint4 o;
        o.x = *(uint32_t*)&p0; o.y = *(uint32_t*)&p1;
        o.z = *(uint32_t*)&p2; o.w = *(uint32_t*)&p3;
        *(uint4*)(out + i) = o;
    }
}

// ================= HMMA GEMM: C = A(fp16,[M][K]) @ W(fp16,[K][N]), trans-B =================
// mode 0: fp32 out (Cf + z*zC). mode 1: gelu->fp16 (Ch). mode 2: fp16 out (Ch + z*zC).
#define PADK 40

template<int BN>
__global__ __launch_bounds__(256, 2)
void k_mma(const __half* __restrict__ A,
           const __half* __restrict__ B16,
           const float* __restrict__ bias,
           float* __restrict__ Cf,
           __half* __restrict__ Ch,
           int N, int K, int mode,
           int zW, int zC, int zB)
{
    constexpr int WMW  = (BN == 128) ? 2 : 4;
    constexpr int WTM  = 128 / WMW;
    constexpr int MT   = WTM / 16;
    constexpr int ASZ  = 128 * PADK;       // halves
    constexpr int BSTR = BN + 8;           // B row stride (halves)
    constexpr int BSZ  = 32 * BSTR;
    constexpr int STG  = ASZ + BSZ;
    constexpr int CB   = BN / 8;           // 16B chunks per B row

    extern __shared__ __half smem_dyn[];
    uint32_t smb = (uint32_t)__cvta_generic_to_shared(smem_dyn);

    int tid = threadIdx.x, wid = tid >> 5, lane = tid & 31;
    int n0 = blockIdx.x * BN, m0 = blockIdx.y * 128, z = blockIdx.z;
    B16  += (size_t)z * zW;
    bias += (size_t)z * zB;
    if (mode == 0 && Cf) Cf += (size_t)z * zC;
    if (mode == 2 && Ch) Ch += (size_t)z * zC;

    int wm = (wid % WMW) * WTM;
    int wn = (wid / WMW) * 32;

    float acc[MT][4][4];
#pragma unroll
    for (int mt = 0; mt < MT; mt++)
#pragma unroll
        for (int nt = 0; nt < 4; nt++)
#pragma unroll
            for (int f = 0; f < 4; f++) acc[mt][nt][f] = 0.f;

    auto load_stage = [&](int s, int k0) {
        uint32_t base = smb + (uint32_t)(s * STG) * 2;
        // A: [128][32] rows padded to PADK
#pragma unroll
        for (int i = 0; i < 2; i++) {
            int idx = tid + i * 256;
            int r = idx >> 2, ch = idx & 3;
            const char* g0 = (const char*)(A + (size_t)(m0 + r) * K + k0) + ch * 16;
            cpa16(base + (uint32_t)(r * PADK) * 2 + ch * 16, g0);
        }
        // B: [32 k-rows][BN cols], native [K][N] source
#pragma unroll
        for (int i = 0; i < (32 * CB) / 256; i++) {
            int idx = tid + i * 256;
            int r = idx / CB, ch = idx % CB;
            const char* g0 = (const char*)(B16 + (size_t)(k0 + r) * N + n0) + ch * 16;
            cpa16(base + (uint32_t)(ASZ + r * BSTR) * 2 + ch * 16, g0);
        }
    };

    int nc = K / 32;
    load_stage(0, 0);
    CP_COMMIT();
    load_stage(1, 32);
    CP_COMMIT();

    uint32_t aRow  = (uint32_t)(wm + (lane & 15));
    uint32_t aK    = (uint32_t)((lane >> 4) * 8);
    uint32_t bkRow = (uint32_t)((lane & 7) + ((lane >> 3) & 1) * 8);
    uint32_t bkCol = (uint32_t)((lane >> 4) * 8);

    for (int c = 0; c < nc; c++) {
        int b = c % 3;
        if (c == nc - 1) { CP_WAIT0(); } else { CP_WAIT1(); }
        __syncthreads();
        if (c + 2 < nc) {
            load_stage((c + 2) % 3, (c + 2) * 32);
            CP_COMMIT();
        }

        uint32_t sbase = smb + (uint32_t)(b * STG) * 2;
#pragma unroll
        for (int k16 = 0; k16 < 2; k16++) {
            uint32_t bh[2][4];
#pragma unroll
            for (int np = 0; np < 2; np++) {
                uint32_t off = (uint32_t)(ASZ +
                    (k16 * 16 + bkRow) * BSTR + wn + np * 16 + bkCol) * 2;
                ldm_x4_t(bh[np], sbase + off);
            }
#pragma unroll
            for (int mt = 0; mt < MT; mt++) {
                uint32_t ah[4];
                uint32_t off = ((aRow + mt * 16) * PADK + (uint32_t)(k16 * 16) + aK) * 2;
                ldm_x4(ah, sbase + off);
#pragma unroll
                for (int nt = 0; nt < 4; nt++)
                    mma16816(acc[mt][nt], ah, &bh[nt >> 1][(nt & 1) * 2]);
            }
        }
    }

    int rbase = m0 + wm + (lane >> 2);
#pragma unroll
    for (int mt = 0; mt < MT; mt++) {
        int row = rbase + mt * 16;
#pragma unroll
        for (int nt = 0; nt < 4; nt++) {
            int col = n0 + wn + nt * 8 + (lane & 3) * 2;
            float b0 = bias[col], b1 = bias[col + 1];
            float v0 = acc[mt][nt][0] + b0;
            float v1 = acc[mt][nt][1] + b1;
            float v2 = acc[mt][nt][2] + b0;
            float v3 = acc[mt][nt][3] + b1;
            if (mode == 0) {
                *(float2*)(Cf + (size_t)row * N + col)       = make_float2(v0, v1);
                *(float2*)(Cf + (size_t)(row + 8) * N + col) = make_float2(v2, v3);
            } else {
                if (mode == 1) {
                    v0 = gelu_tanh(v0); v1 = gelu_tanh(v1);
                    v2 = gelu_tanh(v2); v3 = gelu_tanh(v3);
                }
                __half2 p0 = __halves2half2(__float2half(v0), __float2half(v1));
                __half2 p1 = __halves2half2(__float2half(v2), __float2half(v3));
                *(__half2*)(Ch + (size_t)row * N + col)       = p0;
                *(__half2*)(Ch + (size_t)(row + 8) * N + col) = p1;
            }
        }
    }
}

// ================= embed + LN =================
__global__ void embed_ln_kernel(const int* __restrict__ x,
                                const float* __restrict__ we,
                                const float* __restrict__ pe,
                                const float* __restrict__ te,
                                const float* __restrict__ lw,
                                const float* __restrict__ lb) {
    int t = blockIdx.x, s = t % SS, tid = threadIdx.x;
    int wid = x[t];
    bool act = tid < 192;
    float4 v4 = make_float4(0.f, 0.f, 0.f, 0.f);
    if (act) {
        float4 a = *(const float4*)&we[(size_t)wid * HH + tid * 4];
        float4 b = *(const float4*)&pe[s * HH + tid * 4];
        float4 c = *(const float4*)&te[tid * 4];
        v4 = make_float4(a.x+b.x+c.x, a.y+b.y+c.y, a.z+b.z+c.z, a.w+b.w+c.w);
    }
    float sum = v4.x + v4.y + v4.z + v4.w;
    float sq  = v4.x*v4.x + v4.y*v4.y + v4.z*v4.z + v4.w*v4.w;
    __shared__ float red[256], red2[256];
    red[tid] = sum; red2[tid] = sq; __syncthreads();
    for (int off = 128; off > 0; off >>= 1) {
        if (tid < off) { red[tid] += red[tid+off]; red2[tid] += red2[tid+off]; }
        __syncthreads();
    }
    float m = red[0] * (1.f/HH), var = red2[0] * (1.f/HH) - m*m;
    float rstd = rsqrtf(var + 1e-12f);
    if (act) {
        float4 w4 = *(const float4*)&lw[tid*4];
        float4 b4 = *(const float4*)&lb[tid*4];
        float o0 = (v4.x-m)*rstd*w4.x + b4.x;
        float o1 = (v4.y-m)*rstd*w4.y + b4.y;
        float o2 = (v4.z-m)*rstd*w4.z + b4.z;
        float o3 = (v4.w-m)*rstd*w4.w + b4.w;
        size_t idx = (size_t)t * HH + tid * 4;
        *(float4*)&g_h[idx] = make_float4(o0,o1,o2,o3);
        __half2 p0 = __halves2half2(__float2half(o0), __float2half(o1));
        __half2 p1 = __halves2half2(__float2half(o2), __float2half(o3));
        *(uint2*)(g_h16 + idx) = make_uint2(*(uint32_t*)&p0, *(uint32_t*)&p1);
    }
}

// ================= residual + LN =================
__global__ void resid_ln_kernel(const float* __restrict__ add,
                                const float* __restrict__ lw,
                                const float* __restrict__ lb) {
    int t = blockIdx.x, tid = threadIdx.x;
    bool act = tid < 192;
    float4 v4 = make_float4(0.f, 0.f, 0.f, 0.f);
    size_t idx = (size_t)t * HH + tid * 4;
    if (act) {
        float4 a = *(const float4*)&g_h[idx];
        float4 b = *(const float4*)&add[idx];
        v4 = make_float4(a.x+b.x, a.y+b.y, a.z+b.z, a.w+b.w);
    }
    float sum = v4.x + v4.y + v4.z + v4.w;
    float sq  = v4.x*v4.x + v4.y*v4.y + v4.z*v4.z + v4.w*v4.w;
    __shared__ float red[256], red2[256];
    red[tid] = sum; red2[tid] = sq; __syncthreads();
    for (int off = 128; off > 0; off >>= 1) {
        if (tid < off) { red[tid] += red[tid+off]; red2[tid] += red2[tid+off]; }
        __syncthreads();
    }
    float m = red[0] * (1.f/HH), var = red2[0] * (1.f/HH) - m*m;
    float rstd = rsqrtf(var + 1e-12f);
    if (act) {
        float4 w4 = *(const float4*)&lw[tid*4];
        float4 b4 = *(const float4*)&lb[tid*4];
        float o0 = (v4.x-m)*rstd*w4.x + b4.x;
        float o1 = (v4.y-m)*rstd*w4.y + b4.y;
        float o2 = (v4.z-m)*rstd*w4.z + b4.z;
        float o3 = (v4.w-m)*rstd*w4.w + b4.w;
        *(float4*)&g_h[idx] = make_float4(o0,o1,o2,o3);
        __half2 p0 = __halves2half2(__float2half(o0), __float2half(o1));
        __half2 p1 = __halves2half2(__float2half(o2), __float2half(o3));
        *(uint2*)(g_h16 + idx) = make_uint2(*(uint32_t*)&p0, *(uint32_t*)&p1);
    }
}

// ================= attention v6: HMMA flash-style =================
#define AQ_STR 72
#define AK_STR 72
#define AV_STR 72

__global__ __launch_bounds__(256, 1)
void attn_kernel_v6() {
    extern __shared__ __half smh[];
    __half* Qs = smh;
    __half* Ks = Qs + 128 * AQ_STR;
    __half* Vs = Ks + 256 * AK_STR;
    uint32_t sQ = (uint32_t)__cvta_generic_to_shared(Qs);
    uint32_t sK = (uint32_t)__cvta_generic_to_shared(Ks);
    uint32_t sV = (uint32_t)__cvta_generic_to_shared(Vs);

    const __half* gq = g_qkv16;
    const __half* gk = g_qkv16 + (size_t)TOK * HH;
    const __half* gv = g_qkv16 + 2 * (size_t)TOK * HH;

    int h = blockIdx.x, b = blockIdx.y, qh = blockIdx.z;
    int tid = threadIdx.x, lane = tid & 31, w = tid >> 5;
    size_t base = (size_t)(b * SS) * HH + h * DHH;
    int qoff = qh * 128;

    for (int i = tid; i < 128 * 8; i += 256) {
        int r = i >> 3, ch = i & 7;
        *(uint4*)&Qs[r * AQ_STR + ch * 8] =
            *(const uint4*)&gq[base + (size_t)(qoff + r) * HH + ch * 8];
    }
    for (int i = tid; i < 256 * 8; i += 256) {
        int r = i >> 3, ch = i & 7;
        size_t g = base + (size_t)r * HH + ch * 8;
        *(uint4*)&Ks[r * AK_STR + ch * 8] = *(const uint4*)&gk[g];
        *(uint4*)&Vs[r * AV_STR + ch * 8] = *(const uint4*)&gv[g];
    }
    __syncthreads();

    int wq = w * 16;
    float c[16][2][4];
#pragma unroll
    for (int t = 0; t < 16; t++)
#pragma unroll
        for (int f = 0; f < 2; f++)
#pragma unroll
            for (int k = 0; k < 4; k++) c[t][f][k] = 0.f;

    uint32_t aRow = (uint32_t)(wq + (lane & 15));
    uint32_t aCol = (uint32_t)((lane >> 4) * 8);
    uint32_t bRow = (uint32_t)(((lane >> 4) & 1) * 8 + (lane & 7));
    uint32_t bCol = (uint32_t)(((lane >> 3) & 1) * 8);

#pragma unroll
    for (int k16 = 0; k16 < 4; k16++) {
        uint32_t aq[4];
        ldm_x4(aq, sQ + (aRow * AQ_STR + (uint32_t)(k16 * 16) + aCol) * 2);
#pragma unroll
        for (int t = 0; t < 16; t++) {
            uint32_t bk[4];
            ldm_x4(bk, sK + ((bRow + (uint32_t)(t * 16)) * AK_STR +
                             (uint32_t)(k16 * 16) + bCol) * 2);
            mma16816(c[t][0], aq, &bk[0]);
            mma16816(c[t][1], aq, &bk[2]);
        }
    }

    float m0 = -1e30f, m1 = -1e30f;
#pragma unroll
    for (int t = 0; t < 16; t++)
#pragma unroll
        for (int f = 0; f < 2; f++) {
            m0 = fmaxf(m0, fmaxf(c[t][f][0], c[t][f][1]));
            m1 = fmaxf(m1, fmaxf(c[t][f][2], c[t][f][3]));
        }
    m0 = fmaxf(m0, __shfl_xor_sync(0xffffffffu, m0, 1));
    m0 = fmaxf(m0, __shfl_xor_sync(0xffffffffu, m0, 2));
    m1 = fmaxf(m1, __shfl_xor_sync(0xffffffffu, m1, 1));
    m1 = fmaxf(m1, __shfl_xor_sync(0xffffffffu, m1, 2));

    float s0 = 0.f, s1 = 0.f;
#pragma unroll
    for (int t = 0; t < 16; t++)
#pragma unroll
        for (int f = 0; f < 2; f++) {
            c[t][f][0] = __expf(0.125f * (c[t][f][0] - m0));
            c[t][f][1] = __expf(0.125f * (c[t][f][1] - m0));
            c[t][f][2] = __expf(0.125f * (c[t][f][2] - m1));
            c[t][f][3] = __expf(0.125f * (c[t][f][3] - m1));
            s0 += c[t][f][0] + c[t][f][1];
            s1 += c[t][f][2] + c[t][f][3];
        }
    s0 += __shfl_xor_sync(0xffffffffu, s0, 1);
    s0 += __shfl_xor_sync(0xffffffffu, s0, 2);
    s1 += __shfl_xor_sync(0xffffffffu, s1, 1);
    s1 += __shfl_xor_sync(0xffffffffu, s1, 2);
    float iv0 = 1.f / s0, iv1 = 1.f / s1;

    float ctx[8][4];
#pragma unroll
    for (int nf = 0; nf < 8; nf++)
#pragma unroll
        for (int k = 0; k < 4; k++) ctx[nf][k] = 0.f;

    uint32_t vRow = (uint32_t)((lane & 7) + ((lane >> 3) & 1) * 8);
    uint32_t vCol = (uint32_t)((lane >> 4) * 8);

#pragma unroll
    for (int t = 0; t < 16; t++) {
        uint32_t pa[4];
        __half2 h0 = __halves2half2(__float2half(c[t][0][0] * iv0),
                                    __float2half(c[t][0][1] * iv0));
        __half2 h1 = __halves2half2(__float2half(c[t][0][2] * iv1),
                                    __float2half(c[t][0][3] * iv1));
        __half2 h2 = __halves2half2(__float2half(c[t][1][0] * iv0),
                                    __float2half(c[t][1][1] * iv0));
        __half2 h3 = __halves2half2(__float2half(c[t][1][2] * iv1),
                                    __float2half(c[t][1][3] * iv1));
        pa[0] = *(uint32_t*)&h0;
        pa[1] = *(uint32_t*)&h1;
        pa[2] = *(uint32_t*)&h2;
        pa[3] = *(uint32_t*)&h3;
#pragma unroll
        for (int dn = 0; dn < 4; dn++) {
            uint32_t bv[4];
            ldm_x4_t(bv, sV + ((vRow + (uint32_t)(t * 16)) * AV_STR +
                               (uint32_t)(dn * 16) + vCol) * 2);
            mma16816(ctx[dn * 2 + 0], pa, &bv[0]);
            mma16816(ctx[dn * 2 + 1], pa, &bv[2]);
        }
    }

    int q0 = qoff + wq + (lane >> 2);
#pragma unroll
    for (int nf = 0; nf < 8; nf++) {
        int d = nf * 8 + (lane & 3) * 2;
        size_t i0 = base + (size_t)q0 * HH + d;
        size_t i1 = base + (size_t)(q0 + 8) * HH + d;
        __half2 p0 = __halves2half2(__float2half(ctx[nf][0]), __float2half(ctx[nf][1]));
        __half2 p1 = __halves2half2(__float2half(ctx[nf][2]), __float2half(ctx[nf][3]));
        *(uint32_t*)(g_cx16 + i0) = *(uint32_t*)&p0;
        *(uint32_t*)(g_cx16 + i1) = *(uint32_t*)&p1;
    }
}

// ================= emissions =================
__global__ void emissions_kernel(const float* __restrict__ cw,
                                 const float* __restrict__ cb) {
    int t = blockIdx.x, tid = threadIdx.x;
    float part[CC];
#pragma unroll
    for (int c = 0; c < CC; c++) part[c] = 0.f;
    for (int k = tid; k < HH; k += 256) {
        float hv = g_h[(size_t)t * HH + k];
        const float* wr = cw + (size_t)k * CC;
#pragma unroll
        for (int c = 0; c < CC; c++) part[c] += hv * wr[c];
    }
#pragma unroll
    for (int c = 0; c < CC; c++)
        for (int off = 16; off > 0; off >>= 1)
            part[c] += __shfl_down_sync(0xffffffffu, part[c], off);

    __shared__ float wred[8][CC];
    int lane = tid & 31, w = tid >> 5;
    if (lane == 0)
#pragma unroll
        for (int c = 0; c < CC; c++) wred[w][c] = part[c];
    __syncthreads();
    if (tid < CC) {
        float s = cb[tid];
#pragma unroll
        for (int ww = 0; ww < 8; ww++) s += wred[ww][tid];
        g_em[(size_t)t * CC + tid] = s;
    }
}

// ================= CRF =================
__global__ void crf_kernel(const int* __restrict__ target,
                           const float* __restrict__ cstart,
                           const float* __restrict__ cend,
                           const float* __restrict__ ctrans,
                           float* __restrict__ out) {
    __shared__ float alpha[BB][CC];
    __shared__ float trans[CC][CC];
    __shared__ float den[BB], num[BB];
    int tid = threadIdx.x;

    if (tid < CC * CC) trans[tid / CC][tid % CC] = ctrans[tid];
    __syncthreads();

    int b = tid / CC, j = tid % CC;
    bool act = (tid < BB * CC);
    if (act) alpha[b][j] = cstart[j] + g_em[(size_t)(b * SS) * CC + j];
    __syncthreads();

    for (int s = 1; s < SS; s++) {
        float nv = 0.f;
        if (act) {
            float m = -1e30f;
#pragma unroll
            for (int i = 0; i < CC; i++) m = fmaxf(m, alpha[b][i] + trans[i][j]);
            float sum = 0.f;
#pragma unroll
            for (int i = 0; i < CC; i++) sum += __expf(alpha[b][i] + trans[i][j] - m);
            nv = m + __logf(sum) + g_em[(size_t)(b * SS + s) * CC + j];
            if (!(target[b * SS + s] > -1)) nv = alpha[b][j];
        }
        __syncthreads();
        if (act) alpha[b][j] = nv;
        __syncthreads();
    }

    if (act && j == 0) {
        float m = -1e30f;
#pragma unroll
        for (int jj = 0; jj < CC; jj++) m = fmaxf(m, alpha[b][jj] + cend[jj]);
        float sum = 0.f;
#pragma unroll
        for (int jj = 0; jj < CC; jj++) sum += __expf(alpha[b][jj] + cend[jj] - m);
        den[b] = m + __logf(sum);

        const int* tb = target + b * SS;
        int cnt = 0;
        for (int s = 0; s < SS; s++) cnt += (tb[s] > -1) ? 1 : 0;
        int send = cnt - 1;
        int t0 = tb[0] < 0 ? 0 : tb[0];
        float nu = cstart[t0] + g_em[(size_t)(b * SS) * CC + t0];
        for (int s = 1; s < SS; s++) {
            int ts = tb[s], tp = tb[s - 1];
            float mk = (ts > -1) ? 1.f : 0.f;
            int tsc = ts < 0 ? 0 : ts, tpc = tp < 0 ? 0 : tp;
            nu += mk * (trans[tpc][tsc] + g_em[(size_t)(b * SS + s) * CC + tsc]);
        }
        int last = tb[send < 0 ? 0 : send];
        nu += cend[last < 0 ? 0 : last];
        num[b] = nu;
    }
    __syncthreads();
    if (tid == 0) {
        float L = 0.f;
        for (int bb = 0; bb < BB; bb++) L += num[bb] - den[bb];
        out[0] = -L / BB;
    }
}

// ================= launch =================
extern "C" void kernel_launch(void* const* d_in, const int* in_sizes, int n_in,
                              void* d_out, int out_size) {
    const int*   x          = (const int*)  d_in[0];
    const int*   target     = (const int*)  d_in[1];
    const float* word_emb   = (const float*)d_in[2];
    const float* pos_emb    = (const float*)d_in[3];
    const float* type_emb   = (const float*)d_in[4];
    const float* emb_ln_w   = (const float*)d_in[5];
    const float* emb_ln_b   = (const float*)d_in[6];
    const float* qkv_w      = (const float*)d_in[7];
    const float* qkv_b      = (const float*)d_in[8];
    const float* attn_out_w = (const float*)d_in[9];
    const float* attn_out_b = (const float*)d_in[10];
    const float* attn_ln_w  = (const float*)d_in[11];
    const float* attn_ln_b  = (const float*)d_in[12];
    const float* ffn_w1     = (const float*)d_in[13];
    const float* ffn_b1     = (const float*)d_in[14];
    const float* ffn_w2     = (const float*)d_in[15];
    const float* ffn_b2     = (const float*)d_in[16];
    const float* ffn_ln_w   = (const float*)d_in[17];
    const float* ffn_ln_b   = (const float*)d_in[18];
    const float* cls_w      = (const float*)d_in[19];
    const float* cls_b      = (const float*)d_in[20];
    const float* crf_start  = (const float*)d_in[21];
    const float* crf_end    = (const float*)d_in[22];
    const float* crf_trans  = (const float*)d_in[23];
    float* out = (float*)d_out;

    float *pt1;
    __half *ph16, *pqkv16, *pcx16, *pf16;
    __half *pwq, *pwa, *pw1, *pw2;
    cudaGetSymbolAddress((void**)&pt1,    g_t1);
    cudaGetSymbolAddress((void**)&ph16,   g_h16);
    cudaGetSymbolAddress((void**)&pqkv16, g_qkv16);
    cudaGetSymbolAddress((void**)&pcx16,  g_cx16);
    cudaGetSymbolAddress((void**)&pf16,   g_f16);
    cudaGetSymbolAddress((void**)&pwq, w_qkv16);
    cudaGetSymbolAddress((void**)&pwa, w_ao16);
    cudaGetSymbolAddress((void**)&pw1, w_f116);
    cudaGetSymbolAddress((void**)&pw2, w_f216);

    const int SMEM_ATTN = (128*AQ_STR + 256*AK_STR + 256*AV_STR) * 2;    // 92160
    const int SMEM_G128 = 3 * (128*PADK + 32*(128+8)) * 2;               // 56832
    const int SMEM_G64  = 3 * (128*PADK + 32*(64+8)) * 2;                // 44544
    cudaFuncSetAttribute(attn_kernel_v6,
                         cudaFuncAttributeMaxDynamicSharedMemorySize, SMEM_ATTN);
    cudaFuncSetAttribute(k_mma<128>,
                         cudaFuncAttributeMaxDynamicSharedMemorySize, SMEM_G128);
    cudaFuncSetAttribute(k_mma<64>,
                         cudaFuncAttributeMaxDynamicSharedMemorySize, SMEM_G64);

    // streaming weight converts (native [K][N] layout preserved)
    {
        size_t nq = (size_t)NLL*3*HH*HH;
        size_t na = (size_t)NLL*HH*HH;
        size_t n1 = (size_t)NLL*HH*FFF;
        size_t n2 = (size_t)NLL*FFF*HH;
        k_wconv<<<(unsigned)((nq/8 + 255)/256), 256>>>(qkv_w,      pwq, nq);
        k_wconv<<<(unsigned)((na/8 + 255)/256), 256>>>(attn_out_w, pwa, na);
        k_wconv<<<(unsigned)((n1/8 + 255)/256), 256>>>(ffn_w1,     pw1, n1);
        k_wconv<<<(unsigned)((n2/8 + 255)/256), 256>>>(ffn_w2,     pw2, n2);
    }

    embed_ln_kernel<<<TOK, 256>>>(x, word_emb, pos_emb, type_emb, emb_ln_w, emb_ln_b);

    dim3 gQKV(HH / 128, TOK / 128, 3);
    dim3 gH64(HH / 64,  TOK / 128, 1);
    dim3 gF  (FFF / 128, TOK / 128, 1);
    dim3 gA  (NHH, BB, 2);

    for (int l = 0; l < NLL; l++) {
        k_mma<128><<<gQKV, 256, SMEM_G128>>>(ph16,
            pwq + (size_t)l*3*HH*HH,
            qkv_b + (size_t)l*3*HH,
            nullptr, pqkv16,
            HH, HH, 2, HH*HH, TOK*HH, HH);

        attn_kernel_v6<<<gA, 256, SMEM_ATTN>>>();

        k_mma<64><<<gH64, 256, SMEM_G64>>>(pcx16,
            pwa + (size_t)l*HH*HH,
            attn_out_b + (size_t)l*HH,
            pt1, nullptr,
            HH, HH, 0, 0, 0, 0);
        resid_ln_kernel<<<TOK, 256>>>(pt1, attn_ln_w + (size_t)l*HH, attn_ln_b + (size_t)l*HH);

        k_mma<128><<<gF, 256, SMEM_G128>>>(ph16,
            pw1 + (size_t)l*HH*FFF,
            ffn_b1 + (size_t)l*FFF,
            nullptr, pf16,
            FFF, HH, 1, 0, 0, 0);

        k_mma<64><<<gH64, 256, SMEM_G64>>>(pf16,
            pw2 + (size_t)l*FFF*HH,
            ffn_b2 + (size_t)l*HH,
            pt1, nullptr,
            HH, FFF, 0, 0, 0, 0);
        resid_ln_kernel<<<TOK, 256>>>(pt1, ffn_ln_w + (size_t)l*HH, ffn_ln_b + (size_t)l*HH);
    }

    emissions_kernel<<<TOK, 256>>>(cls_w, cls_b);
    crf_kernel<<<1, 128>>>(target, crf_start, crf_end, crf_trans, out);
}

// round 15
// speedup vs baseline: 2.7091x; 1.0255x over previous
#include <cuda_runtime.h>
#include <cuda_fp16.h>
#include <math.h>
#include <stdint.h>

#define BB   8
#define SS   256
#define HH   768
#define NLL  12
#define NHH  12
#define FFF  3072
#define CC   9
#define DHH  64
#define TOK  (BB*SS)   // 2048

// ================= scratch =================
__device__ float                  g_h    [TOK*HH];
__device__ __align__(256) __half  g_h16  [TOK*HH];
__device__ __align__(256) __half  g_qkv16[3*TOK*HH];
__device__ __align__(256) __half  g_cx16 [TOK*HH];
__device__ __align__(256) float   g_t1   [TOK*HH];
__device__ __align__(256) __half  g_f16  [TOK*FFF];
__device__ float                  g_em   [TOK*CC];

// fp16 weights in NATIVE [K][N] layout
__device__ __align__(256) __half w_qkv16[NLL*3*HH*HH];
__device__ __align__(256) __half w_ao16 [NLL*HH*HH];
__device__ __align__(256) __half w_f116 [NLL*HH*FFF];
__device__ __align__(256) __half w_f216 [NLL*FFF*HH];

// ================= low-level helpers =================
__device__ __forceinline__ void cpa16(uint32_t dst, const void* src) {
    asm volatile("cp.async.cg.shared.global [%0], [%1], 16;"
                 :: "r"(dst), "l"(src) : "memory");
}
#define CP_COMMIT() asm volatile("cp.async.commit_group;" ::: "memory")
#define CP_WAIT1()  asm volatile("cp.async.wait_group 1;" ::: "memory")
#define CP_WAIT0()  asm volatile("cp.async.wait_group 0;" ::: "memory")

__device__ __forceinline__ void ldm_x4(uint32_t* r, uint32_t a) {
    asm volatile("ldmatrix.sync.aligned.m8n8.x4.shared.b16 {%0,%1,%2,%3}, [%4];"
                 : "=r"(r[0]), "=r"(r[1]), "=r"(r[2]), "=r"(r[3]) : "r"(a));
}
__device__ __forceinline__ void ldm_x4_t(uint32_t* r, uint32_t a) {
    asm volatile("ldmatrix.sync.aligned.m8n8.x4.trans.shared.b16 {%0,%1,%2,%3}, [%4];"
                 : "=r"(r[0]), "=r"(r[1]), "=r"(r[2]), "=r"(r[3]) : "r"(a));
}
__device__ __forceinline__ void mma16816(float* c, const uint32_t* a, const uint32_t* b) {
    asm volatile("mma.sync.aligned.m16n8k16.row.col.f32.f16.f16.f32 "
        "{%0,%1,%2,%3}, {%4,%5,%6,%7}, {%8,%9}, {%0,%1,%2,%3};"
        : "+f"(c[0]), "+f"(c[1]), "+f"(c[2]), "+f"(c[3])
        : "r"(a[0]), "r"(a[1]), "r"(a[2]), "r"(a[3]), "r"(b[0]), "r"(b[1]));
}

__device__ __forceinline__ float gelu_tanh(float v) {
    float c = 0.7978845608028654f * (v + 0.044715f * v * v * v);
    return 0.5f * v * (1.f + tanhf(c));
}

// ================= streaming fp32 -> fp16 weight convert =================
__global__ void k_wconv(const float* __restrict__ W,
                        __half* __restrict__ out, size_t n) {
    size_t i = ((size_t)blockIdx.x * 256 + threadIdx.x) * 8;
    if (i < n) {
        float4 a = *(const float4*)(W + i);
        float4 b = *(const float4*)(W + i + 4);
        __half2 p0 = __halves2half2(__float2half(a.x), __float2half(a.y));
        __half2 p1 = __halves2half2(__float2half(a.z), __float2half(a.w));
        __half2 p2 = __halves2half2(__float2half(b.x), __float2half(b.y));
        __half2 p3 = __halves2half2(__float2half(b.z), __float2half(b.w));
        uint4 o;
        o.x = *(uint32_t*)&p0; o.y = *(uint32_t*)&p1;
        o.z = *(uint32_t*)&p2; o.w = *(uint32_t*)&p3;
        *(uint4*)(out + i) = o;
    }
}

// ================= HMMA GEMM: KCH=64, trans-B, 3-stage, 2 CTAs/SM =================
#define PADK 72   // 64 + 8

template<int BN>
__global__ __launch_bounds__(256, 2)
void k_mma(const __half* __restrict__ A,
           const __half* __restrict__ B16,
           const float* __restrict__ bias,
           float* __restrict__ Cf,
           __half* __restrict__ Ch,
           int N, int K, int mode,
           int zW, int zC, int zB)
{
    constexpr int WMW  = (BN == 128) ? 2 : 4;
    constexpr int WTM  = 128 / WMW;
    constexpr int MT   = WTM / 16;
    constexpr int ASZ  = 128 * PADK;       // halves
    constexpr int BSTR = BN + 8;
    constexpr int BSZ  = 64 * BSTR;
    constexpr int STG  = ASZ + BSZ;
    constexpr int CB   = BN / 8;           // 16B chunks per B row

    extern __shared__ __half smem_dyn[];
    uint32_t smb = (uint32_t)__cvta_generic_to_shared(smem_dyn);

    int tid = threadIdx.x, wid = tid >> 5, lane = tid & 31;
    int n0 = blockIdx.x * BN, m0 = blockIdx.y * 128, z = blockIdx.z;
    B16  += (size_t)z * zW;
    bias += (size_t)z * zB;
    if (mode == 0 && Cf) Cf += (size_t)z * zC;
    if (mode == 2 && Ch) Ch += (size_t)z * zC;

    int wm = (wid % WMW) * WTM;
    int wn = (wid / WMW) * 32;

    float acc[MT][4][4];
#pragma unroll
    for (int mt = 0; mt < MT; mt++)
#pragma unroll
        for (int nt = 0; nt < 4; nt++)
#pragma unroll
            for (int f = 0; f < 4; f++) acc[mt][nt][f] = 0.f;

    auto load_stage = [&](int s, int k0) {
        uint32_t base = smb + (uint32_t)(s * STG) * 2;
        // A: 128 rows x 8 chunks of 16B (64 halves)
#pragma unroll
        for (int i = 0; i < 4; i++) {
            int idx = tid + i * 256;
            int r = idx >> 3, ch = idx & 7;
            const char* g0 = (const char*)(A + (size_t)(m0 + r) * K + k0) + ch * 16;
            cpa16(base + (uint32_t)(r * PADK) * 2 + ch * 16, g0);
        }
        // B: 64 k-rows x BN cols
#pragma unroll
        for (int i = 0; i < (64 * CB) / 256; i++) {
            int idx = tid + i * 256;
            int r = idx / CB, ch = idx % CB;
            const char* g0 = (const char*)(B16 + (size_t)(k0 + r) * N + n0) + ch * 16;
            cpa16(base + (uint32_t)(ASZ + r * BSTR) * 2 + ch * 16, g0);
        }
    };

    int nc = K / 64;
    load_stage(0, 0);
    CP_COMMIT();
    load_stage(1, 64);
    CP_COMMIT();

    uint32_t aRow  = (uint32_t)(wm + (lane & 15));
    uint32_t aK    = (uint32_t)((lane >> 4) * 8);
    uint32_t bkRow = (uint32_t)((lane & 7) + ((lane >> 3) & 1) * 8);
    uint32_t bkCol = (uint32_t)((lane >> 4) * 8);

    for (int c = 0; c < nc; c++) {
        int b = c % 3;
        if (c == nc - 1) { CP_WAIT0(); } else { CP_WAIT1(); }
        __syncthreads();
        if (c + 2 < nc) {
            load_stage((c + 2) % 3, (c + 2) * 64);
            CP_COMMIT();
        }

        uint32_t sbase = smb + (uint32_t)(b * STG) * 2;
#pragma unroll
        for (int k16 = 0; k16 < 4; k16++) {
            uint32_t bh[2][4];
#pragma unroll
            for (int np = 0; np < 2; np++) {
                uint32_t off = (uint32_t)(ASZ +
                    (k16 * 16 + bkRow) * BSTR + wn + np * 16 + bkCol) * 2;
                ldm_x4_t(bh[np], sbase + off);
            }
#pragma unroll
            for (int mt = 0; mt < MT; mt++) {
                uint32_t ah[4];
                uint32_t off = ((aRow + mt * 16) * PADK + (uint32_t)(k16 * 16) + aK) * 2;
                ldm_x4(ah, sbase + off);
#pragma unroll
                for (int nt = 0; nt < 4; nt++)
                    mma16816(acc[mt][nt], ah, &bh[nt >> 1][(nt & 1) * 2]);
            }
        }
    }

    int rbase = m0 + wm + (lane >> 2);
#pragma unroll
    for (int mt = 0; mt < MT; mt++) {
        int row = rbase + mt * 16;
#pragma unroll
        for (int nt = 0; nt < 4; nt++) {
            int col = n0 + wn + nt * 8 + (lane & 3) * 2;
            float b0 = bias[col], b1 = bias[col + 1];
            float v0 = acc[mt][nt][0] + b0;
            float v1 = acc[mt][nt][1] + b1;
            float v2 = acc[mt][nt][2] + b0;
            float v3 = acc[mt][nt][3] + b1;
            if (mode == 0) {
                *(float2*)(Cf + (size_t)row * N + col)       = make_float2(v0, v1);
                *(float2*)(Cf + (size_t)(row + 8) * N + col) = make_float2(v2, v3);
            } else {
                if (mode == 1) {
                    v0 = gelu_tanh(v0); v1 = gelu_tanh(v1);
                    v2 = gelu_tanh(v2); v3 = gelu_tanh(v3);
                }
                __half2 p0 = __halves2half2(__float2half(v0), __float2half(v1));
                __half2 p1 = __halves2half2(__float2half(v2), __float2half(v3));
                *(__half2*)(Ch + (size_t)row * N + col)       = p0;
                *(__half2*)(Ch + (size_t)(row + 8) * N + col) = p1;
            }
        }
    }
}

// ================= embed + LN =================
__global__ void embed_ln_kernel(const int* __restrict__ x,
                                const float* __restrict__ we,
                                const float* __restrict__ pe,
                                const float* __restrict__ te,
                                const float* __restrict__ lw,
                                const float* __restrict__ lb) {
    int t = blockIdx.x, s = t % SS, tid = threadIdx.x;
    int wid = x[t];
    bool act = tid < 192;
    float4 v4 = make_float4(0.f, 0.f, 0.f, 0.f);
    if (act) {
        float4 a = *(const float4*)&we[(size_t)wid * HH + tid * 4];
        float4 b = *(const float4*)&pe[s * HH + tid * 4];
        float4 c = *(const float4*)&te[tid * 4];
        v4 = make_float4(a.x+b.x+c.x, a.y+b.y+c.y, a.z+b.z+c.z, a.w+b.w+c.w);
    }
    float sum = v4.x + v4.y + v4.z + v4.w;
    float sq  = v4.x*v4.x + v4.y*v4.y + v4.z*v4.z + v4.w*v4.w;
    __shared__ float red[256], red2[256];
    red[tid] = sum; red2[tid] = sq; __syncthreads();
    for (int off = 128; off > 0; off >>= 1) {
        if (tid < off) { red[tid] += red[tid+off]; red2[tid] += red2[tid+off]; }
        __syncthreads();
    }
    float m = red[0] * (1.f/HH), var = red2[0] * (1.f/HH) - m*m;
    float rstd = rsqrtf(var + 1e-12f);
    if (act) {
        float4 w4 = *(const float4*)&lw[tid*4];
        float4 b4 = *(const float4*)&lb[tid*4];
        float o0 = (v4.x-m)*rstd*w4.x + b4.x;
        float o1 = (v4.y-m)*rstd*w4.y + b4.y;
        float o2 = (v4.z-m)*rstd*w4.z + b4.z;
        float o3 = (v4.w-m)*rstd*w4.w + b4.w;
        size_t idx = (size_t)t * HH + tid * 4;
        *(float4*)&g_h[idx] = make_float4(o0,o1,o2,o3);
        __half2 p0 = __halves2half2(__float2half(o0), __float2half(o1));
        __half2 p1 = __halves2half2(__float2half(o2), __float2half(o3));
        *(uint2*)(g_h16 + idx) = make_uint2(*(uint32_t*)&p0, *(uint32_t*)&p1);
    }
}

// ================= residual + LN =================
__global__ void resid_ln_kernel(const float* __restrict__ add,
                                const float* __restrict__ lw,
                                const float* __restrict__ lb) {
    int t = blockIdx.x, tid = threadIdx.x;
    bool act = tid < 192;
    float4 v4 = make_float4(0.f, 0.f, 0.f, 0.f);
    size_t idx = (size_t)t * HH + tid * 4;
    if (act) {
        float4 a = *(const float4*)&g_h[idx];
        float4 b = *(const float4*)&add[idx];
        v4 = make_float4(a.x+b.x, a.y+b.y, a.z+b.z, a.w+b.w);
    }
    float sum = v4.x + v4.y + v4.z + v4.w;
    float sq  = v4.x*v4.x + v4.y*v4.y + v4.z*v4.z + v4.w*v4.w;
    __shared__ float red[256], red2[256];
    red[tid] = sum; red2[tid] = sq; __syncthreads();
    for (int off = 128; off > 0; off >>= 1) {
        if (tid < off) { red[tid] += red[tid+off]; red2[tid] += red2[tid+off]; }
        __syncthreads();
    }
    float m = red[0] * (1.f/HH), var = red2[0] * (1.f/HH) - m*m;
    float rstd = rsqrtf(var + 1e-12f);
    if (act) {
        float4 w4 = *(const float4*)&lw[tid*4];
        float4 b4 = *(const float4*)&lb[tid*4];
        float o0 = (v4.x-m)*rstd*w4.x + b4.x;
        float o1 = (v4.y-m)*rstd*w4.y + b4.y;
        float o2 = (v4.z-m)*rstd*w4.z + b4.z;
        float o3 = (v4.w-m)*rstd*w4.w + b4.w;
        *(float4*)&g_h[idx] = make_float4(o0,o1,o2,o3);
        __half2 p0 = __halves2half2(__float2half(o0), __float2half(o1));
        __half2 p1 = __halves2half2(__float2half(o2), __float2half(o3));
        *(uint2*)(g_h16 + idx) = make_uint2(*(uint32_t*)&p0, *(uint32_t*)&p1);
    }
}

// ================= attention v6: HMMA flash-style =================
#define AQ_STR 72
#define AK_STR 72
#define AV_STR 72

__global__ __launch_bounds__(256, 1)
void attn_kernel_v6() {
    extern __shared__ __half smh[];
    __half* Qs = smh;
    __half* Ks = Qs + 128 * AQ_STR;
    __half* Vs = Ks + 256 * AK_STR;
    uint32_t sQ = (uint32_t)__cvta_generic_to_shared(Qs);
    uint32_t sK = (uint32_t)__cvta_generic_to_shared(Ks);
    uint32_t sV = (uint32_t)__cvta_generic_to_shared(Vs);

    const __half* gq = g_qkv16;
    const __half* gk = g_qkv16 + (size_t)TOK * HH;
    const __half* gv = g_qkv16 + 2 * (size_t)TOK * HH;

    int h = blockIdx.x, b = blockIdx.y, qh = blockIdx.z;
    int tid = threadIdx.x, lane = tid & 31, w = tid >> 5;
    size_t base = (size_t)(b * SS) * HH + h * DHH;
    int qoff = qh * 128;

    for (int i = tid; i < 128 * 8; i += 256) {
        int r = i >> 3, ch = i & 7;
        *(uint4*)&Qs[r * AQ_STR + ch * 8] =
            *(const uint4*)&gq[base + (size_t)(qoff + r) * HH + ch * 8];
    }
    for (int i = tid; i < 256 * 8; i += 256) {
        int r = i >> 3, ch = i & 7;
        size_t g = base + (size_t)r * HH + ch * 8;
        *(uint4*)&Ks[r * AK_STR + ch * 8] = *(const uint4*)&gk[g];
        *(uint4*)&Vs[r * AV_STR + ch * 8] = *(const uint4*)&gv[g];
    }
    __syncthreads();

    int wq = w * 16;
    float c[16][2][4];
#pragma unroll
    for (int t = 0; t < 16; t++)
#pragma unroll
        for (int f = 0; f < 2; f++)
#pragma unroll
            for (int k = 0; k < 4; k++) c[t][f][k] = 0.f;

    uint32_t aRow = (uint32_t)(wq + (lane & 15));
    uint32_t aCol = (uint32_t)((lane >> 4) * 8);
    uint32_t bRow = (uint32_t)(((lane >> 4) & 1) * 8 + (lane & 7));
    uint32_t bCol = (uint32_t)(((lane >> 3) & 1) * 8);

#pragma unroll
    for (int k16 = 0; k16 < 4; k16++) {
        uint32_t aq[4];
        ldm_x4(aq, sQ + (aRow * AQ_STR + (uint32_t)(k16 * 16) + aCol) * 2);
#pragma unroll
        for (int t = 0; t < 16; t++) {
            uint32_t bk[4];
            ldm_x4(bk, sK + ((bRow + (uint32_t)(t * 16)) * AK_STR +
                             (uint32_t)(k16 * 16) + bCol) * 2);
            mma16816(c[t][0], aq, &bk[0]);
            mma16816(c[t][1], aq, &bk[2]);
        }
    }

    float m0 = -1e30f, m1 = -1e30f;
#pragma unroll
    for (int t = 0; t < 16; t++)
#pragma unroll
        for (int f = 0; f < 2; f++) {
            m0 = fmaxf(m0, fmaxf(c[t][f][0], c[t][f][1]));
            m1 = fmaxf(m1, fmaxf(c[t][f][2], c[t][f][3]));
        }
    m0 = fmaxf(m0, __shfl_xor_sync(0xffffffffu, m0, 1));
    m0 = fmaxf(m0, __shfl_xor_sync(0xffffffffu, m0, 2));
    m1 = fmaxf(m1, __shfl_xor_sync(0xffffffffu, m1, 1));
    m1 = fmaxf(m1, __shfl_xor_sync(0xffffffffu, m1, 2));

    float s0 = 0.f, s1 = 0.f;
#pragma unroll
    for (int t = 0; t < 16; t++)
#pragma unroll
        for (int f = 0; f < 2; f++) {
            c[t][f][0] = __expf(0.125f * (c[t][f][0] - m0));
            c[t][f][1] = __expf(0.125f * (c[t][f][1] - m0));
            c[t][f][2] = __expf(0.125f * (c[t][f][2] - m1));
            c[t][f][3] = __expf(0.125f * (c[t][f][3] - m1));
            s0 += c[t][f][0] + c[t][f][1];
            s1 += c[t][f][2] + c[t][f][3];
        }
    s0 += __shfl_xor_sync(0xffffffffu, s0, 1);
    s0 += __shfl_xor_sync(0xffffffffu, s0, 2);
    s1 += __shfl_xor_sync(0xffffffffu, s1, 1);
    s1 += __shfl_xor_sync(0xffffffffu, s1, 2);
    float iv0 = 1.f / s0, iv1 = 1.f / s1;

    float ctx[8][4];
#pragma unroll
    for (int nf = 0; nf < 8; nf++)
#pragma unroll
        for (int k = 0; k < 4; k++) ctx[nf][k] = 0.f;

    uint32_t vRow = (uint32_t)((lane & 7) + ((lane >> 3) & 1) * 8);
    uint32_t vCol = (uint32_t)((lane >> 4) * 8);

#pragma unroll
    for (int t = 0; t < 16; t++) {
        uint32_t pa[4];
        __half2 h0 = __halves2half2(__float2half(c[t][0][0] * iv0),
                                    __float2half(c[t][0][1] * iv0));
        __half2 h1 = __halves2half2(__float2half(c[t][0][2] * iv1),
                                    __float2half(c[t][0][3] * iv1));
        __half2 h2 = __halves2half2(__float2half(c[t][1][0] * iv0),
                                    __float2half(c[t][1][1] * iv0));
        __half2 h3 = __halves2half2(__float2half(c[t][1][2] * iv1),
                                    __float2half(c[t][1][3] * iv1));
        pa[0] = *(uint32_t*)&h0;
        pa[1] = *(uint32_t*)&h1;
        pa[2] = *(uint32_t*)&h2;
        pa[3] = *(uint32_t*)&h3;
#pragma unroll
        for (int dn = 0; dn < 4; dn++) {
            uint32_t bv[4];
            ldm_x4_t(bv, sV + ((vRow + (uint32_t)(t * 16)) * AV_STR +
                               (uint32_t)(dn * 16) + vCol) * 2);
            mma16816(ctx[dn * 2 + 0], pa, &bv[0]);
            mma16816(ctx[dn * 2 + 1], pa, &bv[2]);
        }
    }

    int q0 = qoff + wq + (lane >> 2);
#pragma unroll
    for (int nf = 0; nf < 8; nf++) {
        int d = nf * 8 + (lane & 3) * 2;
        size_t i0 = base + (size_t)q0 * HH + d;
        size_t i1 = base + (size_t)(q0 + 8) * HH + d;
        __half2 p0 = __halves2half2(__float2half(ctx[nf][0]), __float2half(ctx[nf][1]));
        __half2 p1 = __halves2half2(__float2half(ctx[nf][2]), __float2half(ctx[nf][3]));
        *(uint32_t*)(g_cx16 + i0) = *(uint32_t*)&p0;
        *(uint32_t*)(g_cx16 + i1) = *(uint32_t*)&p1;
    }
}

// ================= emissions =================
__global__ void emissions_kernel(const float* __restrict__ cw,
                                 const float* __restrict__ cb) {
    int t = blockIdx.x, tid = threadIdx.x;
    float part[CC];
#pragma unroll
    for (int c = 0; c < CC; c++) part[c] = 0.f;
    for (int k = tid; k < HH; k += 256) {
        float hv = g_h[(size_t)t * HH + k];
        const float* wr = cw + (size_t)k * CC;
#pragma unroll
        for (int c = 0; c < CC; c++) part[c] += hv * wr[c];
    }
#pragma unroll
    for (int c = 0; c < CC; c++)
        for (int off = 16; off > 0; off >>= 1)
            part[c] += __shfl_down_sync(0xffffffffu, part[c], off);

    __shared__ float wred[8][CC];
    int lane = tid & 31, w = tid >> 5;
    if (lane == 0)
#pragma unroll
        for (int c = 0; c < CC; c++) wred[w][c] = part[c];
    __syncthreads();
    if (tid < CC) {
        float s = cb[tid];
#pragma unroll
        for (int ww = 0; ww < 8; ww++) s += wred[ww][tid];
        g_em[(size_t)t * CC + tid] = s;
    }
}

// ================= CRF =================
__global__ void crf_kernel(const int* __restrict__ target,
                           const float* __restrict__ cstart,
                           const float* __restrict__ cend,
                           const float* __restrict__ ctrans,
                           float* __restrict__ out) {
    __shared__ float alpha[BB][CC];
    __shared__ float trans[CC][CC];
    __shared__ float den[BB], num[BB];
    int tid = threadIdx.x;

    if (tid < CC * CC) trans[tid / CC][tid % CC] = ctrans[tid];
    __syncthreads();

    int b = tid / CC, j = tid % CC;
    bool act = (tid < BB * CC);
    if (act) alpha[b][j] = cstart[j] + g_em[(size_t)(b * SS) * CC + j];
    __syncthreads();

    for (int s = 1; s < SS; s++) {
        float nv = 0.f;
        if (act) {
            float m = -1e30f;
#pragma unroll
            for (int i = 0; i < CC; i++) m = fmaxf(m, alpha[b][i] + trans[i][j]);
            float sum = 0.f;
#pragma unroll
            for (int i = 0; i < CC; i++) sum += __expf(alpha[b][i] + trans[i][j] - m);
            nv = m + __logf(sum) + g_em[(size_t)(b * SS + s) * CC + j];
            if (!(target[b * SS + s] > -1)) nv = alpha[b][j];
        }
        __syncthreads();
        if (act) alpha[b][j] = nv;
        __syncthreads();
    }

    if (act && j == 0) {
        float m = -1e30f;
#pragma unroll
        for (int jj = 0; jj < CC; jj++) m = fmaxf(m, alpha[b][jj] + cend[jj]);
        float sum = 0.f;
#pragma unroll
        for (int jj = 0; jj < CC; jj++) sum += __expf(alpha[b][jj] + cend[jj] - m);
        den[b] = m + __logf(sum);

        const int* tb = target + b * SS;
        int cnt = 0;
        for (int s = 0; s < SS; s++) cnt += (tb[s] > -1) ? 1 : 0;
        int send = cnt - 1;
        int t0 = tb[0] < 0 ? 0 : tb[0];
        float nu = cstart[t0] + g_em[(size_t)(b * SS) * CC + t0];
        for (int s = 1; s < SS; s++) {
            int ts = tb[s], tp = tb[s - 1];
            float mk = (ts > -1) ? 1.f : 0.f;
            int tsc = ts < 0 ? 0 : ts, tpc = tp < 0 ? 0 : tp;
            nu += mk * (trans[tpc][tsc] + g_em[(size_t)(b * SS + s) * CC + tsc]);
        }
        int last = tb[send < 0 ? 0 : send];
        nu += cend[last < 0 ? 0 : last];
        num[b] = nu;
    }
    __syncthreads();
    if (tid == 0) {
        float L = 0.f;
        for (int bb = 0; bb < BB; bb++) L += num[bb] - den[bb];
        out[0] = -L / BB;
    }
}

// ================= launch =================
extern "C" void kernel_launch(void* const* d_in, const int* in_sizes, int n_in,
                              void* d_out, int out_size) {
    const int*   x          = (const int*)  d_in[0];
    const int*   target     = (const int*)  d_in[1];
    const float* word_emb   = (const float*)d_in[2];
    const float* pos_emb    = (const float*)d_in[3];
    const float* type_emb   = (const float*)d_in[4];
    const float* emb_ln_w   = (const float*)d_in[5];
    const float* emb_ln_b   = (const float*)d_in[6];
    const float* qkv_w      = (const float*)d_in[7];
    const float* qkv_b      = (const float*)d_in[8];
    const float* attn_out_w = (const float*)d_in[9];
    const float* attn_out_b = (const float*)d_in[10];
    const float* attn_ln_w  = (const float*)d_in[11];
    const float* attn_ln_b  = (const float*)d_in[12];
    const float* ffn_w1     = (const float*)d_in[13];
    const float* ffn_b1     = (const float*)d_in[14];
    const float* ffn_w2     = (const float*)d_in[15];
    const float* ffn_b2     = (const float*)d_in[16];
    const float* ffn_ln_w   = (const float*)d_in[17];
    const float* ffn_ln_b   = (const float*)d_in[18];
    const float* cls_w      = (const float*)d_in[19];
    const float* cls_b      = (const float*)d_in[20];
    const float* crf_start  = (const float*)d_in[21];
    const float* crf_end    = (const float*)d_in[22];
    const float* crf_trans  = (const float*)d_in[23];
    float* out = (float*)d_out;

    float *pt1;
    __half *ph16, *pqkv16, *pcx16, *pf16;
    __half *pwq, *pwa, *pw1, *pw2;
    cudaGetSymbolAddress((void**)&pt1,    g_t1);
    cudaGetSymbolAddress((void**)&ph16,   g_h16);
    cudaGetSymbolAddress((void**)&pqkv16, g_qkv16);
    cudaGetSymbolAddress((void**)&pcx16,  g_cx16);
    cudaGetSymbolAddress((void**)&pf16,   g_f16);
    cudaGetSymbolAddress((void**)&pwq, w_qkv16);
    cudaGetSymbolAddress((void**)&pwa, w_ao16);
    cudaGetSymbolAddress((void**)&pw1, w_f116);
    cudaGetSymbolAddress((void**)&pw2, w_f216);

    const int SMEM_ATTN = (128*AQ_STR + 256*AK_STR + 256*AV_STR) * 2;    // 92160
    const int SMEM_G128 = 3 * (128*PADK + 64*(128+8)) * 2;               // 107520
    const int SMEM_G64  = 3 * (128*PADK + 64*(64+8)) * 2;                // 82944
    cudaFuncSetAttribute(attn_kernel_v6,
                         cudaFuncAttributeMaxDynamicSharedMemorySize, SMEM_ATTN);
    cudaFuncSetAttribute(k_mma<128>,
                         cudaFuncAttributeMaxDynamicSharedMemorySize, SMEM_G128);
    cudaFuncSetAttribute(k_mma<64>,
                         cudaFuncAttributeMaxDynamicSharedMemorySize, SMEM_G64);

    {
        size_t nq = (size_t)NLL*3*HH*HH;
        size_t na = (size_t)NLL*HH*HH;
        size_t n1 = (size_t)NLL*HH*FFF;
        size_t n2 = (size_t)NLL*FFF*HH;
        k_wconv<<<(unsigned)((nq/8 + 255)/256), 256>>>(qkv_w,      pwq, nq);
        k_wconv<<<(unsigned)((na/8 + 255)/256), 256>>>(attn_out_w, pwa, na);
        k_wconv<<<(unsigned)((n1/8 + 255)/256), 256>>>(ffn_w1,     pw1, n1);
        k_wconv<<<(unsigned)((n2/8 + 255)/256), 256>>>(ffn_w2,     pw2, n2);
    }

    embed_ln_kernel<<<TOK, 256>>>(x, word_emb, pos_emb, type_emb, emb_ln_w, emb_ln_b);

    dim3 gQKV(HH / 128, TOK / 128, 3);
    dim3 gH64(HH / 64,  TOK / 128, 1);
    dim3 gF  (FFF / 128, TOK / 128, 1);
    dim3 gA  (NHH, BB, 2);

    for (int l = 0; l < NLL; l++) {
        k_mma<128><<<gQKV, 256, SMEM_G128>>>(ph16,
            pwq + (size_t)l*3*HH*HH,
            qkv_b + (size_t)l*3*HH,
            nullptr, pqkv16,
            HH, HH, 2, HH*HH, TOK*HH, HH);

        attn_kernel_v6<<<gA, 256, SMEM_ATTN>>>();

        k_mma<64><<<gH64, 256, SMEM_G64>>>(pcx16,
            pwa + (size_t)l*HH*HH,
            attn_out_b + (size_t)l*HH,
            pt1, nullptr,
            HH, HH, 0, 0, 0, 0);
        resid_ln_kernel<<<TOK, 256>>>(pt1, attn_ln_w + (size_t)l*HH, attn_ln_b + (size_t)l*HH);

        k_mma<128><<<gF, 256, SMEM_G128>>>(ph16,
            pw1 + (size_t)l*HH*FFF,
            ffn_b1 + (size_t)l*FFF,
            nullptr, pf16,
            FFF, HH, 1, 0, 0, 0);

        k_mma<64><<<gH64, 256, SMEM_G64>>>(pf16,
            pw2 + (size_t)l*FFF*HH,
            ffn_b2 + (size_t)l*HH,
            pt1, nullptr,
            HH, FFF, 0, 0, 0, 0);
        resid_ln_kernel<<<TOK, 256>>>(pt1, ffn_ln_w + (size_t)l*HH, ffn_ln_b + (size_t)l*HH);
    }

    emissions_kernel<<<TOK, 256>>>(cls_w, cls_b);
    crf_kernel<<<1, 128>>>(target, crf_start, crf_end, crf_trans, out);
}

// round 16
// speedup vs baseline: 2.7676x; 1.0216x over previous
#include <cuda_runtime.h>
#include <cuda_fp16.h>
#include <math.h>
#include <stdint.h>

#define BB   8
#define SS   256
#define HH   768
#define NLL  12
#define NHH  12
#define FFF  3072
#define CC   9
#define DHH  64
#define TOK  (BB*SS)   // 2048

// ================= scratch =================
__device__ float                  g_h    [TOK*HH];
__device__ __align__(256) __half  g_h16  [TOK*HH];
__device__ __align__(256) __half  g_qkv16[3*TOK*HH];
__device__ __align__(256) __half  g_cx16 [TOK*HH];
__device__ __align__(256) float   g_t1   [TOK*HH];
__device__ __align__(256) __half  g_f16  [TOK*FFF];
__device__ float                  g_em   [TOK*CC];

// fp16 weights in NATIVE [K][N] layout
__device__ __align__(256) __half w_qkv16[NLL*3*HH*HH];
__device__ __align__(256) __half w_ao16 [NLL*HH*HH];
__device__ __align__(256) __half w_f116 [NLL*HH*FFF];
__device__ __align__(256) __half w_f216 [NLL*FFF*HH];

// ================= low-level helpers =================
__device__ __forceinline__ void cpa16(uint32_t dst, const void* src) {
    asm volatile("cp.async.cg.shared.global [%0], [%1], 16;"
                 :: "r"(dst), "l"(src) : "memory");
}
#define CP_COMMIT() asm volatile("cp.async.commit_group;" ::: "memory")
#define CP_WAIT1()  asm volatile("cp.async.wait_group 1;" ::: "memory")
#define CP_WAIT0()  asm volatile("cp.async.wait_group 0;" ::: "memory")

__device__ __forceinline__ void ldm_x4(uint32_t* r, uint32_t a) {
    asm volatile("ldmatrix.sync.aligned.m8n8.x4.shared.b16 {%0,%1,%2,%3}, [%4];"
                 : "=r"(r[0]), "=r"(r[1]), "=r"(r[2]), "=r"(r[3]) : "r"(a));
}
__device__ __forceinline__ void ldm_x4_t(uint32_t* r, uint32_t a) {
    asm volatile("ldmatrix.sync.aligned.m8n8.x4.trans.shared.b16 {%0,%1,%2,%3}, [%4];"
                 : "=r"(r[0]), "=r"(r[1]), "=r"(r[2]), "=r"(r[3]) : "r"(a));
}
__device__ __forceinline__ void mma16816(float* c, const uint32_t* a, const uint32_t* b) {
    asm volatile("mma.sync.aligned.m16n8k16.row.col.f32.f16.f16.f32 "
        "{%0,%1,%2,%3}, {%4,%5,%6,%7}, {%8,%9}, {%0,%1,%2,%3};"
        : "+f"(c[0]), "+f"(c[1]), "+f"(c[2]), "+f"(c[3])
        : "r"(a[0]), "r"(a[1]), "r"(a[2]), "r"(a[3]), "r"(b[0]), "r"(b[1]));
}

__device__ __forceinline__ float gelu_tanh(float v) {
    float c = 0.7978845608028654f * (v + 0.044715f * v * v * v);
    return 0.5f * v * (1.f + tanhf(c));
}

// ================= streaming fp32 -> fp16 weight convert =================
__global__ void k_wconv(const float* __restrict__ W,
                        __half* __restrict__ out, size_t n) {
    size_t i = ((size_t)blockIdx.x * 256 + threadIdx.x) * 8;
    if (i < n) {
        float4 a = *(const float4*)(W + i);
        float4 b = *(const float4*)(W + i + 4);
        __half2 p0 = __halves2half2(__float2half(a.x), __float2half(a.y));
        __half2 p1 = __halves2half2(__float2half(a.z), __float2half(a.w));
        __half2 p2 = __halves2half2(__float2half(b.x), __float2half(b.y));
        __half2 p3 = __halves2half2(__float2half(b.z), __float2half(b.w));
        uint4 o;
        o.x = *(uint32_t*)&p0; o.y = *(uint32_t*)&p1;
        o.z = *(uint32_t*)&p2; o.w = *(uint32_t*)&p3;
        *(uint4*)(out + i) = o;
    }
}

// ================= HMMA GEMM: KCH=64, trans-B, 3-stage, 2 CTAs/SM =================
#define PADK 72   // 64 + 8

template<int BN>
__global__ __launch_bounds__(256, 2)
void k_mma(const __half* __restrict__ A,
           const __half* __restrict__ B16,
           const float* __restrict__ bias,
           float* __restrict__ Cf,
           __half* __restrict__ Ch,
           int N, int K, int mode,
           int zW, int zC, int zB)
{
    constexpr int WMW  = (BN == 128) ? 2 : 4;
    constexpr int WTM  = 128 / WMW;
    constexpr int MT   = WTM / 16;
    constexpr int ASZ  = 128 * PADK;
    constexpr int BSTR = BN + 8;
    constexpr int BSZ  = 64 * BSTR;
    constexpr int STG  = ASZ + BSZ;
    constexpr int CB   = BN / 8;

    extern __shared__ __half smem_dyn[];
    uint32_t smb = (uint32_t)__cvta_generic_to_shared(smem_dyn);

    int tid = threadIdx.x, wid = tid >> 5, lane = tid & 31;
    int n0 = blockIdx.x * BN, m0 = blockIdx.y * 128, z = blockIdx.z;
    B16  += (size_t)z * zW;
    bias += (size_t)z * zB;
    if (mode == 0 && Cf) Cf += (size_t)z * zC;
    if (mode == 2 && Ch) Ch += (size_t)z * zC;

    int wm = (wid % WMW) * WTM;
    int wn = (wid / WMW) * 32;

    float acc[MT][4][4];
#pragma unroll
    for (int mt = 0; mt < MT; mt++)
#pragma unroll
        for (int nt = 0; nt < 4; nt++)
#pragma unroll
            for (int f = 0; f < 4; f++) acc[mt][nt][f] = 0.f;

    auto load_stage = [&](int s, int k0) {
        uint32_t base = smb + (uint32_t)(s * STG) * 2;
#pragma unroll
        for (int i = 0; i < 4; i++) {
            int idx = tid + i * 256;
            int r = idx >> 3, ch = idx & 7;
            const char* g0 = (const char*)(A + (size_t)(m0 + r) * K + k0) + ch * 16;
            cpa16(base + (uint32_t)(r * PADK) * 2 + ch * 16, g0);
        }
#pragma unroll
        for (int i = 0; i < (64 * CB) / 256; i++) {
            int idx = tid + i * 256;
            int r = idx / CB, ch = idx % CB;
            const char* g0 = (const char*)(B16 + (size_t)(k0 + r) * N + n0) + ch * 16;
            cpa16(base + (uint32_t)(ASZ + r * BSTR) * 2 + ch * 16, g0);
        }
    };

    int nc = K / 64;
    load_stage(0, 0);
    CP_COMMIT();
    load_stage(1, 64);
    CP_COMMIT();

    uint32_t aRow  = (uint32_t)(wm + (lane & 15));
    uint32_t aK    = (uint32_t)((lane >> 4) * 8);
    uint32_t bkRow = (uint32_t)((lane & 7) + ((lane >> 3) & 1) * 8);
    uint32_t bkCol = (uint32_t)((lane >> 4) * 8);

    for (int c = 0; c < nc; c++) {
        int b = c % 3;
        if (c == nc - 1) { CP_WAIT0(); } else { CP_WAIT1(); }
        __syncthreads();
        if (c + 2 < nc) {
            load_stage((c + 2) % 3, (c + 2) * 64);
            CP_COMMIT();
        }

        uint32_t sbase = smb + (uint32_t)(b * STG) * 2;
#pragma unroll
        for (int k16 = 0; k16 < 4; k16++) {
            uint32_t bh[2][4];
#pragma unroll
            for (int np = 0; np < 2; np++) {
                uint32_t off = (uint32_t)(ASZ +
                    (k16 * 16 + bkRow) * BSTR + wn + np * 16 + bkCol) * 2;
                ldm_x4_t(bh[np], sbase + off);
            }
#pragma unroll
            for (int mt = 0; mt < MT; mt++) {
                uint32_t ah[4];
                uint32_t off = ((aRow + mt * 16) * PADK + (uint32_t)(k16 * 16) + aK) * 2;
                ldm_x4(ah, sbase + off);
#pragma unroll
                for (int nt = 0; nt < 4; nt++)
                    mma16816(acc[mt][nt], ah, &bh[nt >> 1][(nt & 1) * 2]);
            }
        }
    }

    int rbase = m0 + wm + (lane >> 2);
#pragma unroll
    for (int mt = 0; mt < MT; mt++) {
        int row = rbase + mt * 16;
#pragma unroll
        for (int nt = 0; nt < 4; nt++) {
            int col = n0 + wn + nt * 8 + (lane & 3) * 2;
            float b0 = bias[col], b1 = bias[col + 1];
            float v0 = acc[mt][nt][0] + b0;
            float v1 = acc[mt][nt][1] + b1;
            float v2 = acc[mt][nt][2] + b0;
            float v3 = acc[mt][nt][3] + b1;
            if (mode == 0) {
                *(float2*)(Cf + (size_t)row * N + col)       = make_float2(v0, v1);
                *(float2*)(Cf + (size_t)(row + 8) * N + col) = make_float2(v2, v3);
            } else {
                if (mode == 1) {
                    v0 = gelu_tanh(v0); v1 = gelu_tanh(v1);
                    v2 = gelu_tanh(v2); v3 = gelu_tanh(v3);
                }
                __half2 p0 = __halves2half2(__float2half(v0), __float2half(v1));
                __half2 p1 = __halves2half2(__float2half(v2), __float2half(v3));
                *(__half2*)(Ch + (size_t)row * N + col)       = p0;
                *(__half2*)(Ch + (size_t)(row + 8) * N + col) = p1;
            }
        }
    }
}

// ================= embed + LN (warp per token, 8 tokens/CTA) =================
__global__ void embed_ln_kernel(const int* __restrict__ x,
                                const float* __restrict__ we,
                                const float* __restrict__ pe,
                                const float* __restrict__ te,
                                const float* __restrict__ lw,
                                const float* __restrict__ lb) {
    int t = blockIdx.x * 8 + (threadIdx.x >> 5);
    int lane = threadIdx.x & 31;
    int s = t % SS;
    int wid = x[t];
    size_t rb = (size_t)t * HH;

    float4 v[6];
    float sum = 0.f, sq = 0.f;
#pragma unroll
    for (int i = 0; i < 6; i++) {
        int c = (i * 32 + lane) * 4;
        float4 a = *(const float4*)&we[(size_t)wid * HH + c];
        float4 b = *(const float4*)&pe[s * HH + c];
        float4 e = *(const float4*)&te[c];
        v[i] = make_float4(a.x+b.x+e.x, a.y+b.y+e.y, a.z+b.z+e.z, a.w+b.w+e.w);
        sum += v[i].x + v[i].y + v[i].z + v[i].w;
        sq  += v[i].x*v[i].x + v[i].y*v[i].y + v[i].z*v[i].z + v[i].w*v[i].w;
    }
#pragma unroll
    for (int off = 16; off > 0; off >>= 1) {
        sum += __shfl_xor_sync(0xffffffffu, sum, off);
        sq  += __shfl_xor_sync(0xffffffffu, sq,  off);
    }
    float m = sum * (1.f/HH), var = sq * (1.f/HH) - m*m;
    float rstd = rsqrtf(var + 1e-12f);
#pragma unroll
    for (int i = 0; i < 6; i++) {
        int c = (i * 32 + lane) * 4;
        float4 w4 = *(const float4*)&lw[c];
        float4 b4 = *(const float4*)&lb[c];
        float o0 = (v[i].x-m)*rstd*w4.x + b4.x;
        float o1 = (v[i].y-m)*rstd*w4.y + b4.y;
        float o2 = (v[i].z-m)*rstd*w4.z + b4.z;
        float o3 = (v[i].w-m)*rstd*w4.w + b4.w;
        *(float4*)&g_h[rb + c] = make_float4(o0, o1, o2, o3);
        __half2 p0 = __halves2half2(__float2half(o0), __float2half(o1));
        __half2 p1 = __halves2half2(__float2half(o2), __float2half(o3));
        *(uint2*)(g_h16 + rb + c) = make_uint2(*(uint32_t*)&p0, *(uint32_t*)&p1);
    }
}

// ================= residual + LN (warp per token, 8 tokens/CTA) =================
__global__ void resid_ln_kernel(const float* __restrict__ add,
                                const float* __restrict__ lw,
                                const float* __restrict__ lb) {
    int t = blockIdx.x * 8 + (threadIdx.x >> 5);
    int lane = threadIdx.x & 31;
    size_t rb = (size_t)t * HH;

    float4 v[6];
    float sum = 0.f, sq = 0.f;
#pragma unroll
    for (int i = 0; i < 6; i++) {
        int c = (i * 32 + lane) * 4;
        float4 a = *(const float4*)&g_h[rb + c];
        float4 b = *(const float4*)&add[rb + c];
        v[i] = make_float4(a.x+b.x, a.y+b.y, a.z+b.z, a.w+b.w);
        sum += v[i].x + v[i].y + v[i].z + v[i].w;
        sq  += v[i].x*v[i].x + v[i].y*v[i].y + v[i].z*v[i].z + v[i].w*v[i].w;
    }
#pragma unroll
    for (int off = 16; off > 0; off >>= 1) {
        sum += __shfl_xor_sync(0xffffffffu, sum, off);
        sq  += __shfl_xor_sync(0xffffffffu, sq,  off);
    }
    float m = sum * (1.f/HH), var = sq * (1.f/HH) - m*m;
    float rstd = rsqrtf(var + 1e-12f);
#pragma unroll
    for (int i = 0; i < 6; i++) {
        int c = (i * 32 + lane) * 4;
        float4 w4 = *(const float4*)&lw[c];
        float4 b4 = *(const float4*)&lb[c];
        float o0 = (v[i].x-m)*rstd*w4.x + b4.x;
        float o1 = (v[i].y-m)*rstd*w4.y + b4.y;
        float o2 = (v[i].z-m)*rstd*w4.z + b4.z;
        float o3 = (v[i].w-m)*rstd*w4.w + b4.w;
        *(float4*)&g_h[rb + c] = make_float4(o0, o1, o2, o3);
        __half2 p0 = __halves2half2(__float2half(o0), __float2half(o1));
        __half2 p1 = __halves2half2(__float2half(o2), __float2half(o3));
        *(uint2*)(g_h16 + rb + c) = make_uint2(*(uint32_t*)&p0, *(uint32_t*)&p1);
    }
}

// ================= attention v6: HMMA flash-style =================
#define AQ_STR 72
#define AK_STR 72
#define AV_STR 72

__global__ __launch_bounds__(256, 1)
void attn_kernel_v6() {
    extern __shared__ __half smh[];
    __half* Qs = smh;
    __half* Ks = Qs + 128 * AQ_STR;
    __half* Vs = Ks + 256 * AK_STR;
    uint32_t sQ = (uint32_t)__cvta_generic_to_shared(Qs);
    uint32_t sK = (uint32_t)__cvta_generic_to_shared(Ks);
    uint32_t sV = (uint32_t)__cvta_generic_to_shared(Vs);

    const __half* gq = g_qkv16;
    const __half* gk = g_qkv16 + (size_t)TOK * HH;
    const __half* gv = g_qkv16 + 2 * (size_t)TOK * HH;

    int h = blockIdx.x, b = blockIdx.y, qh = blockIdx.z;
    int tid = threadIdx.x, lane = tid & 31, w = tid >> 5;
    size_t base = (size_t)(b * SS) * HH + h * DHH;
    int qoff = qh * 128;

    for (int i = tid; i < 128 * 8; i += 256) {
        int r = i >> 3, ch = i & 7;
        *(uint4*)&Qs[r * AQ_STR + ch * 8] =
            *(const uint4*)&gq[base + (size_t)(qoff + r) * HH + ch * 8];
    }
    for (int i = tid; i < 256 * 8; i += 256) {
        int r = i >> 3, ch = i & 7;
        size_t g = base + (size_t)r * HH + ch * 8;
        *(uint4*)&Ks[r * AK_STR + ch * 8] = *(const uint4*)&gk[g];
        *(uint4*)&Vs[r * AV_STR + ch * 8] = *(const uint4*)&gv[g];
    }
    __syncthreads();

    int wq = w * 16;
    float c[16][2][4];
#pragma unroll
    for (int t = 0; t < 16; t++)
#pragma unroll
        for (int f = 0; f < 2; f++)
#pragma unroll
            for (int k = 0; k < 4; k++) c[t][f][k] = 0.f;

    uint32_t aRow = (uint32_t)(wq + (lane & 15));
    uint32_t aCol = (uint32_t)((lane >> 4) * 8);
    uint32_t bRow = (uint32_t)(((lane >> 4) & 1) * 8 + (lane & 7));
    uint32_t bCol = (uint32_t)(((lane >> 3) & 1) * 8);

#pragma unroll
    for (int k16 = 0; k16 < 4; k16++) {
        uint32_t aq[4];
        ldm_x4(aq, sQ + (aRow * AQ_STR + (uint32_t)(k16 * 16) + aCol) * 2);
#pragma unroll
        for (int t = 0; t < 16; t++) {
            uint32_t bk[4];
            ldm_x4(bk, sK + ((bRow + (uint32_t)(t * 16)) * AK_STR +
                             (uint32_t)(k16 * 16) + bCol) * 2);
            mma16816(c[t][0], aq, &bk[0]);
            mma16816(c[t][1], aq, &bk[2]);
        }
    }

    float m0 = -1e30f, m1 = -1e30f;
#pragma unroll
    for (int t = 0; t < 16; t++)
#pragma unroll
        for (int f = 0; f < 2; f++) {
            m0 = fmaxf(m0, fmaxf(c[t][f][0], c[t][f][1]));
            m1 = fmaxf(m1, fmaxf(c[t][f][2], c[t][f][3]));
        }
    m0 = fmaxf(m0, __shfl_xor_sync(0xffffffffu, m0, 1));
    m0 = fmaxf(m0, __shfl_xor_sync(0xffffffffu, m0, 2));
    m1 = fmaxf(m1, __shfl_xor_sync(0xffffffffu, m1, 1));
    m1 = fmaxf(m1, __shfl_xor_sync(0xffffffffu, m1, 2));

    float s0 = 0.f, s1 = 0.f;
#pragma unroll
    for (int t = 0; t < 16; t++)
#pragma unroll
        for (int f = 0; f < 2; f++) {
            c[t][f][0] = __expf(0.125f * (c[t][f][0] - m0));
            c[t][f][1] = __expf(0.125f * (c[t][f][1] - m0));
            c[t][f][2] = __expf(0.125f * (c[t][f][2] - m1));
            c[t][f][3] = __expf(0.125f * (c[t][f][3] - m1));
            s0 += c[t][f][0] + c[t][f][1];
            s1 += c[t][f][2] + c[t][f][3];
        }
    s0 += __shfl_xor_sync(0xffffffffu, s0, 1);
    s0 += __shfl_xor_sync(0xffffffffu, s0, 2);
    s1 += __shfl_xor_sync(0xffffffffu, s1, 1);
    s1 += __shfl_xor_sync(0xffffffffu, s1, 2);
    float iv0 = 1.f / s0, iv1 = 1.f / s1;

    float ctx[8][4];
#pragma unroll
    for (int nf = 0; nf < 8; nf++)
#pragma unroll
        for (int k = 0; k < 4; k++) ctx[nf][k] = 0.f;

    uint32_t vRow = (uint32_t)((lane & 7) + ((lane >> 3) & 1) * 8);
    uint32_t vCol = (uint32_t)((lane >> 4) * 8);

#pragma unroll
    for (int t = 0; t < 16; t++) {
        uint32_t pa[4];
        __half2 h0 = __halves2half2(__float2half(c[t][0][0] * iv0),
                                    __float2half(c[t][0][1] * iv0));
        __half2 h1 = __halves2half2(__float2half(c[t][0][2] * iv1),
                                    __float2half(c[t][0][3] * iv1));
        __half2 h2 = __halves2half2(__float2half(c[t][1][0] * iv0),
                                    __float2half(c[t][1][1] * iv0));
        __half2 h3 = __halves2half2(__float2half(c[t][1][2] * iv1),
                                    __float2half(c[t][1][3] * iv1));
        pa[0] = *(uint32_t*)&h0;
        pa[1] = *(uint32_t*)&h1;
        pa[2] = *(uint32_t*)&h2;
        pa[3] = *(uint32_t*)&h3;
#pragma unroll
        for (int dn = 0; dn < 4; dn++) {
            uint32_t bv[4];
            ldm_x4_t(bv, sV + ((vRow + (uint32_t)(t * 16)) * AV_STR +
                               (uint32_t)(dn * 16) + vCol) * 2);
            mma16816(ctx[dn * 2 + 0], pa, &bv[0]);
            mma16816(ctx[dn * 2 + 1], pa, &bv[2]);
        }
    }

    int q0 = qoff + wq + (lane >> 2);
#pragma unroll
    for (int nf = 0; nf < 8; nf++) {
        int d = nf * 8 + (lane & 3) * 2;
        size_t i0 = base + (size_t)q0 * HH + d;
        size_t i1 = base + (size_t)(q0 + 8) * HH + d;
        __half2 p0 = __halves2half2(__float2half(ctx[nf][0]), __float2half(ctx[nf][1]));
        __half2 p1 = __halves2half2(__float2half(ctx[nf][2]), __float2half(ctx[nf][3]));
        *(uint32_t*)(g_cx16 + i0) = *(uint32_t*)&p0;
        *(uint32_t*)(g_cx16 + i1) = *(uint32_t*)&p1;
    }
}

// ================= emissions =================
__global__ void emissions_kernel(const float* __restrict__ cw,
                                 const float* __restrict__ cb) {
    int t = blockIdx.x, tid = threadIdx.x;
    float part[CC];
#pragma unroll
    for (int c = 0; c < CC; c++) part[c] = 0.f;
    for (int k = tid; k < HH; k += 256) {
        float hv = g_h[(size_t)t * HH + k];
        const float* wr = cw + (size_t)k * CC;
#pragma unroll
        for (int c = 0; c < CC; c++) part[c] += hv * wr[c];
    }
#pragma unroll
    for (int c = 0; c < CC; c++)
        for (int off = 16; off > 0; off >>= 1)
            part[c] += __shfl_down_sync(0xffffffffu, part[c], off);

    __shared__ float wred[8][CC];
    int lane = tid & 31, w = tid >> 5;
    if (lane == 0)
#pragma unroll
        for (int c = 0; c < CC; c++) wred[w][c] = part[c];
    __syncthreads();
    if (tid < CC) {
        float s = cb[tid];
#pragma unroll
        for (int ww = 0; ww < 8; ww++) s += wred[ww][tid];
        g_em[(size_t)t * CC + tid] = s;
    }
}

// ================= CRF =================
__global__ void crf_kernel(const int* __restrict__ target,
                           const float* __restrict__ cstart,
                           const float* __restrict__ cend,
                           const float* __restrict__ ctrans,
                           float* __restrict__ out) {
    __shared__ float alpha[BB][CC];
    __shared__ float trans[CC][CC];
    __shared__ float den[BB], num[BB];
    int tid = threadIdx.x;

    if (tid < CC * CC) trans[tid / CC][tid % CC] = ctrans[tid];
    __syncthreads();

    int b = tid / CC, j = tid % CC;
    bool act = (tid < BB * CC);
    if (act) alpha[b][j] = cstart[j] + g_em[(size_t)(b * SS) * CC + j];
    __syncthreads();

    for (int s = 1; s < SS; s++) {
        float nv = 0.f;
        if (act) {
            float m = -1e30f;
#pragma unroll
            for (int i = 0; i < CC; i++) m = fmaxf(m, alpha[b][i] + trans[i][j]);
            float sum = 0.f;
#pragma unroll
            for (int i = 0; i < CC; i++) sum += __expf(alpha[b][i] + trans[i][j] - m);
            nv = m + __logf(sum) + g_em[(size_t)(b * SS + s) * CC + j];
            if (!(target[b * SS + s] > -1)) nv = alpha[b][j];
        }
        __syncthreads();
        if (act) alpha[b][j] = nv;
        __syncthreads();
    }

    if (act && j == 0) {
        float m = -1e30f;
#pragma unroll
        for (int jj = 0; jj < CC; jj++) m = fmaxf(m, alpha[b][jj] + cend[jj]);
        float sum = 0.f;
#pragma unroll
        for (int jj = 0; jj < CC; jj++) sum += __expf(alpha[b][jj] + cend[jj] - m);
        den[b] = m + __logf(sum);

        const int* tb = target + b * SS;
        int cnt = 0;
        for (int s = 0; s < SS; s++) cnt += (tb[s] > -1) ? 1 : 0;
        int send = cnt - 1;
        int t0 = tb[0] < 0 ? 0 : tb[0];
        float nu = cstart[t0] + g_em[(size_t)(b * SS) * CC + t0];
        for (int s = 1; s < SS; s++) {
            int ts = tb[s], tp = tb[s - 1];
            float mk = (ts > -1) ? 1.f : 0.f;
            int tsc = ts < 0 ? 0 : ts, tpc = tp < 0 ? 0 : tp;
            nu += mk * (trans[tpc][tsc] + g_em[(size_t)(b * SS + s) * CC + tsc]);
        }
        int last = tb[send < 0 ? 0 : send];
        nu += cend[last < 0 ? 0 : last];
        num[b] = nu;
    }
    __syncthreads();
    if (tid == 0) {
        float L = 0.f;
        for (int bb = 0; bb < BB; bb++) L += num[bb] - den[bb];
        out[0] = -L / BB;
    }
}

// ================= launch =================
extern "C" void kernel_launch(void* const* d_in, const int* in_sizes, int n_in,
                              void* d_out, int out_size) {
    const int*   x          = (const int*)  d_in[0];
    const int*   target     = (const int*)  d_in[1];
    const float* word_emb   = (const float*)d_in[2];
    const float* pos_emb    = (const float*)d_in[3];
    const float* type_emb   = (const float*)d_in[4];
    const float* emb_ln_w   = (const float*)d_in[5];
    const float* emb_ln_b   = (const float*)d_in[6];
    const float* qkv_w      = (const float*)d_in[7];
    const float* qkv_b      = (const float*)d_in[8];
    const float* attn_out_w = (const float*)d_in[9];
    const float* attn_out_b = (const float*)d_in[10];
    const float* attn_ln_w  = (const float*)d_in[11];
    const float* attn_ln_b  = (const float*)d_in[12];
    const float* ffn_w1     = (const float*)d_in[13];
    const float* ffn_b1     = (const float*)d_in[14];
    const float* ffn_w2     = (const float*)d_in[15];
    const float* ffn_b2     = (const float*)d_in[16];
    const float* ffn_ln_w   = (const float*)d_in[17];
    const float* ffn_ln_b   = (const float*)d_in[18];
    const float* cls_w      = (const float*)d_in[19];
    const float* cls_b      = (const float*)d_in[20];
    const float* crf_start  = (const float*)d_in[21];
    const float* crf_end    = (const float*)d_in[22];
    const float* crf_trans  = (const float*)d_in[23];
    float* out = (float*)d_out;

    float *pt1;
    __half *ph16, *pqkv16, *pcx16, *pf16;
    __half *pwq, *pwa, *pw1, *pw2;
    cudaGetSymbolAddress((void**)&pt1,    g_t1);
    cudaGetSymbolAddress((void**)&ph16,   g_h16);
    cudaGetSymbolAddress((void**)&pqkv16, g_qkv16);
    cudaGetSymbolAddress((void**)&pcx16,  g_cx16);
    cudaGetSymbolAddress((void**)&pf16,   g_f16);
    cudaGetSymbolAddress((void**)&pwq, w_qkv16);
    cudaGetSymbolAddress((void**)&pwa, w_ao16);
    cudaGetSymbolAddress((void**)&pw1, w_f116);
    cudaGetSymbolAddress((void**)&pw2, w_f216);

    const int SMEM_ATTN = (128*AQ_STR + 256*AK_STR + 256*AV_STR) * 2;    // 92160
    const int SMEM_G128 = 3 * (128*PADK + 64*(128+8)) * 2;               // 107520
    const int SMEM_G64  = 3 * (128*PADK + 64*(64+8)) * 2;                // 82944
    cudaFuncSetAttribute(attn_kernel_v6,
                         cudaFuncAttributeMaxDynamicSharedMemorySize, SMEM_ATTN);
    cudaFuncSetAttribute(k_mma<128>,
                         cudaFuncAttributeMaxDynamicSharedMemorySize, SMEM_G128);
    cudaFuncSetAttribute(k_mma<64>,
                         cudaFuncAttributeMaxDynamicSharedMemorySize, SMEM_G64);

    {
        size_t nq = (size_t)NLL*3*HH*HH;
        size_t na = (size_t)NLL*HH*HH;
        size_t n1 = (size_t)NLL*HH*FFF;
        size_t n2 = (size_t)NLL*FFF*HH;
        k_wconv<<<(unsigned)((nq/8 + 255)/256), 256>>>(qkv_w,      pwq, nq);
        k_wconv<<<(unsigned)((na/8 + 255)/256), 256>>>(attn_out_w, pwa, na);
        k_wconv<<<(unsigned)((n1/8 + 255)/256), 256>>>(ffn_w1,     pw1, n1);
        k_wconv<<<(unsigned)((n2/8 + 255)/256), 256>>>(ffn_w2,     pw2, n2);
    }

    embed_ln_kernel<<<TOK/8, 256>>>(x, word_emb, pos_emb, type_emb, emb_ln_w, emb_ln_b);

    dim3 gQKV(HH / 128, TOK / 128, 3);
    dim3 gH64(HH / 64,  TOK / 128, 1);
    dim3 gF  (FFF / 128, TOK / 128, 1);
    dim3 gA  (NHH, BB, 2);

    for (int l = 0; l < NLL; l++) {
        k_mma<128><<<gQKV, 256, SMEM_G128>>>(ph16,
            pwq + (size_t)l*3*HH*HH,
            qkv_b + (size_t)l*3*HH,
            nullptr, pqkv16,
            HH, HH, 2, HH*HH, TOK*HH, HH);

        attn_kernel_v6<<<gA, 256, SMEM_ATTN>>>();

        k_mma<64><<<gH64, 256, SMEM_G64>>>(pcx16,
            pwa + (size_t)l*HH*HH,
            attn_out_b + (size_t)l*HH,
            pt1, nullptr,
            HH, HH, 0, 0, 0, 0);
        resid_ln_kernel<<<TOK/8, 256>>>(pt1, attn_ln_w + (size_t)l*HH, attn_ln_b + (size_t)l*HH);

        k_mma<128><<<gF, 256, SMEM_G128>>>(ph16,
            pw1 + (size_t)l*HH*FFF,
            ffn_b1 + (size_t)l*FFF,
            nullptr, pf16,
            FFF, HH, 1, 0, 0, 0);

        k_mma<64><<<gH64, 256, SMEM_G64>>>(pf16,
            pw2 + (size_t)l*FFF*HH,
            ffn_b2 + (size_t)l*HH,
            pt1, nullptr,
            HH, FFF, 0, 0, 0, 0);
        resid_ln_kernel<<<TOK/8, 256>>>(pt1, ffn_ln_w + (size_t)l*HH, ffn_ln_b + (size_t)l*HH);
    }

    emissions_kernel<<<TOK, 256>>>(cls_w, cls_b);
    crf_kernel<<<1, 128>>>(target, crf_start, crf_end, crf_trans, out);
}